// round 9
// baseline (speedup 1.0000x reference)
#include <cuda_runtime.h>
#include <cuda_fp16.h>
#include <cstdint>

// Problem constants
#define NGR 4
#define GF 256
#define DIN 834
#define SS 1568
#define NB 16
#define TOT 160
#define IDIM 1024
#define NMAX 16

// padded dims for MMA
#define CPAD 896            // K padded (28 chunks of 32)
#define SPAD 1664           // s padded (13 tiles of 128)
#define KCHUNKS 28
#define STILES 13
#define MTILES 2            // 256 f / 128

// W pre-scale to keep fp16 lo-part normal
#define WSCALE 1024.0f
#define WUNSCALE (1.0f / 1024.0f)

// smem layout for ctx_mma_k: 80B row stride, 128 rows per tile, 3 tiles/stage
#define RS 80
#define TILE_B (128 * RS)   // 10240
#define AH_OFF 0
#define AL_OFF (TILE_B)
#define BH_OFF (2 * TILE_B)
#define STAGE_B (3 * TILE_B)        // 30720
#define SMEM_DYN (2 * STAGE_B)      // 61440

#define KSPLIT 4

// ---------------- scratch (static device globals) --------------------------
__device__ float g_emb[TOT * NGR * GF];
__device__ float g_embP[KSPLIT * TOT * NGR * GF];
__device__ float g_ctx[NB * NGR * GF * SS];        // [z][f][s]
__device__ float g_adj[NB * NGR * NMAX * SS];
__device__ float g_flat[TOT * NGR * GF];
__device__ int   g_off[NB];
__device__ int   g_cnt[NB];
__device__ __half g_fmT_hi[(long long)NB * SPAD * CPAD];  // [b][s][c]
__device__ __half g_fmT_lo[(long long)NB * SPAD * CPAD];
__device__ __half g_w_hi[NGR * GF * CPAD];                // [g][f][c], x1024
__device__ __half g_w_lo[NGR * GF * CPAD];

// ---------------- PTX helpers (baseline ISA only) ---------------------------
__device__ __forceinline__ uint32_t smem_u32(const void* p) {
    uint32_t a;
    asm("{ .reg .u64 t; cvta.to.shared.u64 t, %1; cvt.u32.u64 %0, t; }"
        : "=r"(a) : "l"(p));
    return a;
}
__device__ __forceinline__ void cp16(uint32_t dst, const void* src) {
    asm volatile("cp.async.cg.shared.global [%0], [%1], 16;"
                 :: "r"(dst), "l"(src) : "memory");
}
__device__ __forceinline__ void cp_commit() {
    asm volatile("cp.async.commit_group;" ::: "memory");
}
template <int N>
__device__ __forceinline__ void cp_wait() {
    asm volatile("cp.async.wait_group %0;" :: "n"(N) : "memory");
}
__device__ __forceinline__ void ldsm4(uint32_t& r0, uint32_t& r1, uint32_t& r2,
                                      uint32_t& r3, uint32_t a) {
    asm volatile("ldmatrix.sync.aligned.m8n8.x4.shared.b16 {%0,%1,%2,%3}, [%4];"
                 : "=r"(r0), "=r"(r1), "=r"(r2), "=r"(r3) : "r"(a));
}
__device__ __forceinline__ void mma_f16(float* c, const uint32_t* a,
                                        uint32_t b0, uint32_t b1) {
    asm volatile(
        "mma.sync.aligned.m16n8k16.row.col.f32.f16.f16.f32 "
        "{%0,%1,%2,%3}, {%4,%5,%6,%7}, {%8,%9}, {%0,%1,%2,%3};"
        : "+f"(c[0]), "+f"(c[1]), "+f"(c[2]), "+f"(c[3])
        : "r"(a[0]), "r"(a[1]), "r"(a[2]), "r"(a[3]), "r"(b0), "r"(b1));
}

// ---------------- K0: ragged bookkeeping ------------------------------------
__global__ void init_offsets_k(const void* __restrict__ counts) {
    if (threadIdx.x == 0 && blockIdx.x == 0) {
        const int* c32 = (const int*)counts;
        const long long* c64 = (const long long*)counts;
        long long s = 0;
        bool ok32 = true;
        for (int b = 0; b < NB; b++) {
            int v = c32[b];
            if (v < 0 || v > NMAX) ok32 = false;
            s += v;
        }
        if (s != TOT) ok32 = false;
        int acc = 0;
        for (int b = 0; b < NB; b++) {
            int c = ok32 ? c32[b] : (int)c64[b];
            if (c < 0) c = 0;
            if (c > NMAX) c = NMAX;
            g_off[b] = acc;
            g_cnt[b] = c;
            acc += c;
        }
    }
}

// ---------------- prep: split W_c (x1024) into fp16 hi/lo, pad K ------------
__global__ void __launch_bounds__(256) split_w_k(const float* __restrict__ Wc) {
    int id = blockIdx.x * 256 + threadIdx.x;
    if (id >= NGR * GF * CPAD) return;
    int cp = id % CPAD;
    int fg = id / CPAD;
    float v = (cp < DIN) ? Wc[(long long)fg * DIN + cp] * WSCALE : 0.f;
    __half h = __float2half(v);
    __half l = __float2half(v - __half2float(h));
    g_w_hi[id] = h;
    g_w_lo[id] = l;
}

// ---------------- prep: transpose fm [b][c][s] -> [b][s][c], fp16 hi only ---
// (B lo-part unused by 2-term scheme, but keep split for symmetry: only hi stored)
__global__ void __launch_bounds__(256) split_fm_k(const float* __restrict__ fm) {
    __shared__ float tile[32][33];
    int b = blockIdx.z;
    int s0 = blockIdx.x * 32, c0 = blockIdx.y * 32;
    int tx = threadIdx.x, ty = threadIdx.y;     // (32, 8)

#pragma unroll
    for (int i = 0; i < 4; i++) {
        int c = c0 + ty + i * 8;
        int s = s0 + tx;
        float v = 0.f;
        if (c < DIN && s < SS) v = fm[((long long)b * DIN + c) * SS + s];
        tile[ty + i * 8][tx] = v;
    }
    __syncthreads();
#pragma unroll
    for (int i = 0; i < 4; i++) {
        int s = s0 + ty + i * 8;
        int c = c0 + tx;
        float v = tile[tx][ty + i * 8];
        __half h = __float2half(v);
        long long o = ((long long)b * SPAD + s) * CPAD + c;
        g_fmT_hi[o] = h;
        g_fmT_lo[o] = __float2half(v - __half2float(h));  // kept for future use
    }
}

// ---------------- K2: ctx via mma.sync fp16 (2-term: (ah+al)*bh) ------------
// CTA tile M(f)=128 x N(s)=128, K chunk 32, 2-stage, 2 CTA/SM.
__global__ void __launch_bounds__(256, 2)
ctx_mma_k(const float* __restrict__ bc) {
    extern __shared__ __align__(16) char sm[];

    int tid = threadIdx.x;
    int lane = tid & 31, wid = tid >> 5;
    int bx = blockIdx.x;
    int stile = bx % STILES;
    int mtile = bx / STILES;
    int z = blockIdx.y;
    int b = z >> 2, g = z & 3;

    uint32_t sb = smem_u32(sm);

    const char* Ahc = (const char*)(g_w_hi + ((long long)g * GF + mtile * 128) * CPAD);
    const char* Alc = (const char*)(g_w_lo + ((long long)g * GF + mtile * 128) * CPAD);
    const char* Bhc = (const char*)(g_fmT_hi + ((long long)b * SPAD + stile * 128) * CPAD);

    int id0 = tid, id1 = tid + 256;
    int row0 = id0 >> 2, ci0 = id0 & 3;
    int row1 = id1 >> 2, ci1 = id1 & 3;
    uint32_t d0 = row0 * RS + ci0 * 16;
    uint32_t d1 = row1 * RS + ci1 * 16;
    long long so0 = (long long)row0 * (CPAD * 2) + ci0 * 16;
    long long so1 = (long long)row1 * (CPAD * 2) + ci1 * 16;

    int warpM = wid & 3, warpN = wid >> 2;
    int m0w = warpM * 32;
    int n0w = warpN * 64;

    uint32_t aOff[2], bOff[4];
#pragma unroll
    for (int i = 0; i < 2; i++)
        aOff[i] = (m0w + i * 16 + (lane & 15)) * RS + (lane >> 4) * 16;
#pragma unroll
    for (int jj = 0; jj < 4; jj++)
        bOff[jj] = (n0w + jj * 16 + (lane & 15)) * RS + (lane >> 4) * 16;

    float acc[2][8][4];
#pragma unroll
    for (int i = 0; i < 2; i++)
#pragma unroll
        for (int j = 0; j < 8; j++)
#pragma unroll
            for (int q = 0; q < 4; q++) acc[i][j][q] = 0.f;

    {   // prologue stage 0
        cp16(sb + AH_OFF + d0, Ahc + so0);
        cp16(sb + AH_OFF + d1, Ahc + so1);
        cp16(sb + AL_OFF + d0, Alc + so0);
        cp16(sb + AL_OFF + d1, Alc + so1);
        cp16(sb + BH_OFF + d0, Bhc + so0);
        cp16(sb + BH_OFF + d1, Bhc + so1);
        cp_commit();
    }

    for (int chunk = 0; chunk < KCHUNKS; chunk++) {
        uint32_t bo = (chunk & 1) ? STAGE_B : 0;
        if (chunk + 1 < KCHUNKS) {
            long long cs = (long long)(chunk + 1) * 64;
            uint32_t nbo = ((chunk + 1) & 1) ? STAGE_B : 0;
            cp16(sb + nbo + AH_OFF + d0, Ahc + so0 + cs);
            cp16(sb + nbo + AH_OFF + d1, Ahc + so1 + cs);
            cp16(sb + nbo + AL_OFF + d0, Alc + so0 + cs);
            cp16(sb + nbo + AL_OFF + d1, Alc + so1 + cs);
            cp16(sb + nbo + BH_OFF + d0, Bhc + so0 + cs);
            cp16(sb + nbo + BH_OFF + d1, Bhc + so1 + cs);
            cp_commit();
            cp_wait<1>();
        } else {
            cp_wait<0>();
        }
        __syncthreads();

#pragma unroll
        for (int ks = 0; ks < 2; ks++) {
            uint32_t kb = ks * 32;
            uint32_t ah[2][4], al[2][4];
#pragma unroll
            for (int i = 0; i < 2; i++) {
                ldsm4(ah[i][0], ah[i][1], ah[i][2], ah[i][3],
                      sb + bo + AH_OFF + aOff[i] + kb);
                ldsm4(al[i][0], al[i][1], al[i][2], al[i][3],
                      sb + bo + AL_OFF + aOff[i] + kb);
            }
#pragma unroll
            for (int jj = 0; jj < 4; jj++) {
                uint32_t h0, h1, h2, h3;
                ldsm4(h0, h1, h2, h3, sb + bo + BH_OFF + bOff[jj] + kb);
                int j0 = 2 * jj, j1 = 2 * jj + 1;
                // 2 terms: ah*bh + al*bh  (4 independent accs between reuse)
                mma_f16(acc[0][j0], ah[0], h0, h2);
                mma_f16(acc[0][j1], ah[0], h1, h3);
                mma_f16(acc[1][j0], ah[1], h0, h2);
                mma_f16(acc[1][j1], ah[1], h1, h3);
                mma_f16(acc[0][j0], al[0], h0, h2);
                mma_f16(acc[0][j1], al[0], h1, h3);
                mma_f16(acc[1][j0], al[1], h0, h2);
                mma_f16(acc[1][j1], al[1], h1, h3);
            }
        }
        __syncthreads();
    }

    float* Cz = g_ctx + (long long)z * GF * SS;
#pragma unroll
    for (int i = 0; i < 2; i++) {
        int f0 = mtile * 128 + m0w + i * 16 + (lane >> 2);
        float bias0 = bc[g * GF + f0];
        float bias1 = bc[g * GF + f0 + 8];
#pragma unroll
        for (int j = 0; j < 8; j++) {
            int s0 = stile * 128 + n0w + j * 8 + 2 * (lane & 3);
            if (s0 < SS) {
                float2 v0 = make_float2(acc[i][j][0] * WUNSCALE + bias0,
                                        acc[i][j][1] * WUNSCALE + bias0);
                float2 v1 = make_float2(acc[i][j][2] * WUNSCALE + bias1,
                                        acc[i][j][3] * WUNSCALE + bias1);
                *(float2*)(Cz + (long long)f0 * SS + s0) = v0;
                *(float2*)(Cz + (long long)(f0 + 8) * SS + s0) = v1;
            }
        }
    }
}

// ---------------- emb split-K partial GEMM ----------------------------------
__global__ void __launch_bounds__(256) emb_part_k(
    const float* __restrict__ A, const float* __restrict__ Bm)
{
    int z = blockIdx.z;
    int kbase = z * (IDIM / KSPLIT);

    __shared__ __align__(16) float As[32][33];
    __shared__ __align__(16) float Bs[32][65];

    int tid = threadIdx.x;
    int m0 = blockIdx.x * 32;
    int n0 = blockIdx.y * 64;
    int tx = tid % 64;
    int ty = tid / 64;

    float acc[8];
#pragma unroll
    for (int i = 0; i < 8; i++) acc[i] = 0.f;

    for (int k0 = kbase; k0 < kbase + IDIM / KSPLIT; k0 += 32) {
#pragma unroll
        for (int t = 0; t < 4; t++) {
            int lin = tid + 256 * t;
            int k = lin & 31, m = lin >> 5;
            As[k][m] = A[(m0 + m) * IDIM + k0 + k];
        }
#pragma unroll
        for (int t = 0; t < 8; t++) {
            int lin = tid + 256 * t;
            int k = lin & 31, n = lin >> 5;
            Bs[k][n] = Bm[(n0 + n) * IDIM + k0 + k];
        }
        __syncthreads();
#pragma unroll
        for (int k = 0; k < 32; k++) {
            float bv = Bs[k][tx];
#pragma unroll
            for (int i = 0; i < 8; i++)
                acc[i] += As[k][ty + 4 * i] * bv;
        }
        __syncthreads();
    }

    float* P = g_embP + (long long)z * TOT * NGR * GF;
#pragma unroll
    for (int i = 0; i < 8; i++) {
        int m = m0 + ty + 4 * i;
        P[m * (NGR * GF) + n0 + tx] = acc[i];
    }
}

__global__ void __launch_bounds__(256) emb_reduce_k(const float* __restrict__ ba) {
    int id = blockIdx.x * 256 + threadIdx.x;
    if (id >= TOT * NGR * GF) return;
    float v = ba[id & (NGR * GF - 1)];
#pragma unroll
    for (int z = 0; z < KSPLIT; z++)
        v += g_embP[z * (TOT * NGR * GF) + id];
    g_emb[id] = v;
}

// ---------------- generic GEMM (head): C = A * B^T, relu --------------------
__global__ void __launch_bounds__(256) gemm_nt_k(
    const float* __restrict__ A, int lda, long long aZ,
    const float* __restrict__ Bm, int ldb, long long bZ,
    const float* __restrict__ bias,
    float* __restrict__ C, int ldc, long long cZ,
    int K, int doRelu)
{
    int z = blockIdx.z;
    A  += (long long)z * aZ;
    Bm += (long long)z * bZ;
    C  += (long long)z * cZ;

    __shared__ __align__(16) float As[32][33];
    __shared__ __align__(16) float Bs[32][65];

    int tid = threadIdx.x;
    int m0 = blockIdx.x * 32;
    int n0 = blockIdx.y * 64;
    int tx = tid % 64;
    int ty = tid / 64;

    float acc[8];
#pragma unroll
    for (int i = 0; i < 8; i++) acc[i] = 0.f;

    for (int k0 = 0; k0 < K; k0 += 32) {
#pragma unroll
        for (int t = 0; t < 4; t++) {
            int lin = tid + 256 * t;
            int k = lin & 31, m = lin >> 5;
            As[k][m] = A[(m0 + m) * (long long)lda + k0 + k];
        }
#pragma unroll
        for (int t = 0; t < 8; t++) {
            int lin = tid + 256 * t;
            int k = lin & 31, n = lin >> 5;
            Bs[k][n] = Bm[(n0 + n) * (long long)ldb + k0 + k];
        }
        __syncthreads();
#pragma unroll
        for (int k = 0; k < 32; k++) {
            float bv = Bs[k][tx];
#pragma unroll
            for (int i = 0; i < 8; i++)
                acc[i] += As[k][ty + 4 * i] * bv;
        }
        __syncthreads();
    }

    float bb = bias ? bias[n0 + tx] : 0.f;
#pragma unroll
    for (int i = 0; i < 8; i++) {
        int m = m0 + ty + 4 * i;
        float v = acc[i] + bb;
        if (doRelu) v = fmaxf(v, 0.f);
        C[m * (long long)ldc + n0 + tx] = v;
    }
}

// ---------------- K3: adj logits (2 s-columns per thread) -------------------
__global__ void __launch_bounds__(256) adj_logits_k() {
    int g = blockIdx.y, b = blockIdx.z;
    __shared__ __align__(16) float a_s[GF * NMAX];   // [f][n]
    int tid = threadIdx.x;
    int cnt = g_cnt[b], off = g_off[b];

    for (int idx = tid; idx < GF * NMAX; idx += 256) {
        int n = idx >> 8, f = idx & 255;
        float v = 0.f;
        if (n < cnt) v = g_emb[(off + n) * (NGR * GF) + g * GF + f];
        a_s[f * NMAX + n] = v;
    }
    __syncthreads();

    int s0 = blockIdx.x * 512 + tid;
    int s1 = s0 + 256;
    if (s0 >= SS) return;
    bool ok1 = (s1 < SS);
    int s1c = ok1 ? s1 : s0;

    const float* ctxp = g_ctx + ((long long)(b * NGR + g)) * GF * SS;
    float acc0[NMAX], acc1[NMAX];
#pragma unroll
    for (int n = 0; n < NMAX; n++) { acc0[n] = 0.f; acc1[n] = 0.f; }

    const float4* ap = (const float4*)a_s;
#pragma unroll 2
    for (int f = 0; f < GF; f++) {
        float x0 = ctxp[(long long)f * SS + s0];
        float x1 = ctxp[(long long)f * SS + s1c];
        float4 a0 = ap[f * 4 + 0];
        float4 a1 = ap[f * 4 + 1];
        float4 a2 = ap[f * 4 + 2];
        float4 a3 = ap[f * 4 + 3];
        acc0[0]  += x0 * a0.x;  acc0[1]  += x0 * a0.y;  acc0[2]  += x0 * a0.z;  acc0[3]  += x0 * a0.w;
        acc0[4]  += x0 * a1.x;  acc0[5]  += x0 * a1.y;  acc0[6]  += x0 * a1.z;  acc0[7]  += x0 * a1.w;
        acc0[8]  += x0 * a2.x;  acc0[9]  += x0 * a2.y;  acc0[10] += x0 * a2.z;  acc0[11] += x0 * a2.w;
        acc0[12] += x0 * a3.x;  acc0[13] += x0 * a3.y;  acc0[14] += x0 * a3.z;  acc0[15] += x0 * a3.w;
        acc1[0]  += x1 * a0.x;  acc1[1]  += x1 * a0.y;  acc1[2]  += x1 * a0.z;  acc1[3]  += x1 * a0.w;
        acc1[4]  += x1 * a1.x;  acc1[5]  += x1 * a1.y;  acc1[6]  += x1 * a1.z;  acc1[7]  += x1 * a1.w;
        acc1[8]  += x1 * a2.x;  acc1[9]  += x1 * a2.y;  acc1[10] += x1 * a2.z;  acc1[11] += x1 * a2.w;
        acc1[12] += x1 * a3.x;  acc1[13] += x1 * a3.y;  acc1[14] += x1 * a3.z;  acc1[15] += x1 * a3.w;
    }

    float* adjp = g_adj + ((long long)(b * NGR + g)) * NMAX * SS;
#pragma unroll
    for (int n = 0; n < NMAX; n++) {
        adjp[(long long)n * SS + s0] = acc0[n];
        if (ok1) adjp[(long long)n * SS + s1] = acc1[n];
    }
}

// ---------------- K4: softmax -------------------------------------------------
__global__ void __launch_bounds__(256) softmax_k() {
    int n = blockIdx.x, g = blockIdx.y, b = blockIdx.z;
    if (n >= g_cnt[b]) return;
    float* row = g_adj + ((long long)((b * NGR + g) * NMAX + n)) * SS;
    int tid = threadIdx.x;
    __shared__ float red[8];

    float mx = -1e30f;
    for (int s = tid; s < SS; s += 256) mx = fmaxf(mx, row[s]);
#pragma unroll
    for (int o = 16; o > 0; o >>= 1) mx = fmaxf(mx, __shfl_xor_sync(0xffffffffu, mx, o));
    if ((tid & 31) == 0) red[tid >> 5] = mx;
    __syncthreads();
    if (tid < 32) {
        float v = (tid < 8) ? red[tid] : -1e30f;
#pragma unroll
        for (int o = 4; o > 0; o >>= 1) v = fmaxf(v, __shfl_xor_sync(0xffffffffu, v, o));
        if (tid == 0) red[0] = v;
    }
    __syncthreads();
    mx = red[0];
    __syncthreads();

    float sum = 0.f;
    for (int s = tid; s < SS; s += 256) {
        float e = __expf(row[s] - mx);
        row[s] = e;
        sum += e;
    }
#pragma unroll
    for (int o = 16; o > 0; o >>= 1) sum += __shfl_xor_sync(0xffffffffu, sum, o);
    if ((tid & 31) == 0) red[tid >> 5] = sum;
    __syncthreads();
    if (tid < 32) {
        float v = (tid < 8) ? red[tid] : 0.f;
#pragma unroll
        for (int o = 4; o > 0; o >>= 1) v += __shfl_xor_sync(0xffffffffu, v, o);
        if (tid == 0) red[0] = v;
    }
    __syncthreads();
    float inv = 1.f / red[0];
    for (int s = tid; s < SS; s += 256) row[s] *= inv;
}

// ---------------- K5: aggregate + residual -----------------------------------
__global__ void __launch_bounds__(256) aggregate_k() {
    int z = blockIdx.y;
    int b = z >> 2, g = z & 3;
    int f0 = blockIdx.x * 64;

    __shared__ __align__(16) float adjS[NMAX][33];
    __shared__ __align__(16) float ctxS[32][65];

    const float* adjp = g_adj + (long long)z * NMAX * SS;
    const float* ctxp = g_ctx + (long long)z * GF * SS;

    int tid = threadIdx.x;
    int fid = tid % 64, grp = tid / 64;
    float acc[4] = {0.f, 0.f, 0.f, 0.f};

    for (int s0 = 0; s0 < SS; s0 += 32) {
#pragma unroll
        for (int t = 0; t < 2; t++) {
            int lin = tid + 256 * t;
            int k = lin & 31, n = lin >> 5;
            adjS[n][k] = adjp[n * SS + s0 + k];
        }
#pragma unroll
        for (int t = 0; t < 8; t++) {
            int lin = tid + 256 * t;
            int k = lin & 31, i = lin >> 5;
            ctxS[k][i] = ctxp[(f0 + i) * SS + s0 + k];
        }
        __syncthreads();
#pragma unroll
        for (int k = 0; k < 32; k++) {
            float bv = ctxS[k][fid];
#pragma unroll
            for (int j = 0; j < 4; j++)
                acc[j] += adjS[grp * 4 + j][k] * bv;
        }
        __syncthreads();
    }

    int cnt = g_cnt[b], off = g_off[b];
#pragma unroll
    for (int j = 0; j < 4; j++) {
        int n = grp * 4 + j;
        if (n < cnt) {
            long long idx = (long long)(off + n) * (NGR * GF) + g * GF + f0 + fid;
            g_flat[idx] = acc[j] + g_emb[idx];
        }
    }
}

// ---------------- launch ----------------------------------------------------
extern "C" void kernel_launch(void* const* d_in, const int* in_sizes, int n_in,
                              void* d_out, int out_size) {
    const float* actor = (const float*)d_in[0];
    const float* fmap  = (const float*)d_in[1];
    const float* W_a   = (const float*)d_in[2];
    const float* b_a   = (const float*)d_in[3];
    const float* W_c   = (const float*)d_in[4];
    const float* b_c   = (const float*)d_in[5];
    const float* W_h   = (const float*)d_in[6];
    const void*  counts = d_in[7];
    int nbias = 0;
    for (int i = 0; i < n_in; i++) {
        switch (in_sizes[i]) {
            case TOT * IDIM:      actor = (const float*)d_in[i]; break;
            case NB * DIN * SS:   fmap  = (const float*)d_in[i]; break;
            case NGR * GF * IDIM: W_a   = (const float*)d_in[i]; break;
            case NGR * GF * DIN:  W_c   = (const float*)d_in[i]; break;
            case NGR * GF * GF:   W_h   = (const float*)d_in[i]; break;
            case NGR * GF:
                if (nbias++ == 0) b_a = (const float*)d_in[i];
                else              b_c = (const float*)d_in[i];
                break;
            case NB:              counts = d_in[i]; break;
            default: break;
        }
    }
    float* out = (float*)d_out;

    float* flat_p;
    cudaGetSymbolAddress((void**)&flat_p, g_flat);

    cudaFuncSetAttribute(ctx_mma_k, cudaFuncAttributeMaxDynamicSharedMemorySize,
                         SMEM_DYN);

    // ctx_mma_k at launch index 3 (ncu lands there)
    init_offsets_k<<<1, 32>>>(counts);                                    // 0
    split_w_k<<<(NGR * GF * CPAD + 255) / 256, 256>>>(W_c);               // 1
    split_fm_k<<<dim3(SPAD / 32, CPAD / 32, NB), dim3(32, 8)>>>(fmap);    // 2
    ctx_mma_k<<<dim3(STILES * MTILES, NB * NGR), 256, SMEM_DYN>>>(b_c);   // 3
    emb_part_k<<<dim3(5, 16, KSPLIT), 256>>>(actor, W_a);                 // 4
    emb_reduce_k<<<(TOT * NGR * GF + 255) / 256, 256>>>(b_a);             // 5
    adj_logits_k<<<dim3(4, NGR, NB), 256>>>();                            // 6
    softmax_k<<<dim3(NMAX, NGR, NB), 256>>>();                            // 7
    aggregate_k<<<dim3(4, 64), 256>>>();                                  // 8
    gemm_nt_k<<<dim3(5, 4, 4), 256>>>(flat_p, NGR * GF, GF,               // 9
                                      W_h, GF, (long long)GF * GF,
                                      nullptr,
                                      out, NGR * GF, GF,
                                      GF, 1);
}

// round 10
// speedup vs baseline: 1.3186x; 1.3186x over previous
#include <cuda_runtime.h>
#include <cstdint>

// Problem constants
#define NGR 4
#define GF 256
#define DIN 834
#define SS 1568
#define NB 16
#define TOT 160
#define IDIM 1024
#define NMAX 16

#define CP2 896             // c padded (28 x 32, 14 x 64)
#define ADJ_LD 1600         // s padded to 25 x 64 for adj storage
#define KSPLIT 4

// ---------------- scratch (static device globals) --------------------------
__device__ float g_emb[TOT * IDIM];
__device__ float g_embP[KSPLIT * TOT * IDIM];
__device__ float g_WcT[NGR * CP2 * GF];              // [g][c][f]
__device__ float g_WcP[NGR * GF * CP2];              // [g][f][c], zero pad
__device__ float g_fmT[(long long)NB * SS * CP2];    // [b][s][c], zero pad
__device__ float g_E2flat[TOT * NGR * CP2];          // [t][g][c]
__device__ float g_E2P[NB * 64 * CP2];               // [b][g*16+n][c]
__device__ float g_dP[NB * 64];
__device__ float g_adj[NB * 64 * ADJ_LD];            // [b][g*16+n][s]
__device__ float g_R[NB * 64 * CP2];
__device__ float g_Rf[TOT * NGR * CP2];              // [t][g][c]
__device__ float g_flat[TOT * IDIM];
__device__ int   g_off[NB];
__device__ int   g_cnt[NB];

// ---------------- K0: ragged bookkeeping ------------------------------------
__global__ void init_offsets_k(const void* __restrict__ counts) {
    if (threadIdx.x == 0 && blockIdx.x == 0) {
        const int* c32 = (const int*)counts;
        const long long* c64 = (const long long*)counts;
        long long s = 0;
        bool ok32 = true;
        for (int b = 0; b < NB; b++) {
            int v = c32[b];
            if (v < 0 || v > NMAX) ok32 = false;
            s += v;
        }
        if (s != TOT) ok32 = false;
        int acc = 0;
        for (int b = 0; b < NB; b++) {
            int c = ok32 ? c32[b] : (int)c64[b];
            if (c < 0) c = 0;
            if (c > NMAX) c = NMAX;
            g_off[b] = acc;
            g_cnt[b] = c;
            acc += c;
        }
    }
}

// ---------------- prep: WcP[g][f][c] (pad c) and WcT[g][c][f] ---------------
__global__ void __launch_bounds__(256) prep_w_k(const float* __restrict__ Wc) {
    int id = blockIdx.x * 256 + threadIdx.x;
    if (id >= NGR * GF * CP2) return;
    int c = id % CP2;
    int rf = id / CP2;
    int f = rf % GF, g = rf / GF;
    float v = (c < DIN) ? Wc[(long long)rf * DIN + c] : 0.f;
    g_WcP[id] = v;
    g_WcT[((long long)g * CP2 + c) * GF + f] = v;
}

// ---------------- prep: fmT[b][s][c] = fm[b][c][s], fp32, pad c -------------
__global__ void __launch_bounds__(256) fmT_k(const float* __restrict__ fm) {
    __shared__ float tile[32][33];
    int b = blockIdx.z;
    int s0 = blockIdx.x * 32, c0 = blockIdx.y * 32;
    int tx = threadIdx.x, ty = threadIdx.y;     // (32, 8)

#pragma unroll
    for (int i = 0; i < 4; i++) {
        int c = c0 + ty + i * 8;
        float v = 0.f;
        if (c < DIN) v = fm[((long long)b * DIN + c) * SS + s0 + tx];
        tile[ty + i * 8][tx] = v;
    }
    __syncthreads();
#pragma unroll
    for (int i = 0; i < 4; i++) {
        int s = s0 + ty + i * 8;
        int c = c0 + tx;
        g_fmT[((long long)b * SS + s) * CP2 + c] = tile[tx][ty + i * 8];
    }
}

// ---------------- emb split-K partial GEMM ----------------------------------
__global__ void __launch_bounds__(256) emb_part_k(
    const float* __restrict__ A, const float* __restrict__ Bm)
{
    int z = blockIdx.z;
    int kbase = z * (IDIM / KSPLIT);

    __shared__ __align__(16) float As[32][33];
    __shared__ __align__(16) float Bs[32][65];

    int tid = threadIdx.x;
    int m0 = blockIdx.x * 32;
    int n0 = blockIdx.y * 64;
    int tx = tid % 64, ty = tid / 64;

    float acc[8];
#pragma unroll
    for (int i = 0; i < 8; i++) acc[i] = 0.f;

    for (int k0 = kbase; k0 < kbase + IDIM / KSPLIT; k0 += 32) {
#pragma unroll
        for (int t = 0; t < 4; t++) {
            int lin = tid + 256 * t;
            int k = lin & 31, m = lin >> 5;
            As[k][m] = A[(m0 + m) * IDIM + k0 + k];
        }
#pragma unroll
        for (int t = 0; t < 8; t++) {
            int lin = tid + 256 * t;
            int k = lin & 31, n = lin >> 5;
            Bs[k][n] = Bm[(n0 + n) * IDIM + k0 + k];
        }
        __syncthreads();
#pragma unroll
        for (int k = 0; k < 32; k++) {
            float bv = Bs[k][tx];
#pragma unroll
            for (int i = 0; i < 8; i++)
                acc[i] += As[k][ty + 4 * i] * bv;
        }
        __syncthreads();
    }

    float* P = g_embP + (long long)z * TOT * IDIM;
#pragma unroll
    for (int i = 0; i < 8; i++) {
        int m = m0 + ty + 4 * i;
        P[m * IDIM + n0 + tx] = acc[i];
    }
}

__global__ void __launch_bounds__(256) emb_reduce_k(const float* __restrict__ ba) {
    int id = blockIdx.x * 256 + threadIdx.x;
    if (id >= TOT * IDIM) return;
    float v = ba[id & (IDIM - 1)];
#pragma unroll
    for (int z = 0; z < KSPLIT; z++)
        v += g_embP[z * (TOT * IDIM) + id];
    g_emb[id] = v;
}

// ---------------- flexible GEMM: C[M][N] = A[M][K] @ B[N][K]^T ---------------
// Tile 32m x 64n, BK=32, 256 threads, 8 outputs/thread. M, K multiples of 32.
// B row index clamped to Brows-1; store zero-fills n >= Nstore.
__global__ void __launch_bounds__(256) gemm_flex_k(
    const float* __restrict__ A, int lda, long long aZ,
    const float* __restrict__ Bm, int ldb, long long bZ, int Brows,
    const float* __restrict__ cbias, long long cbZ,
    const float* __restrict__ rbias, long long rbZ,
    const float* __restrict__ resid, int ldres, long long resZ,
    float* __restrict__ C, int ldc, long long cZ,
    int K, int Nstore, int doRelu)
{
    int z = blockIdx.z;
    A  += (long long)z * aZ;
    Bm += (long long)z * bZ;
    C  += (long long)z * cZ;

    __shared__ __align__(16) float As[32][33];
    __shared__ __align__(16) float Bs[32][65];

    int tid = threadIdx.x;
    int m0 = blockIdx.x * 32;
    int n0 = blockIdx.y * 64;
    int tx = tid % 64, ty = tid / 64;

    float acc[8];
#pragma unroll
    for (int i = 0; i < 8; i++) acc[i] = 0.f;

    for (int k0 = 0; k0 < K; k0 += 32) {
#pragma unroll
        for (int t = 0; t < 4; t++) {
            int lin = tid + 256 * t;
            int k = lin & 31, m = lin >> 5;
            As[k][m] = A[(long long)(m0 + m) * lda + k0 + k];
        }
#pragma unroll
        for (int t = 0; t < 8; t++) {
            int lin = tid + 256 * t;
            int k = lin & 31, n = lin >> 5;
            int r = n0 + n;
            if (r >= Brows) r = Brows - 1;
            Bs[k][n] = Bm[(long long)r * ldb + k0 + k];
        }
        __syncthreads();
#pragma unroll
        for (int k = 0; k < 32; k++) {
            float bv = Bs[k][tx];
#pragma unroll
            for (int i = 0; i < 8; i++)
                acc[i] += As[k][ty + 4 * i] * bv;
        }
        __syncthreads();
    }

    int n = n0 + tx;
    bool nok = (n < Nstore);
    float cb = (cbias && nok) ? cbias[z * cbZ + n] : 0.f;
#pragma unroll
    for (int i = 0; i < 8; i++) {
        int m = m0 + ty + 4 * i;
        float outv = 0.f;
        if (nok) {
            float v = acc[i] + cb;
            if (rbias) v += rbias[z * rbZ + m];
            if (resid) v += resid[z * resZ + (long long)m * ldres + n];
            if (doRelu) v = fmaxf(v, 0.f);
            outv = v;
        }
        C[(long long)m * ldc + n] = outv;
    }
}

// ---------------- scatter E2flat -> E2P (pad rows), dP = emb . b_c ----------
__global__ void __launch_bounds__(256) scatter_e2_k(const float* __restrict__ bc) {
    int row = blockIdx.x;        // g*16 + n
    int b = blockIdx.y;
    int g = row >> 4, n = row & 15;
    int tid = threadIdx.x;
    bool valid = (n < g_cnt[b]);
    int t = g_off[b] + n;

    float* dst = g_E2P + ((long long)b * 64 + row) * CP2;
    const float* src = g_E2flat + ((long long)t * NGR + g) * CP2;
    for (int c = tid; c < CP2; c += 256)
        dst[c] = valid ? src[c] : 0.f;

    // d = sum_f emb[t,g,f] * b_c[g,f]   (256 threads == 256 f)
    __shared__ float red[8];
    float v = valid ? g_emb[t * IDIM + g * GF + tid] * bc[g * GF + tid] : 0.f;
#pragma unroll
    for (int o = 16; o > 0; o >>= 1) v += __shfl_xor_sync(0xffffffffu, v, o);
    if ((tid & 31) == 0) red[tid >> 5] = v;
    __syncthreads();
    if (tid == 0) {
        float s = 0.f;
#pragma unroll
        for (int w = 0; w < 8; w++) s += red[w];
        g_dP[b * 64 + row] = s;
    }
}

// ---------------- softmax over s per valid (b,g,n) row ----------------------
__global__ void __launch_bounds__(256) softmax_k() {
    int n = blockIdx.x, g = blockIdx.y, b = blockIdx.z;
    if (n >= g_cnt[b]) return;
    float* row = g_adj + ((long long)(b * 64 + g * 16 + n)) * ADJ_LD;
    int tid = threadIdx.x;
    __shared__ float red[8];

    float mx = -1e30f;
    for (int s = tid; s < SS; s += 256) mx = fmaxf(mx, row[s]);
#pragma unroll
    for (int o = 16; o > 0; o >>= 1) mx = fmaxf(mx, __shfl_xor_sync(0xffffffffu, mx, o));
    if ((tid & 31) == 0) red[tid >> 5] = mx;
    __syncthreads();
    if (tid < 32) {
        float v = (tid < 8) ? red[tid] : -1e30f;
#pragma unroll
        for (int o = 4; o > 0; o >>= 1) v = fmaxf(v, __shfl_xor_sync(0xffffffffu, v, o));
        if (tid == 0) red[0] = v;
    }
    __syncthreads();
    mx = red[0];
    __syncthreads();

    float sum = 0.f;
    for (int s = tid; s < SS; s += 256) {
        float e = __expf(row[s] - mx);
        row[s] = e;
        sum += e;
    }
#pragma unroll
    for (int o = 16; o > 0; o >>= 1) sum += __shfl_xor_sync(0xffffffffu, sum, o);
    if ((tid & 31) == 0) red[tid >> 5] = sum;
    __syncthreads();
    if (tid < 32) {
        float v = (tid < 8) ? red[tid] : 0.f;
#pragma unroll
        for (int o = 4; o > 0; o >>= 1) v += __shfl_xor_sync(0xffffffffu, v, o);
        if (tid == 0) red[0] = v;
    }
    __syncthreads();
    float inv = 1.f / red[0];
    for (int s = tid; s < SS; s += 256) row[s] *= inv;
}

// ---------------- gather R -> Rf (ragged flat) -------------------------------
__global__ void __launch_bounds__(256) gather_rf_k() {
    int row = blockIdx.x;        // g*16 + n
    int b = blockIdx.y;
    int g = row >> 4, n = row & 15;
    if (n >= g_cnt[b]) return;
    int t = g_off[b] + n;
    int tid = threadIdx.x;
    const float* src = g_R + ((long long)b * 64 + row) * CP2;
    float* dst = g_Rf + ((long long)t * NGR + g) * CP2;
    for (int c = tid; c < CP2; c += 256)
        dst[c] = src[c];
}

// ---------------- launch ----------------------------------------------------
extern "C" void kernel_launch(void* const* d_in, const int* in_sizes, int n_in,
                              void* d_out, int out_size) {
    const float* actor = (const float*)d_in[0];
    const float* fmap  = (const float*)d_in[1];
    const float* W_a   = (const float*)d_in[2];
    const float* b_a   = (const float*)d_in[3];
    const float* W_c   = (const float*)d_in[4];
    const float* b_c   = (const float*)d_in[5];
    const float* W_h   = (const float*)d_in[6];
    const void*  counts = d_in[7];
    int nbias = 0;
    for (int i = 0; i < n_in; i++) {
        switch (in_sizes[i]) {
            case TOT * IDIM:      actor = (const float*)d_in[i]; break;
            case NB * DIN * SS:   fmap  = (const float*)d_in[i]; break;
            case NGR * GF * IDIM: W_a   = (const float*)d_in[i]; break;
            case NGR * GF * DIN:  W_c   = (const float*)d_in[i]; break;
            case NGR * GF * GF:   W_h   = (const float*)d_in[i]; break;
            case NGR * GF:
                if (nbias++ == 0) b_a = (const float*)d_in[i];
                else              b_c = (const float*)d_in[i];
                break;
            case NB:              counts = d_in[i]; break;
            default: break;
        }
    }
    float* out = (float*)d_out;

    float *emb_p, *wcT_p, *wcP_p, *fmT_p, *e2f_p, *e2p_p, *dP_p, *adj_p, *R_p,
          *Rf_p, *flat_p;
    cudaGetSymbolAddress((void**)&emb_p, g_emb);
    cudaGetSymbolAddress((void**)&wcT_p, g_WcT);
    cudaGetSymbolAddress((void**)&wcP_p, g_WcP);
    cudaGetSymbolAddress((void**)&fmT_p, g_fmT);
    cudaGetSymbolAddress((void**)&e2f_p, g_E2flat);
    cudaGetSymbolAddress((void**)&e2p_p, g_E2P);
    cudaGetSymbolAddress((void**)&dP_p, g_dP);
    cudaGetSymbolAddress((void**)&adj_p, g_adj);
    cudaGetSymbolAddress((void**)&R_p, g_R);
    cudaGetSymbolAddress((void**)&Rf_p, g_Rf);
    cudaGetSymbolAddress((void**)&flat_p, g_flat);

    // 0: ragged bookkeeping
    init_offsets_k<<<1, 32>>>(counts);
    // 1: W prep (WcP padded + WcT transposed)
    prep_w_k<<<(NGR * GF * CP2 + 255) / 256, 256>>>(W_c);
    // 2: fm transpose [b][s][c], fp32, zero-padded c
    fmT_k<<<dim3(SS / 32, CP2 / 32, NB), dim3(32, 8)>>>(fmap);
    // 3-4: emb = actor @ W_a^T + b_a (split-K)
    emb_part_k<<<dim3(5, 16, KSPLIT), 256>>>(actor, W_a);
    emb_reduce_k<<<(TOT * IDIM + 255) / 256, 256>>>(b_a);
    // 5: E2flat[t][g][c] = emb[t,g,:] @ WcT[g]^T   (M=160,N=896,K=256, z=g)
    gemm_flex_k<<<dim3(5, CP2 / 64, NGR), 256>>>(
        emb_p, IDIM, GF,
        wcT_p, GF, (long long)CP2 * GF, CP2,
        nullptr, 0, nullptr, 0, nullptr, 0, 0,
        e2f_p, NGR * CP2, CP2,
        GF, CP2, 0);
    // 6: scatter E2flat -> E2P (zero invalid rows) + dP
    scatter_e2_k<<<dim3(64, NB), 256>>>(b_c);
    // 7: adj[b][64][s] = E2P @ fmT^T + dP   (M=64,N=1600,K=896, z=b)
    gemm_flex_k<<<dim3(2, ADJ_LD / 64, NB), 256>>>(
        e2p_p, CP2, 64LL * CP2,
        fmT_p, CP2, (long long)SS * CP2, SS,
        nullptr, 0, dP_p, 64, nullptr, 0, 0,
        adj_p, ADJ_LD, 64LL * ADJ_LD,
        CP2, SS, 0);
    // 8: softmax over s
    softmax_k<<<dim3(NMAX, NGR, NB), 256>>>();
    // 9: R[b][64][c] = adj_sm @ fm^T   (M=64,N=896,K=1568, z=b; zero-fill c>=834)
    gemm_flex_k<<<dim3(2, CP2 / 64, NB), 256>>>(
        adj_p, ADJ_LD, 64LL * ADJ_LD,
        fmap, SS, (long long)DIN * SS, DIN,
        nullptr, 0, nullptr, 0, nullptr, 0, 0,
        R_p, CP2, 64LL * CP2,
        SS, DIN, 0);
    // 10: gather R -> Rf (ragged flat)
    gather_rf_k<<<dim3(64, NB), 256>>>();
    // 11: flat[t][g][f] = Rf @ WcP^T + b_c + emb   (M=160,N=256,K=896, z=g)
    gemm_flex_k<<<dim3(5, NGR, NGR), 256>>>(
        Rf_p, NGR * CP2, CP2,
        wcP_p, CP2, (long long)GF * CP2, GF,
        b_c, GF, nullptr, 0,
        emb_p, IDIM, GF,
        flat_p, IDIM, GF,
        CP2, GF, 0);
    // 12: head: out = relu(flat @ W_h^T)   (M=160,N=256,K=256, z=g)
    gemm_flex_k<<<dim3(5, NGR, NGR), 256>>>(
        flat_p, IDIM, GF,
        W_h, GF, (long long)GF * GF, GF,
        nullptr, 0, nullptr, 0, nullptr, 0, 0,
        out, IDIM, GF,
        GF, GF, 1);
}

// round 11
// speedup vs baseline: 1.8448x; 1.3991x over previous
#include <cuda_runtime.h>
#include <cstdint>

// Problem constants
#define NGR 4
#define GF 256
#define DIN 834
#define SS 1568
#define NB 16
#define TOT 160
#define IDIM 1024
#define NMAX 16

#define CP2 896             // c padded (28 x 32)
#define ADJ_LD 1664         // s padded to 13 x 128
#define KSPLIT 4

// ---------------- scratch (static device globals) --------------------------
__device__ float g_emb[TOT * IDIM];
__device__ float g_embP[KSPLIT * TOT * IDIM];
__device__ float g_WcT[NGR * CP2 * GF];              // [g][c][f]
__device__ float g_WcP[NGR * GF * CP2];              // [g][f][c], zero pad
__device__ float g_E2flat[TOT * NGR * CP2];          // [t][g][c]
__device__ float g_E2P[NB * 64 * CP2];               // [b][g*16+n][c]
__device__ float g_dP[NB * 64];
__device__ float g_adj[NB * 64 * ADJ_LD];            // [b][g*16+n][s]
__device__ float g_R[NB * 64 * CP2];
__device__ float g_Rf[TOT * NGR * CP2];              // [t][g][c]
__device__ float g_flat[TOT * IDIM];
__device__ int   g_off[NB];
__device__ int   g_cnt[NB];

// ---------------- K0: ragged bookkeeping ------------------------------------
__global__ void init_offsets_k(const void* __restrict__ counts) {
    if (threadIdx.x == 0 && blockIdx.x == 0) {
        const int* c32 = (const int*)counts;
        const long long* c64 = (const long long*)counts;
        long long s = 0;
        bool ok32 = true;
        for (int b = 0; b < NB; b++) {
            int v = c32[b];
            if (v < 0 || v > NMAX) ok32 = false;
            s += v;
        }
        if (s != TOT) ok32 = false;
        int acc = 0;
        for (int b = 0; b < NB; b++) {
            int c = ok32 ? c32[b] : (int)c64[b];
            if (c < 0) c = 0;
            if (c > NMAX) c = NMAX;
            g_off[b] = acc;
            g_cnt[b] = c;
            acc += c;
        }
    }
}

// ---------------- prep: WcP[g][f][c] (pad c) and WcT[g][c][f] ---------------
__global__ void __launch_bounds__(256) prep_w_k(const float* __restrict__ Wc) {
    int id = blockIdx.x * 256 + threadIdx.x;
    if (id >= NGR * GF * CP2) return;
    int c = id % CP2;
    int rf = id / CP2;
    int f = rf % GF, g = rf / GF;
    float v = (c < DIN) ? Wc[(long long)rf * DIN + c] : 0.f;
    g_WcP[id] = v;
    g_WcT[((long long)g * CP2 + c) * GF + f] = v;
}

// ---------------- emb split-K partial GEMM ----------------------------------
__global__ void __launch_bounds__(256) emb_part_k(
    const float* __restrict__ A, const float* __restrict__ Bm)
{
    int z = blockIdx.z;
    int kbase = z * (IDIM / KSPLIT);

    __shared__ __align__(16) float As[32][33];
    __shared__ __align__(16) float Bs[32][65];

    int tid = threadIdx.x;
    int m0 = blockIdx.x * 32;
    int n0 = blockIdx.y * 64;
    int tx = tid % 64, ty = tid / 64;

    float acc[8];
#pragma unroll
    for (int i = 0; i < 8; i++) acc[i] = 0.f;

    for (int k0 = kbase; k0 < kbase + IDIM / KSPLIT; k0 += 32) {
#pragma unroll
        for (int t = 0; t < 4; t++) {
            int lin = tid + 256 * t;
            int k = lin & 31, m = lin >> 5;
            As[k][m] = A[(m0 + m) * IDIM + k0 + k];
        }
#pragma unroll
        for (int t = 0; t < 8; t++) {
            int lin = tid + 256 * t;
            int k = lin & 31, n = lin >> 5;
            Bs[k][n] = Bm[(n0 + n) * IDIM + k0 + k];
        }
        __syncthreads();
#pragma unroll
        for (int k = 0; k < 32; k++) {
            float bv = Bs[k][tx];
#pragma unroll
            for (int i = 0; i < 8; i++)
                acc[i] += As[k][ty + 4 * i] * bv;
        }
        __syncthreads();
    }

    float* P = g_embP + (long long)z * TOT * IDIM;
#pragma unroll
    for (int i = 0; i < 8; i++) {
        int m = m0 + ty + 4 * i;
        P[m * IDIM + n0 + tx] = acc[i];
    }
}

__global__ void __launch_bounds__(256) emb_reduce_k(const float* __restrict__ ba) {
    int id = blockIdx.x * 256 + threadIdx.x;
    if (id >= TOT * IDIM) return;
    float v = ba[id & (IDIM - 1)];
#pragma unroll
    for (int z = 0; z < KSPLIT; z++)
        v += g_embP[z * (TOT * IDIM) + id];
    g_emb[id] = v;
}

// ---------------- flexible GEMM (small GEMMs): C = A @ B^T ------------------
__global__ void __launch_bounds__(256) gemm_flex_k(
    const float* __restrict__ A, int lda, long long aZ,
    const float* __restrict__ Bm, int ldb, long long bZ, int Brows,
    const float* __restrict__ cbias, long long cbZ,
    const float* __restrict__ resid, int ldres, long long resZ,
    float* __restrict__ C, int ldc, long long cZ,
    int K, int Nstore, int doRelu)
{
    int z = blockIdx.z;
    A  += (long long)z * aZ;
    Bm += (long long)z * bZ;
    C  += (long long)z * cZ;

    __shared__ __align__(16) float As[32][33];
    __shared__ __align__(16) float Bs[32][65];

    int tid = threadIdx.x;
    int m0 = blockIdx.x * 32;
    int n0 = blockIdx.y * 64;
    int tx = tid % 64, ty = tid / 64;

    float acc[8];
#pragma unroll
    for (int i = 0; i < 8; i++) acc[i] = 0.f;

    for (int k0 = 0; k0 < K; k0 += 32) {
#pragma unroll
        for (int t = 0; t < 4; t++) {
            int lin = tid + 256 * t;
            int k = lin & 31, m = lin >> 5;
            As[k][m] = A[(long long)(m0 + m) * lda + k0 + k];
        }
#pragma unroll
        for (int t = 0; t < 8; t++) {
            int lin = tid + 256 * t;
            int k = lin & 31, n = lin >> 5;
            int r = n0 + n;
            if (r >= Brows) r = Brows - 1;
            Bs[k][n] = Bm[(long long)r * ldb + k0 + k];
        }
        __syncthreads();
#pragma unroll
        for (int k = 0; k < 32; k++) {
            float bv = Bs[k][tx];
#pragma unroll
            for (int i = 0; i < 8; i++)
                acc[i] += As[k][ty + 4 * i] * bv;
        }
        __syncthreads();
    }

    int n = n0 + tx;
    bool nok = (n < Nstore);
    float cb = (cbias && nok) ? cbias[z * cbZ + n] : 0.f;
#pragma unroll
    for (int i = 0; i < 8; i++) {
        int m = m0 + ty + 4 * i;
        float outv = 0.f;
        if (nok) {
            float v = acc[i] + cb;
            if (resid) v += resid[z * resZ + (long long)m * ldres + n];
            if (doRelu) v = fmaxf(v, 0.f);
            outv = v;
        }
        C[(long long)m * ldc + n] = outv;
    }
}

// ---------------- scatter E2flat -> E2P (pad rows), dP = emb . b_c ----------
__global__ void __launch_bounds__(256) scatter_e2_k(const float* __restrict__ bc) {
    int row = blockIdx.x;        // g*16 + n
    int b = blockIdx.y;
    int g = row >> 4, n = row & 15;
    int tid = threadIdx.x;
    bool valid = (n < g_cnt[b]);
    int t = g_off[b] + n;

    float* dst = g_E2P + ((long long)b * 64 + row) * CP2;
    const float* src = g_E2flat + ((long long)t * NGR + g) * CP2;
    for (int c = tid; c < CP2; c += 256)
        dst[c] = valid ? src[c] : 0.f;

    __shared__ float red[8];
    float v = valid ? g_emb[t * IDIM + g * GF + tid] * bc[g * GF + tid] : 0.f;
#pragma unroll
    for (int o = 16; o > 0; o >>= 1) v += __shfl_xor_sync(0xffffffffu, v, o);
    if ((tid & 31) == 0) red[tid >> 5] = v;
    __syncthreads();
    if (tid == 0) {
        float s = 0.f;
#pragma unroll
        for (int w = 0; w < 8; w++) s += red[w];
        g_dP[b * 64 + row] = s;
    }
}

// ---------------- adj GEMM: adj[b][64][s] = E2P @ fm (NN) + dP --------------
// tile 64m x 128n, 256 threads, 8x4 per thread; B loaded NN from fm[c][s].
__global__ void __launch_bounds__(256) adj_gemm_k(const float* __restrict__ fm) {
    __shared__ __align__(16) float As[32][68];
    __shared__ __align__(16) float Bs[32][132];

    int b = blockIdx.y;
    int s0 = blockIdx.x * 128;
    int tid = threadIdx.x;
    int tx = tid & 31, ty = tid >> 5;

    const float* A = g_E2P + (long long)b * 64 * CP2;
    const float* B = fm + (long long)b * DIN * SS;

    float acc[8][4];
#pragma unroll
    for (int i = 0; i < 8; i++)
#pragma unroll
        for (int j = 0; j < 4; j++) acc[i][j] = 0.f;

    for (int k0 = 0; k0 < CP2; k0 += 32) {
#pragma unroll
        for (int t = 0; t < 8; t++) {          // A: 64m x 32k
            int lin = tid + 256 * t;
            int k = lin & 31, m = lin >> 5;
            As[k][m] = A[m * CP2 + k0 + k];
        }
#pragma unroll
        for (int t = 0; t < 16; t++) {         // B: 32k x 128n (NN from fm)
            int lin = tid + 256 * t;
            int n = lin & 127, k = lin >> 7;
            int c = k0 + k; if (c >= DIN) c = DIN - 1;     // A pad zero covers
            int s = s0 + n; if (s >= SS) s = SS - 1;       // store masks pad
            Bs[k][n] = B[(long long)c * SS + s];
        }
        __syncthreads();
#pragma unroll
        for (int k = 0; k < 32; k++) {
            float a[8], bv[4];
            *(float4*)&a[0] = *(const float4*)&As[k][ty * 8];
            *(float4*)&a[4] = *(const float4*)&As[k][ty * 8 + 4];
            *(float4*)&bv[0] = *(const float4*)&Bs[k][tx * 4];
#pragma unroll
            for (int i = 0; i < 8; i++)
#pragma unroll
                for (int j = 0; j < 4; j++)
                    acc[i][j] += a[i] * bv[j];
        }
        __syncthreads();
    }

    float* C = g_adj + (long long)b * 64 * ADJ_LD;
#pragma unroll
    for (int i = 0; i < 8; i++) {
        int m = ty * 8 + i;
        float rb = g_dP[b * 64 + m];
#pragma unroll
        for (int j = 0; j < 4; j++) {
            int n = s0 + tx * 4 + j;
            C[(long long)m * ADJ_LD + n] = (n < SS) ? acc[i][j] + rb : 0.f;
        }
    }
}

// ---------------- R GEMM: R[b][64][c] = adj_sm @ fm^T (NT) ------------------
// tile 64m x 128n, 8x4 per thread; B rows = fm[c][:] (contiguous in k=s).
__global__ void __launch_bounds__(256) r_gemm_k(const float* __restrict__ fm) {
    __shared__ __align__(16) float As[32][68];
    __shared__ __align__(16) float Bs[32][132];

    int b = blockIdx.y;
    int n0 = blockIdx.x * 128;
    int tid = threadIdx.x;
    int tx = tid & 31, ty = tid >> 5;

    const float* A = g_adj + (long long)b * 64 * ADJ_LD;
    const float* B = fm + (long long)b * DIN * SS;

    float acc[8][4];
#pragma unroll
    for (int i = 0; i < 8; i++)
#pragma unroll
        for (int j = 0; j < 4; j++) acc[i][j] = 0.f;

    for (int k0 = 0; k0 < SS; k0 += 32) {
#pragma unroll
        for (int t = 0; t < 8; t++) {          // A: 64m x 32k
            int lin = tid + 256 * t;
            int k = lin & 31, m = lin >> 5;
            As[k][m] = A[(long long)m * ADJ_LD + k0 + k];
        }
#pragma unroll
        for (int t = 0; t < 16; t++) {         // B: 128n x 32k (NT from fm)
            int lin = tid + 256 * t;
            int k = lin & 31, n = lin >> 5;
            int c = n0 + n; if (c >= DIN) c = DIN - 1;     // store masks pad
            Bs[k][n] = B[(long long)c * SS + k0 + k];
        }
        __syncthreads();
#pragma unroll
        for (int k = 0; k < 32; k++) {
            float a[8], bv[4];
            *(float4*)&a[0] = *(const float4*)&As[k][ty * 8];
            *(float4*)&a[4] = *(const float4*)&As[k][ty * 8 + 4];
            *(float4*)&bv[0] = *(const float4*)&Bs[k][tx * 4];
#pragma unroll
            for (int i = 0; i < 8; i++)
#pragma unroll
                for (int j = 0; j < 4; j++)
                    acc[i][j] += a[i] * bv[j];
        }
        __syncthreads();
    }

    float* C = g_R + (long long)b * 64 * CP2;
#pragma unroll
    for (int i = 0; i < 8; i++) {
        int m = ty * 8 + i;
#pragma unroll
        for (int j = 0; j < 4; j++) {
            int n = n0 + tx * 4 + j;
            C[(long long)m * CP2 + n] = (n < DIN) ? acc[i][j] : 0.f;
        }
    }
}

// ---------------- softmax over s per valid (b,g,n) row ----------------------
__global__ void __launch_bounds__(256) softmax_k() {
    int n = blockIdx.x, g = blockIdx.y, b = blockIdx.z;
    if (n >= g_cnt[b]) return;
    float* row = g_adj + ((long long)(b * 64 + g * 16 + n)) * ADJ_LD;
    int tid = threadIdx.x;
    __shared__ float red[8];

    float mx = -1e30f;
    for (int s = tid; s < SS; s += 256) mx = fmaxf(mx, row[s]);
#pragma unroll
    for (int o = 16; o > 0; o >>= 1) mx = fmaxf(mx, __shfl_xor_sync(0xffffffffu, mx, o));
    if ((tid & 31) == 0) red[tid >> 5] = mx;
    __syncthreads();
    if (tid < 32) {
        float v = (tid < 8) ? red[tid] : -1e30f;
#pragma unroll
        for (int o = 4; o > 0; o >>= 1) v = fmaxf(v, __shfl_xor_sync(0xffffffffu, v, o));
        if (tid == 0) red[0] = v;
    }
    __syncthreads();
    mx = red[0];
    __syncthreads();

    float sum = 0.f;
    for (int s = tid; s < SS; s += 256) {
        float e = __expf(row[s] - mx);
        row[s] = e;
        sum += e;
    }
#pragma unroll
    for (int o = 16; o > 0; o >>= 1) sum += __shfl_xor_sync(0xffffffffu, sum, o);
    if ((tid & 31) == 0) red[tid >> 5] = sum;
    __syncthreads();
    if (tid < 32) {
        float v = (tid < 8) ? red[tid] : 0.f;
#pragma unroll
        for (int o = 4; o > 0; o >>= 1) v += __shfl_xor_sync(0xffffffffu, v, o);
        if (tid == 0) red[0] = v;
    }
    __syncthreads();
    float inv = 1.f / red[0];
    for (int s = tid; s < SS; s += 256) row[s] *= inv;
}

// ---------------- gather R -> Rf (ragged flat) -------------------------------
__global__ void __launch_bounds__(256) gather_rf_k() {
    int row = blockIdx.x;
    int b = blockIdx.y;
    int g = row >> 4, n = row & 15;
    if (n >= g_cnt[b]) return;
    int t = g_off[b] + n;
    int tid = threadIdx.x;
    const float* src = g_R + ((long long)b * 64 + row) * CP2;
    float* dst = g_Rf + ((long long)t * NGR + g) * CP2;
    for (int c = tid; c < CP2; c += 256)
        dst[c] = src[c];
}

// ---------------- launch ----------------------------------------------------
extern "C" void kernel_launch(void* const* d_in, const int* in_sizes, int n_in,
                              void* d_out, int out_size) {
    const float* actor = (const float*)d_in[0];
    const float* fmap  = (const float*)d_in[1];
    const float* W_a   = (const float*)d_in[2];
    const float* b_a   = (const float*)d_in[3];
    const float* W_c   = (const float*)d_in[4];
    const float* b_c   = (const float*)d_in[5];
    const float* W_h   = (const float*)d_in[6];
    const void*  counts = d_in[7];
    int nbias = 0;
    for (int i = 0; i < n_in; i++) {
        switch (in_sizes[i]) {
            case TOT * IDIM:      actor = (const float*)d_in[i]; break;
            case NB * DIN * SS:   fmap  = (const float*)d_in[i]; break;
            case NGR * GF * IDIM: W_a   = (const float*)d_in[i]; break;
            case NGR * GF * DIN:  W_c   = (const float*)d_in[i]; break;
            case NGR * GF * GF:   W_h   = (const float*)d_in[i]; break;
            case NGR * GF:
                if (nbias++ == 0) b_a = (const float*)d_in[i];
                else              b_c = (const float*)d_in[i];
                break;
            case NB:              counts = d_in[i]; break;
            default: break;
        }
    }
    float* out = (float*)d_out;

    float *emb_p, *wcT_p, *wcP_p, *e2f_p, *Rf_p, *flat_p;
    cudaGetSymbolAddress((void**)&emb_p, g_emb);
    cudaGetSymbolAddress((void**)&wcT_p, g_WcT);
    cudaGetSymbolAddress((void**)&wcP_p, g_WcP);
    cudaGetSymbolAddress((void**)&e2f_p, g_E2flat);
    cudaGetSymbolAddress((void**)&Rf_p, g_Rf);
    cudaGetSymbolAddress((void**)&flat_p, g_flat);

    // 0: ragged bookkeeping
    init_offsets_k<<<1, 32>>>(counts);
    // 1: W prep
    prep_w_k<<<(NGR * GF * CP2 + 255) / 256, 256>>>(W_c);
    // 2-3: emb = actor @ W_a^T + b_a (split-K)
    emb_part_k<<<dim3(5, 16, KSPLIT), 256>>>(actor, W_a);
    emb_reduce_k<<<(TOT * IDIM + 255) / 256, 256>>>(b_a);
    // 4: E2flat[t][g][c] = emb[t,g,:] @ WcT[g]^T
    gemm_flex_k<<<dim3(5, CP2 / 64, NGR), 256>>>(
        emb_p, IDIM, GF,
        wcT_p, GF, (long long)CP2 * GF, CP2,
        nullptr, 0, nullptr, 0, 0,
        e2f_p, NGR * CP2, CP2,
        GF, CP2, 0);
    // 5: scatter E2 -> padded rows + dP
    scatter_e2_k<<<dim3(64, NB), 256>>>(b_c);
    // 6: adj = E2P @ fm (NN) + dP
    adj_gemm_k<<<dim3(ADJ_LD / 128, NB), 256>>>(fmap);
    // 7: softmax over s
    softmax_k<<<dim3(NMAX, NGR, NB), 256>>>();
    // 8: R = adj_sm @ fm^T (NT)
    r_gemm_k<<<dim3(CP2 / 128, NB), 256>>>(fmap);
    // 9: gather R -> ragged flat
    gather_rf_k<<<dim3(64, NB), 256>>>();
    // 10: flat = Rf @ WcP^T + b_c + emb
    gemm_flex_k<<<dim3(5, NGR, NGR), 256>>>(
        Rf_p, NGR * CP2, CP2,
        wcP_p, CP2, (long long)GF * CP2, GF,
        b_c, GF,
        emb_p, IDIM, GF,
        flat_p, IDIM, GF,
        CP2, GF, 0);
    // 11: head: out = relu(flat @ W_h^T)
    gemm_flex_k<<<dim3(5, NGR, NGR), 256>>>(
        flat_p, IDIM, GF,
        W_h, GF, (long long)GF * GF, GF,
        nullptr, 0, nullptr, 0, 0,
        out, IDIM, GF,
        GF, GF, 1);
}

// round 12
// speedup vs baseline: 2.1427x; 1.1615x over previous
#include <cuda_runtime.h>
#include <cstdint>

// Problem constants
#define NGR 4
#define GF 256
#define DIN 834
#define SS 1568
#define NB 16
#define TOT 160
#define IDIM 1024
#define NMAX 16

#define CP2 896             // c padded (28 x 32)
#define ADJ_LD 1664         // s padded to 52 x 32 (2 x 26 chunks)
#define KSPLIT 8

// ---------------- scratch (static device globals) --------------------------
__device__ float g_emb[TOT * IDIM];
__device__ float g_embP[KSPLIT * TOT * IDIM];
__device__ float g_WcT[NGR * CP2 * GF];              // [g][c][f]
__device__ float g_WcP[NGR * GF * CP2];              // [g][f][c], zero pad
__device__ float g_E2flat[TOT * NGR * CP2];          // [t][g][c]
__device__ float g_E2P[NB * 64 * CP2];               // [b][g*16+n][c]
__device__ float g_dP[NB * 64];
__device__ float g_adj[NB * 64 * ADJ_LD];            // [b][g*16+n][s]
__device__ float g_Rp[2][NB * 64 * CP2];             // split-K partials
__device__ float g_Rf[TOT * NGR * CP2];              // [t][g][c]
__device__ float g_flat[TOT * IDIM];
__device__ int   g_off[NB];
__device__ int   g_cnt[NB];

// ---------------- K0: ragged bookkeeping ------------------------------------
__global__ void init_offsets_k(const void* __restrict__ counts) {
    if (threadIdx.x == 0 && blockIdx.x == 0) {
        const int* c32 = (const int*)counts;
        const long long* c64 = (const long long*)counts;
        long long s = 0;
        bool ok32 = true;
        for (int b = 0; b < NB; b++) {
            int v = c32[b];
            if (v < 0 || v > NMAX) ok32 = false;
            s += v;
        }
        if (s != TOT) ok32 = false;
        int acc = 0;
        for (int b = 0; b < NB; b++) {
            int c = ok32 ? c32[b] : (int)c64[b];
            if (c < 0) c = 0;
            if (c > NMAX) c = NMAX;
            g_off[b] = acc;
            g_cnt[b] = c;
            acc += c;
        }
    }
}

// ---------------- prep: WcP[g][f][c] (pad c) and WcT[g][c][f] ---------------
__global__ void __launch_bounds__(256) prep_w_k(const float* __restrict__ Wc) {
    int id = blockIdx.x * 256 + threadIdx.x;
    if (id >= NGR * GF * CP2) return;
    int c = id % CP2;
    int rf = id / CP2;
    int f = rf % GF, g = rf / GF;
    float v = (c < DIN) ? Wc[(long long)rf * DIN + c] : 0.f;
    g_WcP[id] = v;
    g_WcT[((long long)g * CP2 + c) * GF + f] = v;
}

// ---------------- emb split-K partial GEMM ----------------------------------
__global__ void __launch_bounds__(256) emb_part_k(
    const float* __restrict__ A, const float* __restrict__ Bm)
{
    int z = blockIdx.z;
    int kbase = z * (IDIM / KSPLIT);

    __shared__ __align__(16) float As[32][33];
    __shared__ __align__(16) float Bs[32][65];

    int tid = threadIdx.x;
    int m0 = blockIdx.x * 32;
    int n0 = blockIdx.y * 64;
    int tx = tid % 64, ty = tid / 64;

    float acc[8];
#pragma unroll
    for (int i = 0; i < 8; i++) acc[i] = 0.f;

    for (int k0 = kbase; k0 < kbase + IDIM / KSPLIT; k0 += 32) {
#pragma unroll
        for (int t = 0; t < 4; t++) {
            int lin = tid + 256 * t;
            int k = lin & 31, m = lin >> 5;
            As[k][m] = A[(m0 + m) * IDIM + k0 + k];
        }
#pragma unroll
        for (int t = 0; t < 8; t++) {
            int lin = tid + 256 * t;
            int k = lin & 31, n = lin >> 5;
            Bs[k][n] = Bm[(n0 + n) * IDIM + k0 + k];
        }
        __syncthreads();
#pragma unroll
        for (int k = 0; k < 32; k++) {
            float bv = Bs[k][tx];
#pragma unroll
            for (int i = 0; i < 8; i++)
                acc[i] += As[k][ty + 4 * i] * bv;
        }
        __syncthreads();
    }

    float* P = g_embP + (long long)z * TOT * IDIM;
#pragma unroll
    for (int i = 0; i < 8; i++) {
        int m = m0 + ty + 4 * i;
        P[m * IDIM + n0 + tx] = acc[i];
    }
}

__global__ void __launch_bounds__(256) emb_reduce_k(const float* __restrict__ ba) {
    int id = blockIdx.x * 256 + threadIdx.x;
    if (id >= TOT * IDIM) return;
    float v = ba[id & (IDIM - 1)];
#pragma unroll
    for (int z = 0; z < KSPLIT; z++)
        v += g_embP[z * (TOT * IDIM) + id];
    g_emb[id] = v;
}

// ---------------- flexible GEMM (small GEMMs): C = A @ B^T ------------------
__global__ void __launch_bounds__(256) gemm_flex_k(
    const float* __restrict__ A, int lda, long long aZ,
    const float* __restrict__ Bm, int ldb, long long bZ, int Brows,
    const float* __restrict__ cbias, long long cbZ,
    const float* __restrict__ resid, int ldres, long long resZ,
    float* __restrict__ C, int ldc, long long cZ,
    int K, int Nstore, int doRelu)
{
    int z = blockIdx.z;
    A  += (long long)z * aZ;
    Bm += (long long)z * bZ;
    C  += (long long)z * cZ;

    __shared__ __align__(16) float As[32][33];
    __shared__ __align__(16) float Bs[32][65];

    int tid = threadIdx.x;
    int m0 = blockIdx.x * 32;
    int n0 = blockIdx.y * 64;
    int tx = tid % 64, ty = tid / 64;

    float acc[8];
#pragma unroll
    for (int i = 0; i < 8; i++) acc[i] = 0.f;

    for (int k0 = 0; k0 < K; k0 += 32) {
#pragma unroll
        for (int t = 0; t < 4; t++) {
            int lin = tid + 256 * t;
            int k = lin & 31, m = lin >> 5;
            As[k][m] = A[(long long)(m0 + m) * lda + k0 + k];
        }
#pragma unroll
        for (int t = 0; t < 8; t++) {
            int lin = tid + 256 * t;
            int k = lin & 31, n = lin >> 5;
            int r = n0 + n;
            if (r >= Brows) r = Brows - 1;
            Bs[k][n] = Bm[(long long)r * ldb + k0 + k];
        }
        __syncthreads();
#pragma unroll
        for (int k = 0; k < 32; k++) {
            float bv = Bs[k][tx];
#pragma unroll
            for (int i = 0; i < 8; i++)
                acc[i] += As[k][ty + 4 * i] * bv;
        }
        __syncthreads();
    }

    int n = n0 + tx;
    bool nok = (n < Nstore);
    float cb = (cbias && nok) ? cbias[z * cbZ + n] : 0.f;
#pragma unroll
    for (int i = 0; i < 8; i++) {
        int m = m0 + ty + 4 * i;
        float outv = 0.f;
        if (nok) {
            float v = acc[i] + cb;
            if (resid) v += resid[z * resZ + (long long)m * ldres + n];
            if (doRelu) v = fmaxf(v, 0.f);
            outv = v;
        }
        C[(long long)m * ldc + n] = outv;
    }
}

// ---------------- scatter E2flat -> E2P (pad rows), dP = emb . b_c ----------
__global__ void __launch_bounds__(256) scatter_e2_k(const float* __restrict__ bc) {
    int row = blockIdx.x;        // g*16 + n
    int b = blockIdx.y;
    int g = row >> 4, n = row & 15;
    int tid = threadIdx.x;
    bool valid = (n < g_cnt[b]);
    int t = g_off[b] + n;

    float* dst = g_E2P + ((long long)b * 64 + row) * CP2;
    const float* src = g_E2flat + ((long long)t * NGR + g) * CP2;
    for (int c = tid; c < CP2; c += 256)
        dst[c] = valid ? src[c] : 0.f;

    __shared__ float red[8];
    float v = valid ? g_emb[t * IDIM + g * GF + tid] * bc[g * GF + tid] : 0.f;
#pragma unroll
    for (int o = 16; o > 0; o >>= 1) v += __shfl_xor_sync(0xffffffffu, v, o);
    if ((tid & 31) == 0) red[tid >> 5] = v;
    __syncthreads();
    if (tid == 0) {
        float s = 0.f;
#pragma unroll
        for (int w = 0; w < 8; w++) s += red[w];
        g_dP[b * 64 + row] = s;
    }
}

// ---------------- adj GEMM: adj[b][64][s] = E2P @ fm (NN) + dP --------------
__global__ void __launch_bounds__(256) adj_gemm_k(const float* __restrict__ fm) {
    __shared__ __align__(16) float As[32][68];
    __shared__ __align__(16) float Bs[32][132];

    int b = blockIdx.y;
    int s0 = blockIdx.x * 128;
    int tid = threadIdx.x;
    int tx = tid & 31, ty = tid >> 5;

    const float* A = g_E2P + (long long)b * 64 * CP2;
    const float* B = fm + (long long)b * DIN * SS;

    float acc[8][4];
#pragma unroll
    for (int i = 0; i < 8; i++)
#pragma unroll
        for (int j = 0; j < 4; j++) acc[i][j] = 0.f;

    for (int k0 = 0; k0 < CP2; k0 += 32) {
#pragma unroll
        for (int t = 0; t < 8; t++) {
            int lin = tid + 256 * t;
            int k = lin & 31, m = lin >> 5;
            As[k][m] = A[m * CP2 + k0 + k];
        }
#pragma unroll
        for (int t = 0; t < 16; t++) {
            int lin = tid + 256 * t;
            int n = lin & 127, k = lin >> 7;
            int c = k0 + k; if (c >= DIN) c = DIN - 1;
            int s = s0 + n; if (s >= SS) s = SS - 1;
            Bs[k][n] = B[(long long)c * SS + s];
        }
        __syncthreads();
#pragma unroll
        for (int k = 0; k < 32; k++) {
            float a[8], bv[4];
            *(float4*)&a[0] = *(const float4*)&As[k][ty * 8];
            *(float4*)&a[4] = *(const float4*)&As[k][ty * 8 + 4];
            *(float4*)&bv[0] = *(const float4*)&Bs[k][tx * 4];
#pragma unroll
            for (int i = 0; i < 8; i++)
#pragma unroll
                for (int j = 0; j < 4; j++)
                    acc[i][j] += a[i] * bv[j];
        }
        __syncthreads();
    }

    float* C = g_adj + (long long)b * 64 * ADJ_LD;
#pragma unroll
    for (int i = 0; i < 8; i++) {
        int m = ty * 8 + i;
        float rb = g_dP[b * 64 + m];
#pragma unroll
        for (int j = 0; j < 4; j++) {
            int n = s0 + tx * 4 + j;
            C[(long long)m * ADJ_LD + n] = (n < SS) ? acc[i][j] + rb : 0.f;
        }
    }
}

// ---------------- R GEMM (split-K x2): Rp[z] = adj_sm[k-half] @ fm^T --------
// k covers ADJ_LD (adj zero-padded past SS); fm col index clamped (adj=0 there)
__global__ void __launch_bounds__(256) r_gemm_k(const float* __restrict__ fm) {
    __shared__ __align__(16) float As[32][68];
    __shared__ __align__(16) float Bs[32][132];

    int b = blockIdx.y;
    int n0 = blockIdx.x * 128;
    int zk = blockIdx.z;                 // 0 / 1
    int kstart = zk * (ADJ_LD / 2);      // 832 each = 26 chunks
    int tid = threadIdx.x;
    int tx = tid & 31, ty = tid >> 5;

    const float* A = g_adj + (long long)b * 64 * ADJ_LD;
    const float* B = fm + (long long)b * DIN * SS;

    float acc[8][4];
#pragma unroll
    for (int i = 0; i < 8; i++)
#pragma unroll
        for (int j = 0; j < 4; j++) acc[i][j] = 0.f;

    for (int kc = 0; kc < ADJ_LD / 2; kc += 32) {
        int k0 = kstart + kc;
#pragma unroll
        for (int t = 0; t < 8; t++) {
            int lin = tid + 256 * t;
            int k = lin & 31, m = lin >> 5;
            As[k][m] = A[(long long)m * ADJ_LD + k0 + k];
        }
#pragma unroll
        for (int t = 0; t < 16; t++) {
            int lin = tid + 256 * t;
            int k = lin & 31, n = lin >> 5;
            int c = n0 + n; if (c >= DIN) c = DIN - 1;
            int s = k0 + k; if (s >= SS) s = SS - 1;   // adj=0 there
            Bs[k][n] = B[(long long)c * SS + s];
        }
        __syncthreads();
#pragma unroll
        for (int k = 0; k < 32; k++) {
            float a[8], bv[4];
            *(float4*)&a[0] = *(const float4*)&As[k][ty * 8];
            *(float4*)&a[4] = *(const float4*)&As[k][ty * 8 + 4];
            *(float4*)&bv[0] = *(const float4*)&Bs[k][tx * 4];
#pragma unroll
            for (int i = 0; i < 8; i++)
#pragma unroll
                for (int j = 0; j < 4; j++)
                    acc[i][j] += a[i] * bv[j];
        }
        __syncthreads();
    }

    float* C = g_Rp[zk] + (long long)b * 64 * CP2;
#pragma unroll
    for (int i = 0; i < 8; i++) {
        int m = ty * 8 + i;
#pragma unroll
        for (int j = 0; j < 4; j++) {
            int n = n0 + tx * 4 + j;
            C[(long long)m * CP2 + n] = (n < DIN) ? acc[i][j] : 0.f;
        }
    }
}

// ---------------- softmax over s per valid (b,g,n) row ----------------------
__global__ void __launch_bounds__(256) softmax_k() {
    int n = blockIdx.x, g = blockIdx.y, b = blockIdx.z;
    if (n >= g_cnt[b]) return;
    float* row = g_adj + ((long long)(b * 64 + g * 16 + n)) * ADJ_LD;
    int tid = threadIdx.x;
    __shared__ float red[8];

    float mx = -1e30f;
    for (int s = tid; s < SS; s += 256) mx = fmaxf(mx, row[s]);
#pragma unroll
    for (int o = 16; o > 0; o >>= 1) mx = fmaxf(mx, __shfl_xor_sync(0xffffffffu, mx, o));
    if ((tid & 31) == 0) red[tid >> 5] = mx;
    __syncthreads();
    if (tid < 32) {
        float v = (tid < 8) ? red[tid] : -1e30f;
#pragma unroll
        for (int o = 4; o > 0; o >>= 1) v = fmaxf(v, __shfl_xor_sync(0xffffffffu, v, o));
        if (tid == 0) red[0] = v;
    }
    __syncthreads();
    mx = red[0];
    __syncthreads();

    float sum = 0.f;
    for (int s = tid; s < SS; s += 256) {
        float e = __expf(row[s] - mx);
        row[s] = e;
        sum += e;
    }
#pragma unroll
    for (int o = 16; o > 0; o >>= 1) sum += __shfl_xor_sync(0xffffffffu, sum, o);
    if ((tid & 31) == 0) red[tid >> 5] = sum;
    __syncthreads();
    if (tid < 32) {
        float v = (tid < 8) ? red[tid] : 0.f;
#pragma unroll
        for (int o = 4; o > 0; o >>= 1) v += __shfl_xor_sync(0xffffffffu, v, o);
        if (tid == 0) red[0] = v;
    }
    __syncthreads();
    float inv = 1.f / red[0];
    for (int s = tid; s < SS; s += 256) row[s] *= inv;
}

// ---------------- gather Rp0+Rp1 -> Rf (ragged flat) -------------------------
__global__ void __launch_bounds__(256) gather_rf_k() {
    int row = blockIdx.x;
    int b = blockIdx.y;
    int g = row >> 4, n = row & 15;
    if (n >= g_cnt[b]) return;
    int t = g_off[b] + n;
    int tid = threadIdx.x;
    const float* s0 = g_Rp[0] + ((long long)b * 64 + row) * CP2;
    const float* s1 = g_Rp[1] + ((long long)b * 64 + row) * CP2;
    float* dst = g_Rf + ((long long)t * NGR + g) * CP2;
    for (int c = tid; c < CP2; c += 256)
        dst[c] = s0[c] + s1[c];
}

// ---------------- launch ----------------------------------------------------
extern "C" void kernel_launch(void* const* d_in, const int* in_sizes, int n_in,
                              void* d_out, int out_size) {
    const float* actor = (const float*)d_in[0];
    const float* fmap  = (const float*)d_in[1];
    const float* W_a   = (const float*)d_in[2];
    const float* b_a   = (const float*)d_in[3];
    const float* W_c   = (const float*)d_in[4];
    const float* b_c   = (const float*)d_in[5];
    const float* W_h   = (const float*)d_in[6];
    const void*  counts = d_in[7];
    int nbias = 0;
    for (int i = 0; i < n_in; i++) {
        switch (in_sizes[i]) {
            case TOT * IDIM:      actor = (const float*)d_in[i]; break;
            case NB * DIN * SS:   fmap  = (const float*)d_in[i]; break;
            case NGR * GF * IDIM: W_a   = (const float*)d_in[i]; break;
            case NGR * GF * DIN:  W_c   = (const float*)d_in[i]; break;
            case NGR * GF * GF:   W_h   = (const float*)d_in[i]; break;
            case NGR * GF:
                if (nbias++ == 0) b_a = (const float*)d_in[i];
                else              b_c = (const float*)d_in[i];
                break;
            case NB:              counts = d_in[i]; break;
            default: break;
        }
    }
    float* out = (float*)d_out;

    float *emb_p, *wcT_p, *wcP_p, *e2f_p, *Rf_p, *flat_p;
    cudaGetSymbolAddress((void**)&emb_p, g_emb);
    cudaGetSymbolAddress((void**)&wcT_p, g_WcT);
    cudaGetSymbolAddress((void**)&wcP_p, g_WcP);
    cudaGetSymbolAddress((void**)&e2f_p, g_E2flat);
    cudaGetSymbolAddress((void**)&Rf_p, g_Rf);
    cudaGetSymbolAddress((void**)&flat_p, g_flat);

    // 0: ragged bookkeeping
    init_offsets_k<<<1, 32>>>(counts);
    // 1: W prep
    prep_w_k<<<(NGR * GF * CP2 + 255) / 256, 256>>>(W_c);
    // 2-3: emb = actor @ W_a^T + b_a (split-K x8)
    emb_part_k<<<dim3(5, 16, KSPLIT), 256>>>(actor, W_a);
    emb_reduce_k<<<(TOT * IDIM + 255) / 256, 256>>>(b_a);
    // 4: E2flat[t][g][c] = emb[t,g,:] @ WcT[g]^T
    gemm_flex_k<<<dim3(5, CP2 / 64, NGR), 256>>>(
        emb_p, IDIM, GF,
        wcT_p, GF, (long long)CP2 * GF, CP2,
        nullptr, 0, nullptr, 0, 0,
        e2f_p, NGR * CP2, CP2,
        GF, CP2, 0);
    // 5: scatter E2 -> padded rows + dP
    scatter_e2_k<<<dim3(64, NB), 256>>>(b_c);
    // 6: adj = E2P @ fm (NN) + dP
    adj_gemm_k<<<dim3(ADJ_LD / 128, NB), 256>>>(fmap);
    // 7: softmax over s
    softmax_k<<<dim3(NMAX, NGR, NB), 256>>>();
    // 8: R partials = adj_sm @ fm^T (NT, split-K x2)
    r_gemm_k<<<dim3(CP2 / 128, NB, 2), 256>>>(fmap);
    // 9: gather Rp0+Rp1 -> ragged flat
    gather_rf_k<<<dim3(64, NB), 256>>>();
    // 10: flat = Rf @ WcP^T + b_c + emb
    gemm_flex_k<<<dim3(5, NGR, NGR), 256>>>(
        Rf_p, NGR * CP2, CP2,
        wcP_p, CP2, (long long)GF * CP2, GF,
        b_c, GF,
        emb_p, IDIM, GF,
        flat_p, IDIM, GF,
        CP2, GF, 0);
    // 11: head: out = relu(flat @ W_h^T)
    gemm_flex_k<<<dim3(5, NGR, NGR), 256>>>(
        flat_p, IDIM, GF,
        W_h, GF, (long long)GF * GF, GF,
        nullptr, 0, nullptr, 0, 0,
        out, IDIM, GF,
        GF, GF, 1);
}

// round 13
// speedup vs baseline: 2.5175x; 1.1749x over previous
#include <cuda_runtime.h>
#include <cstdint>

// Problem constants
#define NGR 4
#define GF 256
#define DIN 834
#define SS 1568
#define NB 16
#define TOT 160
#define IDIM 1024
#define NMAX 16

#define CP2 896             // c padded (28 x 32)
#define ADJ_LD 1664         // s padded (52 x 32)
#define KSPLIT 8
#define RSPLIT 4            // r_gemm split-K (1664/4 = 416 = 13 x 32)
#define ASPLIT 2            // adj_gemm split-K (896/2 = 448 = 14 x 32)

// ---------------- scratch (static device globals) --------------------------
__device__ float g_emb[TOT * IDIM];
__device__ float g_embP[KSPLIT * TOT * IDIM];
__device__ float g_WcT[NGR * CP2 * GF];              // [g][c][f]
__device__ float g_WcP[NGR * GF * CP2];              // [g][f][c], zero pad
__device__ float g_E2flat[TOT * NGR * CP2];          // [t][g][c]
__device__ float g_E2P[NB * 64 * CP2];               // [b][g*16+n][c]
__device__ float g_dP[NB * 64];
__device__ float g_adjP[ASPLIT][NB * 64 * ADJ_LD];   // adj logit partials
__device__ float g_adj[NB * 64 * ADJ_LD];            // softmaxed; zero init
__device__ float g_Rp[RSPLIT][NB * 64 * CP2];        // R split-K partials
__device__ float g_Rf[TOT * NGR * CP2];              // [t][g][c]
__device__ float g_flat[TOT * IDIM];
__device__ int   g_off[NB];
__device__ int   g_cnt[NB];

// ---------------- K0: ragged bookkeeping ------------------------------------
__global__ void init_offsets_k(const void* __restrict__ counts) {
    if (threadIdx.x == 0 && blockIdx.x == 0) {
        const int* c32 = (const int*)counts;
        const long long* c64 = (const long long*)counts;
        long long s = 0;
        bool ok32 = true;
        for (int b = 0; b < NB; b++) {
            int v = c32[b];
            if (v < 0 || v > NMAX) ok32 = false;
            s += v;
        }
        if (s != TOT) ok32 = false;
        int acc = 0;
        for (int b = 0; b < NB; b++) {
            int c = ok32 ? c32[b] : (int)c64[b];
            if (c < 0) c = 0;
            if (c > NMAX) c = NMAX;
            g_off[b] = acc;
            g_cnt[b] = c;
            acc += c;
        }
    }
}

// ---------------- prep: WcP[g][f][c] (pad c) and WcT[g][c][f] ---------------
__global__ void __launch_bounds__(256) prep_w_k(const float* __restrict__ Wc) {
    int id = blockIdx.x * 256 + threadIdx.x;
    if (id >= NGR * GF * CP2) return;
    int c = id % CP2;
    int rf = id / CP2;
    int f = rf % GF, g = rf / GF;
    float v = (c < DIN) ? Wc[(long long)rf * DIN + c] : 0.f;
    g_WcP[id] = v;
    g_WcT[((long long)g * CP2 + c) * GF + f] = v;
}

// ---------------- emb split-K partial GEMM ----------------------------------
__global__ void __launch_bounds__(256) emb_part_k(
    const float* __restrict__ A, const float* __restrict__ Bm)
{
    int z = blockIdx.z;
    int kbase = z * (IDIM / KSPLIT);

    __shared__ __align__(16) float As[32][33];
    __shared__ __align__(16) float Bs[32][65];

    int tid = threadIdx.x;
    int m0 = blockIdx.x * 32;
    int n0 = blockIdx.y * 64;
    int tx = tid % 64, ty = tid / 64;

    float acc[8];
#pragma unroll
    for (int i = 0; i < 8; i++) acc[i] = 0.f;

    for (int k0 = kbase; k0 < kbase + IDIM / KSPLIT; k0 += 32) {
#pragma unroll
        for (int t = 0; t < 4; t++) {
            int lin = tid + 256 * t;
            int k = lin & 31, m = lin >> 5;
            As[k][m] = A[(m0 + m) * IDIM + k0 + k];
        }
#pragma unroll
        for (int t = 0; t < 8; t++) {
            int lin = tid + 256 * t;
            int k = lin & 31, n = lin >> 5;
            Bs[k][n] = Bm[(n0 + n) * IDIM + k0 + k];
        }
        __syncthreads();
#pragma unroll
        for (int k = 0; k < 32; k++) {
            float bv = Bs[k][tx];
#pragma unroll
            for (int i = 0; i < 8; i++)
                acc[i] += As[k][ty + 4 * i] * bv;
        }
        __syncthreads();
    }

    float* P = g_embP + (long long)z * TOT * IDIM;
#pragma unroll
    for (int i = 0; i < 8; i++) {
        int m = m0 + ty + 4 * i;
        P[m * IDIM + n0 + tx] = acc[i];
    }
}

__global__ void __launch_bounds__(256) emb_reduce_k(const float* __restrict__ ba) {
    int id = blockIdx.x * 256 + threadIdx.x;
    if (id >= TOT * IDIM) return;
    float v = ba[id & (IDIM - 1)];
#pragma unroll
    for (int z = 0; z < KSPLIT; z++)
        v += g_embP[z * (TOT * IDIM) + id];
    g_emb[id] = v;
}

// ---------------- flexible GEMM (small GEMMs): C = A @ B^T ------------------
__global__ void __launch_bounds__(256) gemm_flex_k(
    const float* __restrict__ A, int lda, long long aZ,
    const float* __restrict__ Bm, int ldb, long long bZ, int Brows,
    const float* __restrict__ cbias, long long cbZ,
    const float* __restrict__ resid, int ldres, long long resZ,
    float* __restrict__ C, int ldc, long long cZ,
    int K, int Nstore, int doRelu)
{
    int z = blockIdx.z;
    A  += (long long)z * aZ;
    Bm += (long long)z * bZ;
    C  += (long long)z * cZ;

    __shared__ __align__(16) float As[32][33];
    __shared__ __align__(16) float Bs[32][65];

    int tid = threadIdx.x;
    int m0 = blockIdx.x * 32;
    int n0 = blockIdx.y * 64;
    int tx = tid % 64, ty = tid / 64;

    float acc[8];
#pragma unroll
    for (int i = 0; i < 8; i++) acc[i] = 0.f;

    for (int k0 = 0; k0 < K; k0 += 32) {
#pragma unroll
        for (int t = 0; t < 4; t++) {
            int lin = tid + 256 * t;
            int k = lin & 31, m = lin >> 5;
            As[k][m] = A[(long long)(m0 + m) * lda + k0 + k];
        }
#pragma unroll
        for (int t = 0; t < 8; t++) {
            int lin = tid + 256 * t;
            int k = lin & 31, n = lin >> 5;
            int r = n0 + n;
            if (r >= Brows) r = Brows - 1;
            Bs[k][n] = Bm[(long long)r * ldb + k0 + k];
        }
        __syncthreads();
#pragma unroll
        for (int k = 0; k < 32; k++) {
            float bv = Bs[k][tx];
#pragma unroll
            for (int i = 0; i < 8; i++)
                acc[i] += As[k][ty + 4 * i] * bv;
        }
        __syncthreads();
    }

    int n = n0 + tx;
    bool nok = (n < Nstore);
    float cb = (cbias && nok) ? cbias[z * cbZ + n] : 0.f;
#pragma unroll
    for (int i = 0; i < 8; i++) {
        int m = m0 + ty + 4 * i;
        float outv = 0.f;
        if (nok) {
            float v = acc[i] + cb;
            if (resid) v += resid[z * resZ + (long long)m * ldres + n];
            if (doRelu) v = fmaxf(v, 0.f);
            outv = v;
        }
        C[(long long)m * ldc + n] = outv;
    }
}

// ---------------- scatter E2flat -> E2P (pad rows), dP = emb . b_c ----------
__global__ void __launch_bounds__(256) scatter_e2_k(const float* __restrict__ bc) {
    int row = blockIdx.x;        // g*16 + n
    int b = blockIdx.y;
    int g = row >> 4, n = row & 15;
    int tid = threadIdx.x;
    bool valid = (n < g_cnt[b]);
    int t = g_off[b] + n;

    float* dst = g_E2P + ((long long)b * 64 + row) * CP2;
    const float* src = g_E2flat + ((long long)t * NGR + g) * CP2;
    for (int c = tid; c < CP2; c += 256)
        dst[c] = valid ? src[c] : 0.f;

    __shared__ float red[8];
    float v = valid ? g_emb[t * IDIM + g * GF + tid] * bc[g * GF + tid] : 0.f;
#pragma unroll
    for (int o = 16; o > 0; o >>= 1) v += __shfl_xor_sync(0xffffffffu, v, o);
    if ((tid & 31) == 0) red[tid >> 5] = v;
    __syncthreads();
    if (tid == 0) {
        float s = 0.f;
#pragma unroll
        for (int w = 0; w < 8; w++) s += red[w];
        g_dP[b * 64 + row] = s;
    }
}

// ---------------- adj GEMM (split-K x2): adjP[z] = E2P[k-half] @ fm ---------
__global__ void __launch_bounds__(256) adj_gemm_k(const float* __restrict__ fm) {
    __shared__ __align__(16) float As[32][68];
    __shared__ __align__(16) float Bs[32][132];

    int b = blockIdx.y;
    int s0 = blockIdx.x * 128;
    int zk = blockIdx.z;
    int kstart = zk * (CP2 / ASPLIT);    // 448 = 14 chunks
    int tid = threadIdx.x;
    int tx = tid & 31, ty = tid >> 5;

    const float* A = g_E2P + (long long)b * 64 * CP2;
    const float* B = fm + (long long)b * DIN * SS;

    float acc[8][4];
#pragma unroll
    for (int i = 0; i < 8; i++)
#pragma unroll
        for (int j = 0; j < 4; j++) acc[i][j] = 0.f;

    for (int kc = 0; kc < CP2 / ASPLIT; kc += 32) {
        int k0 = kstart + kc;
#pragma unroll
        for (int t = 0; t < 8; t++) {
            int lin = tid + 256 * t;
            int k = lin & 31, m = lin >> 5;
            As[k][m] = A[m * CP2 + k0 + k];
        }
#pragma unroll
        for (int t = 0; t < 16; t++) {
            int lin = tid + 256 * t;
            int n = lin & 127, k = lin >> 7;
            int c = k0 + k; if (c >= DIN) c = DIN - 1;     // E2P pad zero covers
            int s = s0 + n; if (s >= SS) s = SS - 1;       // store masks pad
            Bs[k][n] = B[(long long)c * SS + s];
        }
        __syncthreads();
#pragma unroll
        for (int k = 0; k < 32; k++) {
            float a[8], bv[4];
            *(float4*)&a[0] = *(const float4*)&As[k][ty * 8];
            *(float4*)&a[4] = *(const float4*)&As[k][ty * 8 + 4];
            *(float4*)&bv[0] = *(const float4*)&Bs[k][tx * 4];
#pragma unroll
            for (int i = 0; i < 8; i++)
#pragma unroll
                for (int j = 0; j < 4; j++)
                    acc[i][j] += a[i] * bv[j];
        }
        __syncthreads();
    }

    float* C = g_adjP[zk] + (long long)b * 64 * ADJ_LD;
#pragma unroll
    for (int i = 0; i < 8; i++) {
        int m = ty * 8 + i;
        float rb = (zk == 0) ? g_dP[b * 64 + m] : 0.f;
#pragma unroll
        for (int j = 0; j < 4; j++) {
            int n = s0 + tx * 4 + j;
            C[(long long)m * ADJ_LD + n] = (n < SS) ? acc[i][j] + rb : 0.f;
        }
    }
}

// ---------------- softmax: sum adj partials, softmax, write g_adj -----------
// g_adj invalid rows / pad cols stay statically zero (never written).
__global__ void __launch_bounds__(256) softmax_k() {
    int n = blockIdx.x, g = blockIdx.y, b = blockIdx.z;
    if (n >= g_cnt[b]) return;
    long long roff = (long long)(b * 64 + g * 16 + n) * ADJ_LD;
    const float* p0 = g_adjP[0] + roff;
    const float* p1 = g_adjP[1] + roff;
    float* row = g_adj + roff;
    int tid = threadIdx.x;
    __shared__ float red[8];

    float mx = -1e30f;
    for (int s = tid; s < SS; s += 256) mx = fmaxf(mx, p0[s] + p1[s]);
#pragma unroll
    for (int o = 16; o > 0; o >>= 1) mx = fmaxf(mx, __shfl_xor_sync(0xffffffffu, mx, o));
    if ((tid & 31) == 0) red[tid >> 5] = mx;
    __syncthreads();
    if (tid < 32) {
        float v = (tid < 8) ? red[tid] : -1e30f;
#pragma unroll
        for (int o = 4; o > 0; o >>= 1) v = fmaxf(v, __shfl_xor_sync(0xffffffffu, v, o));
        if (tid == 0) red[0] = v;
    }
    __syncthreads();
    mx = red[0];
    __syncthreads();

    float sum = 0.f;
    for (int s = tid; s < SS; s += 256) {
        float e = __expf(p0[s] + p1[s] - mx);
        row[s] = e;
        sum += e;
    }
#pragma unroll
    for (int o = 16; o > 0; o >>= 1) sum += __shfl_xor_sync(0xffffffffu, sum, o);
    if ((tid & 31) == 0) red[tid >> 5] = sum;
    __syncthreads();
    if (tid < 32) {
        float v = (tid < 8) ? red[tid] : 0.f;
#pragma unroll
        for (int o = 4; o > 0; o >>= 1) v += __shfl_xor_sync(0xffffffffu, v, o);
        if (tid == 0) red[0] = v;
    }
    __syncthreads();
    float inv = 1.f / red[0];
    for (int s = tid; s < SS; s += 256) row[s] *= inv;
}

// ---------------- R GEMM (split-K x4): Rp[z] = adj_sm[k-quarter] @ fm^T -----
__global__ void __launch_bounds__(256) r_gemm_k(const float* __restrict__ fm) {
    __shared__ __align__(16) float As[32][68];
    __shared__ __align__(16) float Bs[32][132];

    int b = blockIdx.y;
    int n0 = blockIdx.x * 128;
    int zk = blockIdx.z;
    int kstart = zk * (ADJ_LD / RSPLIT);   // 416 = 13 chunks
    int tid = threadIdx.x;
    int tx = tid & 31, ty = tid >> 5;

    const float* A = g_adj + (long long)b * 64 * ADJ_LD;
    const float* B = fm + (long long)b * DIN * SS;

    float acc[8][4];
#pragma unroll
    for (int i = 0; i < 8; i++)
#pragma unroll
        for (int j = 0; j < 4; j++) acc[i][j] = 0.f;

    for (int kc = 0; kc < ADJ_LD / RSPLIT; kc += 32) {
        int k0 = kstart + kc;
#pragma unroll
        for (int t = 0; t < 8; t++) {
            int lin = tid + 256 * t;
            int k = lin & 31, m = lin >> 5;
            As[k][m] = A[(long long)m * ADJ_LD + k0 + k];
        }
#pragma unroll
        for (int t = 0; t < 16; t++) {
            int lin = tid + 256 * t;
            int k = lin & 31, n = lin >> 5;
            int c = n0 + n; if (c >= DIN) c = DIN - 1;     // store masks pad
            int s = k0 + k; if (s >= SS) s = SS - 1;       // adj=0 there
            Bs[k][n] = B[(long long)c * SS + s];
        }
        __syncthreads();
#pragma unroll
        for (int k = 0; k < 32; k++) {
            float a[8], bv[4];
            *(float4*)&a[0] = *(const float4*)&As[k][ty * 8];
            *(float4*)&a[4] = *(const float4*)&As[k][ty * 8 + 4];
            *(float4*)&bv[0] = *(const float4*)&Bs[k][tx * 4];
#pragma unroll
            for (int i = 0; i < 8; i++)
#pragma unroll
                for (int j = 0; j < 4; j++)
                    acc[i][j] += a[i] * bv[j];
        }
        __syncthreads();
    }

    float* C = g_Rp[zk] + (long long)b * 64 * CP2;
#pragma unroll
    for (int i = 0; i < 8; i++) {
        int m = ty * 8 + i;
#pragma unroll
        for (int j = 0; j < 4; j++) {
            int n = n0 + tx * 4 + j;
            C[(long long)m * CP2 + n] = (n < DIN) ? acc[i][j] : 0.f;
        }
    }
}

// ---------------- gather sum(Rp) -> Rf (ragged flat) -------------------------
__global__ void __launch_bounds__(256) gather_rf_k() {
    int row = blockIdx.x;
    int b = blockIdx.y;
    int g = row >> 4, n = row & 15;
    if (n >= g_cnt[b]) return;
    int t = g_off[b] + n;
    int tid = threadIdx.x;
    long long roff = ((long long)b * 64 + row) * CP2;
    float* dst = g_Rf + ((long long)t * NGR + g) * CP2;
    for (int c = tid; c < CP2; c += 256) {
        float v = 0.f;
#pragma unroll
        for (int z = 0; z < RSPLIT; z++)
            v += g_Rp[z][roff + c];
        dst[c] = v;
    }
}

// ---------------- launch ----------------------------------------------------
extern "C" void kernel_launch(void* const* d_in, const int* in_sizes, int n_in,
                              void* d_out, int out_size) {
    const float* actor = (const float*)d_in[0];
    const float* fmap  = (const float*)d_in[1];
    const float* W_a   = (const float*)d_in[2];
    const float* b_a   = (const float*)d_in[3];
    const float* W_c   = (const float*)d_in[4];
    const float* b_c   = (const float*)d_in[5];
    const float* W_h   = (const float*)d_in[6];
    const void*  counts = d_in[7];
    int nbias = 0;
    for (int i = 0; i < n_in; i++) {
        switch (in_sizes[i]) {
            case TOT * IDIM:      actor = (const float*)d_in[i]; break;
            case NB * DIN * SS:   fmap  = (const float*)d_in[i]; break;
            case NGR * GF * IDIM: W_a   = (const float*)d_in[i]; break;
            case NGR * GF * DIN:  W_c   = (const float*)d_in[i]; break;
            case NGR * GF * GF:   W_h   = (const float*)d_in[i]; break;
            case NGR * GF:
                if (nbias++ == 0) b_a = (const float*)d_in[i];
                else              b_c = (const float*)d_in[i];
                break;
            case NB:              counts = d_in[i]; break;
            default: break;
        }
    }
    float* out = (float*)d_out;

    float *emb_p, *wcT_p, *wcP_p, *e2f_p, *Rf_p, *flat_p;
    cudaGetSymbolAddress((void**)&emb_p, g_emb);
    cudaGetSymbolAddress((void**)&wcT_p, g_WcT);
    cudaGetSymbolAddress((void**)&wcP_p, g_WcP);
    cudaGetSymbolAddress((void**)&e2f_p, g_E2flat);
    cudaGetSymbolAddress((void**)&Rf_p, g_Rf);
    cudaGetSymbolAddress((void**)&flat_p, g_flat);

    // 0: ragged bookkeeping
    init_offsets_k<<<1, 32>>>(counts);
    // 1: W prep
    prep_w_k<<<(NGR * GF * CP2 + 255) / 256, 256>>>(W_c);
    // 2-3: emb = actor @ W_a^T + b_a (split-K x8)
    emb_part_k<<<dim3(5, 16, KSPLIT), 256>>>(actor, W_a);
    emb_reduce_k<<<(TOT * IDIM + 255) / 256, 256>>>(b_a);
    // 4: E2flat[t][g][c] = emb[t,g,:] @ WcT[g]^T
    gemm_flex_k<<<dim3(5, CP2 / 64, NGR), 256>>>(
        emb_p, IDIM, GF,
        wcT_p, GF, (long long)CP2 * GF, CP2,
        nullptr, 0, nullptr, 0, 0,
        e2f_p, NGR * CP2, CP2,
        GF, CP2, 0);
    // 5: scatter E2 -> padded rows + dP
    scatter_e2_k<<<dim3(64, NB), 256>>>(b_c);
    // 6: adj partials = E2P @ fm (NN, split-K x2)
    adj_gemm_k<<<dim3(ADJ_LD / 128, NB, ASPLIT), 256>>>(fmap);
    // 7: softmax (sums partials) -> g_adj
    softmax_k<<<dim3(NMAX, NGR, NB), 256>>>();
    // 8: R partials = adj_sm @ fm^T (NT, split-K x4)
    r_gemm_k<<<dim3(CP2 / 128, NB, RSPLIT), 256>>>(fmap);
    // 9: gather sum(Rp) -> ragged flat
    gather_rf_k<<<dim3(64, NB), 256>>>();
    // 10: flat = Rf @ WcP^T + b_c + emb
    gemm_flex_k<<<dim3(5, NGR, NGR), 256>>>(
        Rf_p, NGR * CP2, CP2,
        wcP_p, CP2, (long long)GF * CP2, GF,
        b_c, GF,
        emb_p, IDIM, GF,
        flat_p, IDIM, GF,
        CP2, GF, 0);
    // 11: head: out = relu(flat @ W_h^T)
    gemm_flex_k<<<dim3(5, NGR, NGR), 256>>>(
        flat_p, IDIM, GF,
        W_h, GF, (long long)GF * GF, GF,
        nullptr, 0, nullptr, 0, 0,
        out, IDIM, GF,
        GF, GF, 1);
}

// round 14
// speedup vs baseline: 2.7131x; 1.0777x over previous
#include <cuda_runtime.h>
#include <cuda_bf16.h>
#include <cstdint>

// Problem constants
#define NGR 4
#define GF 256
#define DIN 834
#define SS 1568
#define NB 16
#define TOT 160
#define IDIM 1024
#define NMAX 16

#define CP2 896             // c padded (28 x 32)
#define ADJ_LD 1664         // s padded (52 x 32)
#define SROWS 1664          // fmT s rows (13 x 128)
#define KSPLIT 8
#define RSPLIT 4
#define ASPLIT 2

// mma smem: RS2=80B row stride, chunk k=32 bf16 (64B) per stage slot
#define RS2 80
#define A_TB (64 * RS2)             // 5120
#define B_TB (128 * RS2)            // 10240
#define AH2 0
#define AL2 (A_TB)
#define BH2 (2 * A_TB)
#define BL2 (2 * A_TB + B_TB)
#define STG2 (2 * A_TB + 2 * B_TB)  // 30720
#define SMEM2 (2 * STG2)            // 61440

// ---------------- scratch (static device globals) --------------------------
__device__ float g_emb[TOT * IDIM];
__device__ float g_embP[KSPLIT * TOT * IDIM];
__device__ float g_WcT[NGR * CP2 * GF];              // [g][c][f]
__device__ float g_WcP[NGR * GF * CP2];              // [g][f][c], zero pad
__device__ float g_E2flat[TOT * NGR * CP2];          // [t][g][c]
__device__ __nv_bfloat16 g_e2h[NB * 64 * CP2];       // A of adj (hi), pad zero
__device__ __nv_bfloat16 g_e2l[NB * 64 * CP2];
__device__ float g_dP[NB * 64];
__device__ __nv_bfloat16 g_fmTh[(long long)NB * SROWS * CP2];  // [b][s][c]
__device__ __nv_bfloat16 g_fmTl[(long long)NB * SROWS * CP2];
__device__ __nv_bfloat16 g_fmCh[(long long)NB * DIN * SS];     // [b][c][s]
__device__ __nv_bfloat16 g_fmCl[(long long)NB * DIN * SS];
__device__ float g_adjP[ASPLIT][NB * 64 * ADJ_LD];   // adj logit partials
__device__ __nv_bfloat16 g_adjh[NB * 64 * ADJ_LD];   // softmaxed, zero-static
__device__ __nv_bfloat16 g_adjl[NB * 64 * ADJ_LD];
__device__ float g_Rp[RSPLIT][NB * 64 * CP2];
__device__ float g_Rf[TOT * NGR * CP2];
__device__ float g_flat[TOT * IDIM];
__device__ int   g_off[NB];
__device__ int   g_cnt[NB];

// ---------------- PTX helpers ------------------------------------------------
__device__ __forceinline__ uint32_t smem_u32(const void* p) {
    uint32_t a;
    asm("{ .reg .u64 t; cvta.to.shared.u64 t, %1; cvt.u32.u64 %0, t; }"
        : "=r"(a) : "l"(p));
    return a;
}
__device__ __forceinline__ void cp16(uint32_t dst, const void* src) {
    asm volatile("cp.async.cg.shared.global [%0], [%1], 16;"
                 :: "r"(dst), "l"(src) : "memory");
}
__device__ __forceinline__ void cp_commit() {
    asm volatile("cp.async.commit_group;" ::: "memory");
}
template <int N>
__device__ __forceinline__ void cp_wait() {
    asm volatile("cp.async.wait_group %0;" :: "n"(N) : "memory");
}
__device__ __forceinline__ void ldsm4(uint32_t& r0, uint32_t& r1, uint32_t& r2,
                                      uint32_t& r3, uint32_t a) {
    asm volatile("ldmatrix.sync.aligned.m8n8.x4.shared.b16 {%0,%1,%2,%3}, [%4];"
                 : "=r"(r0), "=r"(r1), "=r"(r2), "=r"(r3) : "r"(a));
}
__device__ __forceinline__ void mma_bf16(float* c, const uint32_t* a,
                                         uint32_t b0, uint32_t b1) {
    asm volatile(
        "mma.sync.aligned.m16n8k16.row.col.f32.bf16.bf16.f32 "
        "{%0,%1,%2,%3}, {%4,%5,%6,%7}, {%8,%9}, {%0,%1,%2,%3};"
        : "+f"(c[0]), "+f"(c[1]), "+f"(c[2]), "+f"(c[3])
        : "r"(a[0]), "r"(a[1]), "r"(a[2]), "r"(a[3]), "r"(b0), "r"(b1));
}

// ---------------- K0: ragged bookkeeping ------------------------------------
__global__ void init_offsets_k(const void* __restrict__ counts) {
    if (threadIdx.x == 0 && blockIdx.x == 0) {
        const int* c32 = (const int*)counts;
        const long long* c64 = (const long long*)counts;
        long long s = 0;
        bool ok32 = true;
        for (int b = 0; b < NB; b++) {
            int v = c32[b];
            if (v < 0 || v > NMAX) ok32 = false;
            s += v;
        }
        if (s != TOT) ok32 = false;
        int acc = 0;
        for (int b = 0; b < NB; b++) {
            int c = ok32 ? c32[b] : (int)c64[b];
            if (c < 0) c = 0;
            if (c > NMAX) c = NMAX;
            g_off[b] = acc;
            g_cnt[b] = c;
            acc += c;
        }
    }
}

// ---------------- prep: WcP[g][f][c] + WcT[g][c][f] -------------------------
__global__ void __launch_bounds__(256) prep_w_k(const float* __restrict__ Wc) {
    int id = blockIdx.x * 256 + threadIdx.x;
    if (id >= NGR * GF * CP2) return;
    int c = id % CP2;
    int rf = id / CP2;
    int f = rf % GF, g = rf / GF;
    float v = (c < DIN) ? Wc[(long long)rf * DIN + c] : 0.f;
    g_WcP[id] = v;
    g_WcT[((long long)g * CP2 + c) * GF + f] = v;
}

// ---------------- prep: fm -> bf16 hi/lo in fmT[s][c] and fmC[c][s] ---------
__global__ void __launch_bounds__(256) split_fm_k(const float* __restrict__ fm) {
    __shared__ float tile[32][33];
    int b = blockIdx.z;
    int s0 = blockIdx.x * 32, c0 = blockIdx.y * 32;
    int tx = threadIdx.x, ty = threadIdx.y;     // (32, 8)

#pragma unroll
    for (int i = 0; i < 4; i++) {
        int c = c0 + ty + i * 8;
        int s = s0 + tx;
        float v = 0.f;
        if (c < DIN) {
            v = fm[((long long)b * DIN + c) * SS + s];
            __nv_bfloat16 h = __float2bfloat16(v);
            long long o = ((long long)b * DIN + c) * SS + s;
            g_fmCh[o] = h;
            g_fmCl[o] = __float2bfloat16(v - __bfloat162float(h));
        }
        tile[ty + i * 8][tx] = v;
    }
    __syncthreads();
#pragma unroll
    for (int i = 0; i < 4; i++) {
        int s = s0 + ty + i * 8;
        int c = c0 + tx;
        float v = tile[tx][ty + i * 8];
        __nv_bfloat16 h = __float2bfloat16(v);
        long long o = ((long long)b * SROWS + s) * CP2 + c;
        g_fmTh[o] = h;
        g_fmTl[o] = __float2bfloat16(v - __bfloat162float(h));
    }
}

// ---------------- emb split-K partial GEMM ----------------------------------
__global__ void __launch_bounds__(256) emb_part_k(
    const float* __restrict__ A, const float* __restrict__ Bm)
{
    int z = blockIdx.z;
    int kbase = z * (IDIM / KSPLIT);

    __shared__ __align__(16) float As[32][33];
    __shared__ __align__(16) float Bs[32][65];

    int tid = threadIdx.x;
    int m0 = blockIdx.x * 32;
    int n0 = blockIdx.y * 64;
    int tx = tid % 64, ty = tid / 64;

    float acc[8];
#pragma unroll
    for (int i = 0; i < 8; i++) acc[i] = 0.f;

    for (int k0 = kbase; k0 < kbase + IDIM / KSPLIT; k0 += 32) {
#pragma unroll
        for (int t = 0; t < 4; t++) {
            int lin = tid + 256 * t;
            int k = lin & 31, m = lin >> 5;
            As[k][m] = A[(m0 + m) * IDIM + k0 + k];
        }
#pragma unroll
        for (int t = 0; t < 8; t++) {
            int lin = tid + 256 * t;
            int k = lin & 31, n = lin >> 5;
            Bs[k][n] = Bm[(n0 + n) * IDIM + k0 + k];
        }
        __syncthreads();
#pragma unroll
        for (int k = 0; k < 32; k++) {
            float bv = Bs[k][tx];
#pragma unroll
            for (int i = 0; i < 8; i++)
                acc[i] += As[k][ty + 4 * i] * bv;
        }
        __syncthreads();
    }

    float* P = g_embP + (long long)z * TOT * IDIM;
#pragma unroll
    for (int i = 0; i < 8; i++) {
        int m = m0 + ty + 4 * i;
        P[m * IDIM + n0 + tx] = acc[i];
    }
}

__global__ void __launch_bounds__(256) emb_reduce_k(const float* __restrict__ ba) {
    int id = blockIdx.x * 256 + threadIdx.x;
    if (id >= TOT * IDIM) return;
    float v = ba[id & (IDIM - 1)];
#pragma unroll
    for (int z = 0; z < KSPLIT; z++)
        v += g_embP[z * (TOT * IDIM) + id];
    g_emb[id] = v;
}

// ---------------- flexible GEMM (small GEMMs): C = A @ B^T ------------------
__global__ void __launch_bounds__(256) gemm_flex_k(
    const float* __restrict__ A, int lda, long long aZ,
    const float* __restrict__ Bm, int ldb, long long bZ, int Brows,
    const float* __restrict__ cbias, long long cbZ,
    const float* __restrict__ resid, int ldres, long long resZ,
    float* __restrict__ C, int ldc, long long cZ,
    int K, int Nstore, int doRelu)
{
    int z = blockIdx.z;
    A  += (long long)z * aZ;
    Bm += (long long)z * bZ;
    C  += (long long)z * cZ;

    __shared__ __align__(16) float As[32][33];
    __shared__ __align__(16) float Bs[32][65];

    int tid = threadIdx.x;
    int m0 = blockIdx.x * 32;
    int n0 = blockIdx.y * 64;
    int tx = tid % 64, ty = tid / 64;

    float acc[8];
#pragma unroll
    for (int i = 0; i < 8; i++) acc[i] = 0.f;

    for (int k0 = 0; k0 < K; k0 += 32) {
#pragma unroll
        for (int t = 0; t < 4; t++) {
            int lin = tid + 256 * t;
            int k = lin & 31, m = lin >> 5;
            As[k][m] = A[(long long)(m0 + m) * lda + k0 + k];
        }
#pragma unroll
        for (int t = 0; t < 8; t++) {
            int lin = tid + 256 * t;
            int k = lin & 31, n = lin >> 5;
            int r = n0 + n;
            if (r >= Brows) r = Brows - 1;
            Bs[k][n] = Bm[(long long)r * ldb + k0 + k];
        }
        __syncthreads();
#pragma unroll
        for (int k = 0; k < 32; k++) {
            float bv = Bs[k][tx];
#pragma unroll
            for (int i = 0; i < 8; i++)
                acc[i] += As[k][ty + 4 * i] * bv;
        }
        __syncthreads();
    }

    int n = n0 + tx;
    bool nok = (n < Nstore);
    float cb = (cbias && nok) ? cbias[z * cbZ + n] : 0.f;
#pragma unroll
    for (int i = 0; i < 8; i++) {
        int m = m0 + ty + 4 * i;
        float outv = 0.f;
        if (nok) {
            float v = acc[i] + cb;
            if (resid) v += resid[z * resZ + (long long)m * ldres + n];
            if (doRelu) v = fmaxf(v, 0.f);
            outv = v;
        }
        C[(long long)m * ldc + n] = outv;
    }
}

// ---------------- scatter E2 -> bf16 hi/lo padded rows, dP -------------------
__global__ void __launch_bounds__(256) scatter_e2_k(const float* __restrict__ bc) {
    int row = blockIdx.x;        // g*16 + n
    int b = blockIdx.y;
    int g = row >> 4, n = row & 15;
    int tid = threadIdx.x;
    bool valid = (n < g_cnt[b]);
    int t = g_off[b] + n;

    long long doff = ((long long)b * 64 + row) * CP2;
    const float* src = g_E2flat + ((long long)t * NGR + g) * CP2;
    for (int c = tid; c < CP2; c += 256) {
        float v = valid ? src[c] : 0.f;
        __nv_bfloat16 h = __float2bfloat16(v);
        g_e2h[doff + c] = h;
        g_e2l[doff + c] = __float2bfloat16(v - __bfloat162float(h));
    }

    __shared__ float red[8];
    float v = valid ? g_emb[t * IDIM + g * GF + tid] * bc[g * GF + tid] : 0.f;
#pragma unroll
    for (int o = 16; o > 0; o >>= 1) v += __shfl_xor_sync(0xffffffffu, v, o);
    if ((tid & 31) == 0) red[tid >> 5] = v;
    __syncthreads();
    if (tid == 0) {
        float s = 0.f;
#pragma unroll
        for (int w = 0; w < 8; w++) s += red[w];
        g_dP[b * 64 + row] = s;
    }
}

// ---------------- adj MMA (bf16 3-term, split-K x2) --------------------------
// adjP[zk][b][64][s] = E2[b] @ fmT[b]^T over k-half; M=64, N=128, chunks of k32
__global__ void __launch_bounds__(256, 2) adj_mma_k() {
    extern __shared__ __align__(16) char sm[];
    int tid = threadIdx.x, lane = tid & 31, wid = tid >> 5;
    int stile = blockIdx.x, b = blockIdx.y, zk = blockIdx.z;
    uint32_t sb = smem_u32(sm);

    const char* Ah = (const char*)(g_e2h + (long long)b * 64 * CP2);
    const char* Al = (const char*)(g_e2l + (long long)b * 64 * CP2);
    const char* Bh = (const char*)(g_fmTh + ((long long)b * SROWS + stile * 128) * CP2);
    const char* Bl = (const char*)(g_fmTl + ((long long)b * SROWS + stile * 128) * CP2);

    int rA = tid >> 2, cA = tid & 3;
    uint32_t dA = rA * RS2 + cA * 16;
    long long sA = (long long)rA * (CP2 * 2) + cA * 16;
    int rB0 = tid >> 2, cB0 = tid & 3;
    int id1 = tid + 256;
    int rB1 = id1 >> 2, cB1 = id1 & 3;
    uint32_t dB0 = rB0 * RS2 + cB0 * 16, dB1 = rB1 * RS2 + cB1 * 16;
    long long sB0 = (long long)rB0 * (CP2 * 2) + cB0 * 16;
    long long sB1 = (long long)rB1 * (CP2 * 2) + cB1 * 16;

    int warpM = wid & 1, warpN = wid >> 1;
    uint32_t aOff[2], bOff[2];
#pragma unroll
    for (int i = 0; i < 2; i++)
        aOff[i] = (warpM * 32 + i * 16 + (lane & 15)) * RS2 + (lane >> 4) * 16;
#pragma unroll
    for (int jj = 0; jj < 2; jj++)
        bOff[jj] = (warpN * 32 + jj * 16 + (lane & 15)) * RS2 + (lane >> 4) * 16;

    float acc[2][4][4];
#pragma unroll
    for (int i = 0; i < 2; i++)
#pragma unroll
        for (int j = 0; j < 4; j++)
#pragma unroll
            for (int q = 0; q < 4; q++) acc[i][j][q] = 0.f;

    const int NCH = CP2 / 32 / ASPLIT;   // 14
    int kbeg = zk * NCH;
    {
        long long ko = (long long)kbeg * 64;
        cp16(sb + AH2 + dA, Ah + sA + ko);
        cp16(sb + AL2 + dA, Al + sA + ko);
        cp16(sb + BH2 + dB0, Bh + sB0 + ko);
        cp16(sb + BH2 + dB1, Bh + sB1 + ko);
        cp16(sb + BL2 + dB0, Bl + sB0 + ko);
        cp16(sb + BL2 + dB1, Bl + sB1 + ko);
        cp_commit();
    }

    for (int kc = 0; kc < NCH; kc++) {
        uint32_t bo = (kc & 1) ? STG2 : 0;
        if (kc + 1 < NCH) {
            long long ko = (long long)(kbeg + kc + 1) * 64;
            uint32_t nbo = ((kc + 1) & 1) ? STG2 : 0;
            cp16(sb + nbo + AH2 + dA, Ah + sA + ko);
            cp16(sb + nbo + AL2 + dA, Al + sA + ko);
            cp16(sb + nbo + BH2 + dB0, Bh + sB0 + ko);
            cp16(sb + nbo + BH2 + dB1, Bh + sB1 + ko);
            cp16(sb + nbo + BL2 + dB0, Bl + sB0 + ko);
            cp16(sb + nbo + BL2 + dB1, Bl + sB1 + ko);
            cp_commit();
            cp_wait<1>();
        } else {
            cp_wait<0>();
        }
        __syncthreads();

#pragma unroll
        for (int ks = 0; ks < 2; ks++) {
            uint32_t kb = ks * 32;
            uint32_t ah[2][4], al[2][4];
#pragma unroll
            for (int i = 0; i < 2; i++) {
                ldsm4(ah[i][0], ah[i][1], ah[i][2], ah[i][3],
                      sb + bo + AH2 + aOff[i] + kb);
                ldsm4(al[i][0], al[i][1], al[i][2], al[i][3],
                      sb + bo + AL2 + aOff[i] + kb);
            }
#pragma unroll
            for (int jj = 0; jj < 2; jj++) {
                uint32_t h0, h1, h2, h3, l0, l1, l2, l3;
                ldsm4(h0, h1, h2, h3, sb + bo + BH2 + bOff[jj] + kb);
                ldsm4(l0, l1, l2, l3, sb + bo + BL2 + bOff[jj] + kb);
                int j0 = 2 * jj, j1 = 2 * jj + 1;
                mma_bf16(acc[0][j0], ah[0], h0, h2);
                mma_bf16(acc[0][j1], ah[0], h1, h3);
                mma_bf16(acc[1][j0], ah[1], h0, h2);
                mma_bf16(acc[1][j1], ah[1], h1, h3);
                mma_bf16(acc[0][j0], ah[0], l0, l2);
                mma_bf16(acc[0][j1], ah[0], l1, l3);
                mma_bf16(acc[1][j0], ah[1], l0, l2);
                mma_bf16(acc[1][j1], ah[1], l1, l3);
                mma_bf16(acc[0][j0], al[0], h0, h2);
                mma_bf16(acc[0][j1], al[0], h1, h3);
                mma_bf16(acc[1][j0], al[1], h0, h2);
                mma_bf16(acc[1][j1], al[1], h1, h3);
            }
        }
        __syncthreads();
    }

    float* C = g_adjP[zk] + (long long)b * 64 * ADJ_LD;
#pragma unroll
    for (int i = 0; i < 2; i++) {
        int m = warpM * 32 + i * 16 + (lane >> 2);
        float rb0 = (zk == 0) ? g_dP[b * 64 + m] : 0.f;
        float rb1 = (zk == 0) ? g_dP[b * 64 + m + 8] : 0.f;
#pragma unroll
        for (int j = 0; j < 4; j++) {
            int n = stile * 128 + warpN * 32 + j * 8 + 2 * (lane & 3);
            C[(long long)m * ADJ_LD + n]           = acc[i][j][0] + rb0;
            C[(long long)m * ADJ_LD + n + 1]       = acc[i][j][1] + rb0;
            C[(long long)(m + 8) * ADJ_LD + n]     = acc[i][j][2] + rb1;
            C[(long long)(m + 8) * ADJ_LD + n + 1] = acc[i][j][3] + rb1;
        }
    }
}

// ---------------- softmax: sum partials, softmax, emit bf16 hi/lo ------------
__global__ void __launch_bounds__(256) softmax_k() {
    int n = blockIdx.x, g = blockIdx.y, b = blockIdx.z;
    if (n >= g_cnt[b]) return;
    long long roff = (long long)(b * 64 + g * 16 + n) * ADJ_LD;
    float* p0 = g_adjP[0] + roff;
    const float* p1 = g_adjP[1] + roff;
    int tid = threadIdx.x;
    __shared__ float red[8];

    float mx = -1e30f;
    for (int s = tid; s < SS; s += 256) mx = fmaxf(mx, p0[s] + p1[s]);
#pragma unroll
    for (int o = 16; o > 0; o >>= 1) mx = fmaxf(mx, __shfl_xor_sync(0xffffffffu, mx, o));
    if ((tid & 31) == 0) red[tid >> 5] = mx;
    __syncthreads();
    if (tid < 32) {
        float v = (tid < 8) ? red[tid] : -1e30f;
#pragma unroll
        for (int o = 4; o > 0; o >>= 1) v = fmaxf(v, __shfl_xor_sync(0xffffffffu, v, o));
        if (tid == 0) red[0] = v;
    }
    __syncthreads();
    mx = red[0];
    __syncthreads();

    float sum = 0.f;
    for (int s = tid; s < SS; s += 256) {
        float e = __expf(p0[s] + p1[s] - mx);
        p0[s] = e;                        // reuse partial-0 as temp
        sum += e;
    }
#pragma unroll
    for (int o = 16; o > 0; o >>= 1) sum += __shfl_xor_sync(0xffffffffu, sum, o);
    if ((tid & 31) == 0) red[tid >> 5] = sum;
    __syncthreads();
    if (tid < 32) {
        float v = (tid < 8) ? red[tid] : 0.f;
#pragma unroll
        for (int o = 4; o > 0; o >>= 1) v += __shfl_xor_sync(0xffffffffu, v, o);
        if (tid == 0) red[0] = v;
    }
    __syncthreads();
    float inv = 1.f / red[0];
    for (int s = tid; s < SS; s += 256) {
        float v = p0[s] * inv;
        __nv_bfloat16 h = __float2bfloat16(v);
        g_adjh[roff + s] = h;
        g_adjl[roff + s] = __float2bfloat16(v - __bfloat162float(h));
    }
}

// ---------------- R MMA (bf16 3-term, split-K x4 over s) ---------------------
// Rp[zk][b][64][c] = adj_sm @ fmC^T; M=64, N=128 c-tile, k=s chunks 13/12/12/12
__global__ void __launch_bounds__(256, 2) r_mma_k() {
    extern __shared__ __align__(16) char sm[];
    int tid = threadIdx.x, lane = tid & 31, wid = tid >> 5;
    int b = blockIdx.y, zk = blockIdx.z;
    int n0 = blockIdx.x * 128;
    uint32_t sb = smem_u32(sm);

    const char* Ah = (const char*)(g_adjh + (long long)b * 64 * ADJ_LD);
    const char* Al = (const char*)(g_adjl + (long long)b * 64 * ADJ_LD);
    const char* Bh = (const char*)(g_fmCh + (long long)b * DIN * SS);
    const char* Bl = (const char*)(g_fmCl + (long long)b * DIN * SS);

    int rA = tid >> 2, cA = tid & 3;
    uint32_t dA = rA * RS2 + cA * 16;
    long long sA = (long long)rA * (ADJ_LD * 2) + cA * 16;
    int rB0 = tid >> 2, cB0 = tid & 3;
    int id1 = tid + 256;
    int rB1 = id1 >> 2, cB1 = id1 & 3;
    int cr0 = n0 + rB0; if (cr0 >= DIN) cr0 = DIN - 1;
    int cr1 = n0 + rB1; if (cr1 >= DIN) cr1 = DIN - 1;
    uint32_t dB0 = rB0 * RS2 + cB0 * 16, dB1 = rB1 * RS2 + cB1 * 16;
    long long sB0 = (long long)cr0 * (SS * 2) + cB0 * 16;
    long long sB1 = (long long)cr1 * (SS * 2) + cB1 * 16;

    int warpM = wid & 1, warpN = wid >> 1;
    uint32_t aOff[2], bOff[2];
#pragma unroll
    for (int i = 0; i < 2; i++)
        aOff[i] = (warpM * 32 + i * 16 + (lane & 15)) * RS2 + (lane >> 4) * 16;
#pragma unroll
    for (int jj = 0; jj < 2; jj++)
        bOff[jj] = (warpN * 32 + jj * 16 + (lane & 15)) * RS2 + (lane >> 4) * 16;

    float acc[2][4][4];
#pragma unroll
    for (int i = 0; i < 2; i++)
#pragma unroll
        for (int j = 0; j < 4; j++)
#pragma unroll
            for (int q = 0; q < 4; q++) acc[i][j][q] = 0.f;

    int kbeg = (zk == 0) ? 0 : (zk * 12 + 1);   // 13/12/12/12 chunks of k32
    int kcnt = (zk == 0) ? 13 : 12;
    {
        long long ko = (long long)kbeg * 64;
        cp16(sb + AH2 + dA, Ah + sA + ko);
        cp16(sb + AL2 + dA, Al + sA + ko);
        cp16(sb + BH2 + dB0, Bh + sB0 + ko);
        cp16(sb + BH2 + dB1, Bh + sB1 + ko);
        cp16(sb + BL2 + dB0, Bl + sB0 + ko);
        cp16(sb + BL2 + dB1, Bl + sB1 + ko);
        cp_commit();
    }

    for (int kc = 0; kc < kcnt; kc++) {
        uint32_t bo = (kc & 1) ? STG2 : 0;
        if (kc + 1 < kcnt) {
            long long ko = (long long)(kbeg + kc + 1) * 64;
            uint32_t nbo = ((kc + 1) & 1) ? STG2 : 0;
            cp16(sb + nbo + AH2 + dA, Ah + sA + ko);
            cp16(sb + nbo + AL2 + dA, Al + sA + ko);
            cp16(sb + nbo + BH2 + dB0, Bh + sB0 + ko);
            cp16(sb + nbo + BH2 + dB1, Bh + sB1 + ko);
            cp16(sb + nbo + BL2 + dB0, Bl + sB0 + ko);
            cp16(sb + nbo + BL2 + dB1, Bl + sB1 + ko);
            cp_commit();
            cp_wait<1>();
        } else {
            cp_wait<0>();
        }
        __syncthreads();

#pragma unroll
        for (int ks = 0; ks < 2; ks++) {
            uint32_t kb = ks * 32;
            uint32_t ah[2][4], al[2][4];
#pragma unroll
            for (int i = 0; i < 2; i++) {
                ldsm4(ah[i][0], ah[i][1], ah[i][2], ah[i][3],
                      sb + bo + AH2 + aOff[i] + kb);
                ldsm4(al[i][0], al[i][1], al[i][2], al[i][3],
                      sb + bo + AL2 + aOff[i] + kb);
            }
#pragma unroll
            for (int jj = 0; jj < 2; jj++) {
                uint32_t h0, h1, h2, h3, l0, l1, l2, l3;
                ldsm4(h0, h1, h2, h3, sb + bo + BH2 + bOff[jj] + kb);
                ldsm4(l0, l1, l2, l3, sb + bo + BL2 + bOff[jj] + kb);
                int j0 = 2 * jj, j1 = 2 * jj + 1;
                mma_bf16(acc[0][j0], ah[0], h0, h2);
                mma_bf16(acc[0][j1], ah[0], h1, h3);
                mma_bf16(acc[1][j0], ah[1], h0, h2);
                mma_bf16(acc[1][j1], ah[1], h1, h3);
                mma_bf16(acc[0][j0], ah[0], l0, l2);
                mma_bf16(acc[0][j1], ah[0], l1, l3);
                mma_bf16(acc[1][j0], ah[1], l0, l2);
                mma_bf16(acc[1][j1], ah[1], l1, l3);
                mma_bf16(acc[0][j0], al[0], h0, h2);
                mma_bf16(acc[0][j1], al[0], h1, h3);
                mma_bf16(acc[1][j0], al[1], h0, h2);
                mma_bf16(acc[1][j1], al[1], h1, h3);
            }
        }
        __syncthreads();
    }

    float* C = g_Rp[zk] + (long long)b * 64 * CP2;
#pragma unroll
    for (int i = 0; i < 2; i++) {
        int m = warpM * 32 + i * 16 + (lane >> 2);
#pragma unroll
        for (int j = 0; j < 4; j++) {
            int n = n0 + warpN * 32 + j * 8 + 2 * (lane & 3);
            bool ok0 = (n < DIN), ok1 = (n + 1 < DIN);
            C[(long long)m * CP2 + n]           = ok0 ? acc[i][j][0] : 0.f;
            C[(long long)m * CP2 + n + 1]       = ok1 ? acc[i][j][1] : 0.f;
            C[(long long)(m + 8) * CP2 + n]     = ok0 ? acc[i][j][2] : 0.f;
            C[(long long)(m + 8) * CP2 + n + 1] = ok1 ? acc[i][j][3] : 0.f;
        }
    }
}

// ---------------- gather sum(Rp) -> Rf (ragged flat) -------------------------
__global__ void __launch_bounds__(256) gather_rf_k() {
    int row = blockIdx.x;
    int b = blockIdx.y;
    int g = row >> 4, n = row & 15;
    if (n >= g_cnt[b]) return;
    int t = g_off[b] + n;
    int tid = threadIdx.x;
    long long roff = ((long long)b * 64 + row) * CP2;
    float* dst = g_Rf + ((long long)t * NGR + g) * CP2;
    for (int c = tid; c < CP2; c += 256) {
        float v = 0.f;
#pragma unroll
        for (int z = 0; z < RSPLIT; z++)
            v += g_Rp[z][roff + c];
        dst[c] = v;
    }
}

// ---------------- launch ----------------------------------------------------
extern "C" void kernel_launch(void* const* d_in, const int* in_sizes, int n_in,
                              void* d_out, int out_size) {
    const float* actor = (const float*)d_in[0];
    const float* fmap  = (const float*)d_in[1];
    const float* W_a   = (const float*)d_in[2];
    const float* b_a   = (const float*)d_in[3];
    const float* W_c   = (const float*)d_in[4];
    const float* b_c   = (const float*)d_in[5];
    const float* W_h   = (const float*)d_in[6];
    const void*  counts = d_in[7];
    int nbias = 0;
    for (int i = 0; i < n_in; i++) {
        switch (in_sizes[i]) {
            case TOT * IDIM:      actor = (const float*)d_in[i]; break;
            case NB * DIN * SS:   fmap  = (const float*)d_in[i]; break;
            case NGR * GF * IDIM: W_a   = (const float*)d_in[i]; break;
            case NGR * GF * DIN:  W_c   = (const float*)d_in[i]; break;
            case NGR * GF * GF:   W_h   = (const float*)d_in[i]; break;
            case NGR * GF:
                if (nbias++ == 0) b_a = (const float*)d_in[i];
                else              b_c = (const float*)d_in[i];
                break;
            case NB:              counts = d_in[i]; break;
            default: break;
        }
    }
    float* out = (float*)d_out;

    float *emb_p, *wcT_p, *wcP_p, *e2f_p, *Rf_p, *flat_p;
    cudaGetSymbolAddress((void**)&emb_p, g_emb);
    cudaGetSymbolAddress((void**)&wcT_p, g_WcT);
    cudaGetSymbolAddress((void**)&wcP_p, g_WcP);
    cudaGetSymbolAddress((void**)&e2f_p, g_E2flat);
    cudaGetSymbolAddress((void**)&Rf_p, g_Rf);
    cudaGetSymbolAddress((void**)&flat_p, g_flat);

    cudaFuncSetAttribute(adj_mma_k, cudaFuncAttributeMaxDynamicSharedMemorySize, SMEM2);
    cudaFuncSetAttribute(r_mma_k, cudaFuncAttributeMaxDynamicSharedMemorySize, SMEM2);

    // 0: ragged bookkeeping
    init_offsets_k<<<1, 32>>>(counts);
    // 1: W prep
    prep_w_k<<<(NGR * GF * CP2 + 255) / 256, 256>>>(W_c);
    // 2: fm -> bf16 hi/lo (both layouts)
    split_fm_k<<<dim3(SS / 32, CP2 / 32, NB), dim3(32, 8)>>>(fmap);
    // 3-4: emb = actor @ W_a^T + b_a (split-K x8)
    emb_part_k<<<dim3(5, 16, KSPLIT), 256>>>(actor, W_a);
    emb_reduce_k<<<(TOT * IDIM + 255) / 256, 256>>>(b_a);
    // 5: E2flat[t][g][c] = emb[t,g,:] @ WcT[g]^T
    gemm_flex_k<<<dim3(5, CP2 / 64, NGR), 256>>>(
        emb_p, IDIM, GF,
        wcT_p, GF, (long long)CP2 * GF, CP2,
        nullptr, 0, nullptr, 0, 0,
        e2f_p, NGR * CP2, CP2,
        GF, CP2, 0);
    // 6: scatter E2 -> bf16 padded rows + dP
    scatter_e2_k<<<dim3(64, NB), 256>>>(b_c);
    // 7: adj partials via bf16 MMA (split-K x2)
    adj_mma_k<<<dim3(SROWS / 128, NB, ASPLIT), 256, SMEM2>>>();
    // 8: softmax (sums partials) -> adj bf16 hi/lo
    softmax_k<<<dim3(NMAX, NGR, NB), 256>>>();
    // 9: R partials via bf16 MMA (split-K x4)
    r_mma_k<<<dim3(CP2 / 128, NB, RSPLIT), 256, SMEM2>>>();
    // 10: gather sum(Rp) -> ragged flat
    gather_rf_k<<<dim3(64, NB), 256>>>();
    // 11: flat = Rf @ WcP^T + b_c + emb
    gemm_flex_k<<<dim3(5, NGR, NGR), 256>>>(
        Rf_p, NGR * CP2, CP2,
        wcP_p, CP2, (long long)GF * CP2, GF,
        b_c, GF,
        emb_p, IDIM, GF,
        flat_p, IDIM, GF,
        CP2, GF, 0);
    // 12: head: out = relu(flat @ W_h^T)
    gemm_flex_k<<<dim3(5, NGR, NGR), 256>>>(
        flat_p, IDIM, GF,
        W_h, GF, (long long)GF * GF, GF,
        nullptr, 0, nullptr, 0, 0,
        out, IDIM, GF,
        GF, GF, 1);
}

// round 15
// speedup vs baseline: 3.2604x; 1.2017x over previous
#include <cuda_runtime.h>
#include <cuda_fp16.h>
#include <cstdint>

// Problem constants
#define NGR 4
#define GF 256
#define DIN 834
#define SS 1568
#define NB 16
#define TOT 160
#define IDIM 1024
#define NMAX 16

#define CP2 896             // c padded (28 x 32)
#define ADJ_LD 1664         // s padded (52 x 32)
#define SROWS 1664          // fmT s rows (13 x 128)
#define KSPLIT 8
#define RSPLIT 4
#define ASPLIT 2

// mma smem: RS2=80B row stride, chunk k=32 fp16 (64B) per stage slot
#define RS2 80
#define A_TB (64 * RS2)             // 5120
#define B_TB (128 * RS2)            // 10240
#define AH2 0
#define AL2 (A_TB)
#define BH2 (2 * A_TB)
#define STG2 (2 * A_TB + B_TB)      // 20480
#define SMEM2 (2 * STG2)            // 40960

// ---------------- scratch (static device globals) --------------------------
__device__ float g_emb[TOT * IDIM];
__device__ float g_embP[KSPLIT * TOT * IDIM];
__device__ float g_WcT[NGR * CP2 * GF];              // [g][c][f]
__device__ float g_WcP[NGR * GF * CP2];              // [g][f][c], zero pad
__device__ float g_E2flat[TOT * NGR * CP2];          // [t][g][c]
__device__ __half g_e2h[NB * 64 * CP2];              // A of adj (hi), pad zero
__device__ __half g_e2l[NB * 64 * CP2];
__device__ float g_dP[NB * 64];
__device__ __half g_fmTh[(long long)NB * SROWS * CP2];  // [b][s][c] (B of adj)
__device__ __half g_fmCh[(long long)NB * DIN * SS];     // [b][c][s] (B of r)
__device__ float g_adjP[ASPLIT][NB * 64 * ADJ_LD];   // adj logit partials
__device__ __half g_adjh[NB * 64 * ADJ_LD];          // softmaxed, zero-static
__device__ __half g_adjl[NB * 64 * ADJ_LD];
__device__ float g_Rp[RSPLIT][NB * 64 * CP2];
__device__ float g_Rf[TOT * NGR * CP2];
__device__ float g_flat[TOT * IDIM];
__device__ int   g_off[NB];
__device__ int   g_cnt[NB];

// ---------------- PTX helpers ------------------------------------------------
__device__ __forceinline__ uint32_t smem_u32(const void* p) {
    uint32_t a;
    asm("{ .reg .u64 t; cvta.to.shared.u64 t, %1; cvt.u32.u64 %0, t; }"
        : "=r"(a) : "l"(p));
    return a;
}
__device__ __forceinline__ void cp16(uint32_t dst, const void* src) {
    asm volatile("cp.async.cg.shared.global [%0], [%1], 16;"
                 :: "r"(dst), "l"(src) : "memory");
}
__device__ __forceinline__ void cp_commit() {
    asm volatile("cp.async.commit_group;" ::: "memory");
}
template <int N>
__device__ __forceinline__ void cp_wait() {
    asm volatile("cp.async.wait_group %0;" :: "n"(N) : "memory");
}
__device__ __forceinline__ void ldsm4(uint32_t& r0, uint32_t& r1, uint32_t& r2,
                                      uint32_t& r3, uint32_t a) {
    asm volatile("ldmatrix.sync.aligned.m8n8.x4.shared.b16 {%0,%1,%2,%3}, [%4];"
                 : "=r"(r0), "=r"(r1), "=r"(r2), "=r"(r3) : "r"(a));
}
__device__ __forceinline__ void mma_f16(float* c, const uint32_t* a,
                                        uint32_t b0, uint32_t b1) {
    asm volatile(
        "mma.sync.aligned.m16n8k16.row.col.f32.f16.f16.f32 "
        "{%0,%1,%2,%3}, {%4,%5,%6,%7}, {%8,%9}, {%0,%1,%2,%3};"
        : "+f"(c[0]), "+f"(c[1]), "+f"(c[2]), "+f"(c[3])
        : "r"(a[0]), "r"(a[1]), "r"(a[2]), "r"(a[3]), "r"(b0), "r"(b1));
}

// ---------------- K0: ragged bookkeeping ------------------------------------
__global__ void init_offsets_k(const void* __restrict__ counts) {
    if (threadIdx.x == 0 && blockIdx.x == 0) {
        const int* c32 = (const int*)counts;
        const long long* c64 = (const long long*)counts;
        long long s = 0;
        bool ok32 = true;
        for (int b = 0; b < NB; b++) {
            int v = c32[b];
            if (v < 0 || v > NMAX) ok32 = false;
            s += v;
        }
        if (s != TOT) ok32 = false;
        int acc = 0;
        for (int b = 0; b < NB; b++) {
            int c = ok32 ? c32[b] : (int)c64[b];
            if (c < 0) c = 0;
            if (c > NMAX) c = NMAX;
            g_off[b] = acc;
            g_cnt[b] = c;
            acc += c;
        }
    }
}

// ---------------- prep: WcP[g][f][c] + WcT[g][c][f] -------------------------
__global__ void __launch_bounds__(256) prep_w_k(const float* __restrict__ Wc) {
    int id = blockIdx.x * 256 + threadIdx.x;
    if (id >= NGR * GF * CP2) return;
    int c = id % CP2;
    int rf = id / CP2;
    int f = rf % GF, g = rf / GF;
    float v = (c < DIN) ? Wc[(long long)rf * DIN + c] : 0.f;
    g_WcP[id] = v;
    g_WcT[((long long)g * CP2 + c) * GF + f] = v;
}

// ---------------- prep: fm -> fp16 hi in fmT[s][c] and fmC[c][s] ------------
__global__ void __launch_bounds__(256) split_fm_k(const float* __restrict__ fm) {
    __shared__ float tile[32][33];
    int b = blockIdx.z;
    int s0 = blockIdx.x * 32, c0 = blockIdx.y * 32;
    int tx = threadIdx.x, ty = threadIdx.y;     // (32, 8)

#pragma unroll
    for (int i = 0; i < 4; i++) {
        int c = c0 + ty + i * 8;
        int s = s0 + tx;
        float v = 0.f;
        if (c < DIN) {
            v = fm[((long long)b * DIN + c) * SS + s];
            g_fmCh[((long long)b * DIN + c) * SS + s] = __float2half(v);
        }
        tile[ty + i * 8][tx] = v;
    }
    __syncthreads();
#pragma unroll
    for (int i = 0; i < 4; i++) {
        int s = s0 + ty + i * 8;
        int c = c0 + tx;
        g_fmTh[((long long)b * SROWS + s) * CP2 + c] =
            __float2half(tile[tx][ty + i * 8]);
    }
}

// ---------------- emb split-K partial GEMM ----------------------------------
__global__ void __launch_bounds__(256) emb_part_k(
    const float* __restrict__ A, const float* __restrict__ Bm)
{
    int z = blockIdx.z;
    int kbase = z * (IDIM / KSPLIT);

    __shared__ __align__(16) float As[32][33];
    __shared__ __align__(16) float Bs[32][65];

    int tid = threadIdx.x;
    int m0 = blockIdx.x * 32;
    int n0 = blockIdx.y * 64;
    int tx = tid % 64, ty = tid / 64;

    float acc[8];
#pragma unroll
    for (int i = 0; i < 8; i++) acc[i] = 0.f;

    for (int k0 = kbase; k0 < kbase + IDIM / KSPLIT; k0 += 32) {
#pragma unroll
        for (int t = 0; t < 4; t++) {
            int lin = tid + 256 * t;
            int k = lin & 31, m = lin >> 5;
            As[k][m] = A[(m0 + m) * IDIM + k0 + k];
        }
#pragma unroll
        for (int t = 0; t < 8; t++) {
            int lin = tid + 256 * t;
            int k = lin & 31, n = lin >> 5;
            Bs[k][n] = Bm[(n0 + n) * IDIM + k0 + k];
        }
        __syncthreads();
#pragma unroll
        for (int k = 0; k < 32; k++) {
            float bv = Bs[k][tx];
#pragma unroll
            for (int i = 0; i < 8; i++)
                acc[i] += As[k][ty + 4 * i] * bv;
        }
        __syncthreads();
    }

    float* P = g_embP + (long long)z * TOT * IDIM;
#pragma unroll
    for (int i = 0; i < 8; i++) {
        int m = m0 + ty + 4 * i;
        P[m * IDIM + n0 + tx] = acc[i];
    }
}

__global__ void __launch_bounds__(256) emb_reduce_k(const float* __restrict__ ba) {
    int id = blockIdx.x * 256 + threadIdx.x;
    if (id >= TOT * IDIM) return;
    float v = ba[id & (IDIM - 1)];
#pragma unroll
    for (int z = 0; z < KSPLIT; z++)
        v += g_embP[z * (TOT * IDIM) + id];
    g_emb[id] = v;
}

// ---------------- flexible GEMM (small GEMMs): C = A @ B^T ------------------
__global__ void __launch_bounds__(256) gemm_flex_k(
    const float* __restrict__ A, int lda, long long aZ,
    const float* __restrict__ Bm, int ldb, long long bZ, int Brows,
    const float* __restrict__ cbias, long long cbZ,
    const float* __restrict__ resid, int ldres, long long resZ,
    float* __restrict__ C, int ldc, long long cZ,
    int K, int Nstore, int doRelu)
{
    int z = blockIdx.z;
    A  += (long long)z * aZ;
    Bm += (long long)z * bZ;
    C  += (long long)z * cZ;

    __shared__ __align__(16) float As[32][33];
    __shared__ __align__(16) float Bs[32][65];

    int tid = threadIdx.x;
    int m0 = blockIdx.x * 32;
    int n0 = blockIdx.y * 64;
    int tx = tid % 64, ty = tid / 64;

    float acc[8];
#pragma unroll
    for (int i = 0; i < 8; i++) acc[i] = 0.f;

    for (int k0 = 0; k0 < K; k0 += 32) {
#pragma unroll
        for (int t = 0; t < 4; t++) {
            int lin = tid + 256 * t;
            int k = lin & 31, m = lin >> 5;
            As[k][m] = A[(long long)(m0 + m) * lda + k0 + k];
        }
#pragma unroll
        for (int t = 0; t < 8; t++) {
            int lin = tid + 256 * t;
            int k = lin & 31, n = lin >> 5;
            int r = n0 + n;
            if (r >= Brows) r = Brows - 1;
            Bs[k][n] = Bm[(long long)r * ldb + k0 + k];
        }
        __syncthreads();
#pragma unroll
        for (int k = 0; k < 32; k++) {
            float bv = Bs[k][tx];
#pragma unroll
            for (int i = 0; i < 8; i++)
                acc[i] += As[k][ty + 4 * i] * bv;
        }
        __syncthreads();
    }

    int n = n0 + tx;
    bool nok = (n < Nstore);
    float cb = (cbias && nok) ? cbias[z * cbZ + n] : 0.f;
#pragma unroll
    for (int i = 0; i < 8; i++) {
        int m = m0 + ty + 4 * i;
        float outv = 0.f;
        if (nok) {
            float v = acc[i] + cb;
            if (resid) v += resid[z * resZ + (long long)m * ldres + n];
            if (doRelu) v = fmaxf(v, 0.f);
            outv = v;
        }
        C[(long long)m * ldc + n] = outv;
    }
}

// ---------------- scatter E2 -> fp16 hi/lo padded rows, dP -------------------
__global__ void __launch_bounds__(256) scatter_e2_k(const float* __restrict__ bc) {
    int row = blockIdx.x;        // g*16 + n
    int b = blockIdx.y;
    int g = row >> 4, n = row & 15;
    int tid = threadIdx.x;
    bool valid = (n < g_cnt[b]);
    int t = g_off[b] + n;

    long long doff = ((long long)b * 64 + row) * CP2;
    const float* src = g_E2flat + ((long long)t * NGR + g) * CP2;
    for (int c = tid; c < CP2; c += 256) {
        float v = valid ? src[c] : 0.f;
        __half h = __float2half(v);
        g_e2h[doff + c] = h;
        g_e2l[doff + c] = __float2half(v - __half2float(h));
    }

    __shared__ float red[8];
    float v = valid ? g_emb[t * IDIM + g * GF + tid] * bc[g * GF + tid] : 0.f;
#pragma unroll
    for (int o = 16; o > 0; o >>= 1) v += __shfl_xor_sync(0xffffffffu, v, o);
    if ((tid & 31) == 0) red[tid >> 5] = v;
    __syncthreads();
    if (tid == 0) {
        float s = 0.f;
#pragma unroll
        for (int w = 0; w < 8; w++) s += red[w];
        g_dP[b * 64 + row] = s;
    }
}

// ---------------- adj MMA (fp16 2-term, split-K x2) --------------------------
__global__ void __launch_bounds__(256, 3) adj_mma_k() {
    extern __shared__ __align__(16) char sm[];
    int tid = threadIdx.x, lane = tid & 31, wid = tid >> 5;
    int stile = blockIdx.x, b = blockIdx.y, zk = blockIdx.z;
    uint32_t sb = smem_u32(sm);

    const char* Ah = (const char*)(g_e2h + (long long)b * 64 * CP2);
    const char* Al = (const char*)(g_e2l + (long long)b * 64 * CP2);
    const char* Bh = (const char*)(g_fmTh + ((long long)b * SROWS + stile * 128) * CP2);

    int rA = tid >> 2, cA = tid & 3;
    uint32_t dA = rA * RS2 + cA * 16;
    long long sA = (long long)rA * (CP2 * 2) + cA * 16;
    int rB0 = tid >> 2, cB0 = tid & 3;
    int id1 = tid + 256;
    int rB1 = id1 >> 2, cB1 = id1 & 3;
    uint32_t dB0 = rB0 * RS2 + cB0 * 16, dB1 = rB1 * RS2 + cB1 * 16;
    long long sB0 = (long long)rB0 * (CP2 * 2) + cB0 * 16;
    long long sB1 = (long long)rB1 * (CP2 * 2) + cB1 * 16;

    int warpM = wid & 1, warpN = wid >> 1;
    uint32_t aOff[2], bOff[2];
#pragma unroll
    for (int i = 0; i < 2; i++)
        aOff[i] = (warpM * 32 + i * 16 + (lane & 15)) * RS2 + (lane >> 4) * 16;
#pragma unroll
    for (int jj = 0; jj < 2; jj++)
        bOff[jj] = (warpN * 32 + jj * 16 + (lane & 15)) * RS2 + (lane >> 4) * 16;

    float acc[2][4][4];
#pragma unroll
    for (int i = 0; i < 2; i++)
#pragma unroll
        for (int j = 0; j < 4; j++)
#pragma unroll
            for (int q = 0; q < 4; q++) acc[i][j][q] = 0.f;

    const int NCH = CP2 / 32 / ASPLIT;   // 14
    int kbeg = zk * NCH;
    {
        long long ko = (long long)kbeg * 64;
        cp16(sb + AH2 + dA, Ah + sA + ko);
        cp16(sb + AL2 + dA, Al + sA + ko);
        cp16(sb + BH2 + dB0, Bh + sB0 + ko);
        cp16(sb + BH2 + dB1, Bh + sB1 + ko);
        cp_commit();
    }

    for (int kc = 0; kc < NCH; kc++) {
        uint32_t bo = (kc & 1) ? STG2 : 0;
        if (kc + 1 < NCH) {
            long long ko = (long long)(kbeg + kc + 1) * 64;
            uint32_t nbo = ((kc + 1) & 1) ? STG2 : 0;
            cp16(sb + nbo + AH2 + dA, Ah + sA + ko);
            cp16(sb + nbo + AL2 + dA, Al + sA + ko);
            cp16(sb + nbo + BH2 + dB0, Bh + sB0 + ko);
            cp16(sb + nbo + BH2 + dB1, Bh + sB1 + ko);
            cp_commit();
            cp_wait<1>();
        } else {
            cp_wait<0>();
        }
        __syncthreads();

#pragma unroll
        for (int ks = 0; ks < 2; ks++) {
            uint32_t kb = ks * 32;
            uint32_t ah[2][4], al[2][4];
#pragma unroll
            for (int i = 0; i < 2; i++) {
                ldsm4(ah[i][0], ah[i][1], ah[i][2], ah[i][3],
                      sb + bo + AH2 + aOff[i] + kb);
                ldsm4(al[i][0], al[i][1], al[i][2], al[i][3],
                      sb + bo + AL2 + aOff[i] + kb);
            }
#pragma unroll
            for (int jj = 0; jj < 2; jj++) {
                uint32_t h0, h1, h2, h3;
                ldsm4(h0, h1, h2, h3, sb + bo + BH2 + bOff[jj] + kb);
                int j0 = 2 * jj, j1 = 2 * jj + 1;
                mma_f16(acc[0][j0], ah[0], h0, h2);
                mma_f16(acc[0][j1], ah[0], h1, h3);
                mma_f16(acc[1][j0], ah[1], h0, h2);
                mma_f16(acc[1][j1], ah[1], h1, h3);
                mma_f16(acc[0][j0], al[0], h0, h2);
                mma_f16(acc[0][j1], al[0], h1, h3);
                mma_f16(acc[1][j0], al[1], h0, h2);
                mma_f16(acc[1][j1], al[1], h1, h3);
            }
        }
        __syncthreads();
    }

    float* C = g_adjP[zk] + (long long)b * 64 * ADJ_LD;
#pragma unroll
    for (int i = 0; i < 2; i++) {
        int m = warpM * 32 + i * 16 + (lane >> 2);
        float rb0 = (zk == 0) ? g_dP[b * 64 + m] : 0.f;
        float rb1 = (zk == 0) ? g_dP[b * 64 + m + 8] : 0.f;
#pragma unroll
        for (int j = 0; j < 4; j++) {
            int n = stile * 128 + warpN * 32 + j * 8 + 2 * (lane & 3);
            C[(long long)m * ADJ_LD + n]           = acc[i][j][0] + rb0;
            C[(long long)m * ADJ_LD + n + 1]       = acc[i][j][1] + rb0;
            C[(long long)(m + 8) * ADJ_LD + n]     = acc[i][j][2] + rb1;
            C[(long long)(m + 8) * ADJ_LD + n + 1] = acc[i][j][3] + rb1;
        }
    }
}

// ---------------- softmax: sum partials, softmax, emit fp16 hi/lo ------------
__global__ void __launch_bounds__(256) softmax_k() {
    int n = blockIdx.x, g = blockIdx.y, b = blockIdx.z;
    if (n >= g_cnt[b]) return;
    long long roff = (long long)(b * 64 + g * 16 + n) * ADJ_LD;
    float* p0 = g_adjP[0] + roff;
    const float* p1 = g_adjP[1] + roff;
    int tid = threadIdx.x;
    __shared__ float red[8];

    float mx = -1e30f;
    for (int s = tid; s < SS; s += 256) mx = fmaxf(mx, p0[s] + p1[s]);
#pragma unroll
    for (int o = 16; o > 0; o >>= 1) mx = fmaxf(mx, __shfl_xor_sync(0xffffffffu, mx, o));
    if ((tid & 31) == 0) red[tid >> 5] = mx;
    __syncthreads();
    if (tid < 32) {
        float v = (tid < 8) ? red[tid] : -1e30f;
#pragma unroll
        for (int o = 4; o > 0; o >>= 1) v = fmaxf(v, __shfl_xor_sync(0xffffffffu, v, o));
        if (tid == 0) red[0] = v;
    }
    __syncthreads();
    mx = red[0];
    __syncthreads();

    float sum = 0.f;
    for (int s = tid; s < SS; s += 256) {
        float e = __expf(p0[s] + p1[s] - mx);
        p0[s] = e;
        sum += e;
    }
#pragma unroll
    for (int o = 16; o > 0; o >>= 1) sum += __shfl_xor_sync(0xffffffffu, sum, o);
    if ((tid & 31) == 0) red[tid >> 5] = sum;
    __syncthreads();
    if (tid < 32) {
        float v = (tid < 8) ? red[tid] : 0.f;
#pragma unroll
        for (int o = 4; o > 0; o >>= 1) v += __shfl_xor_sync(0xffffffffu, v, o);
        if (tid == 0) red[0] = v;
    }
    __syncthreads();
    float inv = 1.f / red[0];
    for (int s = tid; s < SS; s += 256) {
        float v = p0[s] * inv;
        __half h = __float2half(v);
        g_adjh[roff + s] = h;
        g_adjl[roff + s] = __float2half(v - __half2float(h));
    }
}

// ---------------- R MMA (fp16 2-term, split-K x4 over s) ---------------------
__global__ void __launch_bounds__(256, 3) r_mma_k() {
    extern __shared__ __align__(16) char sm[];
    int tid = threadIdx.x, lane = tid & 31, wid = tid >> 5;
    int b = blockIdx.y, zk = blockIdx.z;
    int n0 = blockIdx.x * 128;
    uint32_t sb = smem_u32(sm);

    const char* Ah = (const char*)(g_adjh + (long long)b * 64 * ADJ_LD);
    const char* Al = (const char*)(g_adjl + (long long)b * 64 * ADJ_LD);
    const char* Bh = (const char*)(g_fmCh + (long long)b * DIN * SS);

    int rA = tid >> 2, cA = tid & 3;
    uint32_t dA = rA * RS2 + cA * 16;
    long long sA = (long long)rA * (ADJ_LD * 2) + cA * 16;
    int rB0 = tid >> 2, cB0 = tid & 3;
    int id1 = tid + 256;
    int rB1 = id1 >> 2, cB1 = id1 & 3;
    int cr0 = n0 + rB0; if (cr0 >= DIN) cr0 = DIN - 1;
    int cr1 = n0 + rB1; if (cr1 >= DIN) cr1 = DIN - 1;
    uint32_t dB0 = rB0 * RS2 + cB0 * 16, dB1 = rB1 * RS2 + cB1 * 16;
    long long sB0 = (long long)cr0 * (SS * 2) + cB0 * 16;
    long long sB1 = (long long)cr1 * (SS * 2) + cB1 * 16;

    int warpM = wid & 1, warpN = wid >> 1;
    uint32_t aOff[2], bOff[2];
#pragma unroll
    for (int i = 0; i < 2; i++)
        aOff[i] = (warpM * 32 + i * 16 + (lane & 15)) * RS2 + (lane >> 4) * 16;
#pragma unroll
    for (int jj = 0; jj < 2; jj++)
        bOff[jj] = (warpN * 32 + jj * 16 + (lane & 15)) * RS2 + (lane >> 4) * 16;

    float acc[2][4][4];
#pragma unroll
    for (int i = 0; i < 2; i++)
#pragma unroll
        for (int j = 0; j < 4; j++)
#pragma unroll
            for (int q = 0; q < 4; q++) acc[i][j][q] = 0.f;

    int kbeg = (zk == 0) ? 0 : (zk * 12 + 1);   // 13/12/12/12 chunks of k32
    int kcnt = (zk == 0) ? 13 : 12;
    {
        long long ko = (long long)kbeg * 64;
        cp16(sb + AH2 + dA, Ah + sA + ko);
        cp16(sb + AL2 + dA, Al + sA + ko);
        cp16(sb + BH2 + dB0, Bh + sB0 + ko);
        cp16(sb + BH2 + dB1, Bh + sB1 + ko);
        cp_commit();
    }

    for (int kc = 0; kc < kcnt; kc++) {
        uint32_t bo = (kc & 1) ? STG2 : 0;
        if (kc + 1 < kcnt) {
            long long ko = (long long)(kbeg + kc + 1) * 64;
            uint32_t nbo = ((kc + 1) & 1) ? STG2 : 0;
            cp16(sb + nbo + AH2 + dA, Ah + sA + ko);
            cp16(sb + nbo + AL2 + dA, Al + sA + ko);
            cp16(sb + nbo + BH2 + dB0, Bh + sB0 + ko);
            cp16(sb + nbo + BH2 + dB1, Bh + sB1 + ko);
            cp_commit();
            cp_wait<1>();
        } else {
            cp_wait<0>();
        }
        __syncthreads();

#pragma unroll
        for (int ks = 0; ks < 2; ks++) {
            uint32_t kb = ks * 32;
            uint32_t ah[2][4], al[2][4];
#pragma unroll
            for (int i = 0; i < 2; i++) {
                ldsm4(ah[i][0], ah[i][1], ah[i][2], ah[i][3],
                      sb + bo + AH2 + aOff[i] + kb);
                ldsm4(al[i][0], al[i][1], al[i][2], al[i][3],
                      sb + bo + AL2 + aOff[i] + kb);
            }
#pragma unroll
            for (int jj = 0; jj < 2; jj++) {
                uint32_t h0, h1, h2, h3;
                ldsm4(h0, h1, h2, h3, sb + bo + BH2 + bOff[jj] + kb);
                int j0 = 2 * jj, j1 = 2 * jj + 1;
                mma_f16(acc[0][j0], ah[0], h0, h2);
                mma_f16(acc[0][j1], ah[0], h1, h3);
                mma_f16(acc[1][j0], ah[1], h0, h2);
                mma_f16(acc[1][j1], ah[1], h1, h3);
                mma_f16(acc[0][j0], al[0], h0, h2);
                mma_f16(acc[0][j1], al[0], h1, h3);
                mma_f16(acc[1][j0], al[1], h0, h2);
                mma_f16(acc[1][j1], al[1], h1, h3);
            }
        }
        __syncthreads();
    }

    float* C = g_Rp[zk] + (long long)b * 64 * CP2;
#pragma unroll
    for (int i = 0; i < 2; i++) {
        int m = warpM * 32 + i * 16 + (lane >> 2);
#pragma unroll
        for (int j = 0; j < 4; j++) {
            int n = n0 + warpN * 32 + j * 8 + 2 * (lane & 3);
            bool ok0 = (n < DIN), ok1 = (n + 1 < DIN);
            C[(long long)m * CP2 + n]           = ok0 ? acc[i][j][0] : 0.f;
            C[(long long)m * CP2 + n + 1]       = ok1 ? acc[i][j][1] : 0.f;
            C[(long long)(m + 8) * CP2 + n]     = ok0 ? acc[i][j][2] : 0.f;
            C[(long long)(m + 8) * CP2 + n + 1] = ok1 ? acc[i][j][3] : 0.f;
        }
    }
}

// ---------------- gather sum(Rp) -> Rf (ragged flat) -------------------------
__global__ void __launch_bounds__(256) gather_rf_k() {
    int row = blockIdx.x;
    int b = blockIdx.y;
    int g = row >> 4, n = row & 15;
    if (n >= g_cnt[b]) return;
    int t = g_off[b] + n;
    int tid = threadIdx.x;
    long long roff = ((long long)b * 64 + row) * CP2;
    float* dst = g_Rf + ((long long)t * NGR + g) * CP2;
    for (int c = tid; c < CP2; c += 256) {
        float v = 0.f;
#pragma unroll
        for (int z = 0; z < RSPLIT; z++)
            v += g_Rp[z][roff + c];
        dst[c] = v;
    }
}

// ---------------- launch ----------------------------------------------------
extern "C" void kernel_launch(void* const* d_in, const int* in_sizes, int n_in,
                              void* d_out, int out_size) {
    const float* actor = (const float*)d_in[0];
    const float* fmap  = (const float*)d_in[1];
    const float* W_a   = (const float*)d_in[2];
    const float* b_a   = (const float*)d_in[3];
    const float* W_c   = (const float*)d_in[4];
    const float* b_c   = (const float*)d_in[5];
    const float* W_h   = (const float*)d_in[6];
    const void*  counts = d_in[7];
    int nbias = 0;
    for (int i = 0; i < n_in; i++) {
        switch (in_sizes[i]) {
            case TOT * IDIM:      actor = (const float*)d_in[i]; break;
            case NB * DIN * SS:   fmap  = (const float*)d_in[i]; break;
            case NGR * GF * IDIM: W_a   = (const float*)d_in[i]; break;
            case NGR * GF * DIN:  W_c   = (const float*)d_in[i]; break;
            case NGR * GF * GF:   W_h   = (const float*)d_in[i]; break;
            case NGR * GF:
                if (nbias++ == 0) b_a = (const float*)d_in[i];
                else              b_c = (const float*)d_in[i];
                break;
            case NB:              counts = d_in[i]; break;
            default: break;
        }
    }
    float* out = (float*)d_out;

    float *emb_p, *wcT_p, *wcP_p, *e2f_p, *Rf_p, *flat_p;
    cudaGetSymbolAddress((void**)&emb_p, g_emb);
    cudaGetSymbolAddress((void**)&wcT_p, g_WcT);
    cudaGetSymbolAddress((void**)&wcP_p, g_WcP);
    cudaGetSymbolAddress((void**)&e2f_p, g_E2flat);
    cudaGetSymbolAddress((void**)&Rf_p, g_Rf);
    cudaGetSymbolAddress((void**)&flat_p, g_flat);

    cudaFuncSetAttribute(adj_mma_k, cudaFuncAttributeMaxDynamicSharedMemorySize, SMEM2);
    cudaFuncSetAttribute(r_mma_k, cudaFuncAttributeMaxDynamicSharedMemorySize, SMEM2);

    // 0: ragged bookkeeping
    init_offsets_k<<<1, 32>>>(counts);
    // 1: W prep
    prep_w_k<<<(NGR * GF * CP2 + 255) / 256, 256>>>(W_c);
    // 2: emb partials (split-K x8)
    emb_part_k<<<dim3(5, 16, KSPLIT), 256>>>(actor, W_a);
    // 3: fm -> fp16 (both layouts)  [profile slot]
    split_fm_k<<<dim3(SS / 32, CP2 / 32, NB), dim3(32, 8)>>>(fmap);
    // 4: emb reduce + bias
    emb_reduce_k<<<(TOT * IDIM + 255) / 256, 256>>>(b_a);
    // 5: E2flat[t][g][c] = emb[t,g,:] @ WcT[g]^T
    gemm_flex_k<<<dim3(5, CP2 / 64, NGR), 256>>>(
        emb_p, IDIM, GF,
        wcT_p, GF, (long long)CP2 * GF, CP2,
        nullptr, 0, nullptr, 0, 0,
        e2f_p, NGR * CP2, CP2,
        GF, CP2, 0);
    // 6: scatter E2 -> fp16 padded rows + dP
    scatter_e2_k<<<dim3(64, NB), 256>>>(b_c);
    // 7: adj partials via fp16 MMA (split-K x2)
    adj_mma_k<<<dim3(SROWS / 128, NB, ASPLIT), 256, SMEM2>>>();
    // 8: softmax (sums partials) -> adj fp16 hi/lo
    softmax_k<<<dim3(NMAX, NGR, NB), 256>>>();
    // 9: R partials via fp16 MMA (split-K x4)
    r_mma_k<<<dim3(CP2 / 128, NB, RSPLIT), 256, SMEM2>>>();
    // 10: gather sum(Rp) -> ragged flat
    gather_rf_k<<<dim3(64, NB), 256>>>();
    // 11: flat = Rf @ WcP^T + b_c + emb
    gemm_flex_k<<<dim3(5, NGR, NGR), 256>>>(
        Rf_p, NGR * CP2, CP2,
        wcP_p, CP2, (long long)GF * CP2, GF,
        b_c, GF,
        emb_p, IDIM, GF,
        flat_p, IDIM, GF,
        CP2, GF, 0);
    // 12: head: out = relu(flat @ W_h^T)
    gemm_flex_k<<<dim3(5, NGR, NGR), 256>>>(
        flat_p, IDIM, GF,
        W_h, GF, (long long)GF * GF, GF,
        nullptr, 0, nullptr, 0, 0,
        out, IDIM, GF,
        GF, GF, 1);
}

// round 16
// speedup vs baseline: 3.4788x; 1.0670x over previous
#include <cuda_runtime.h>
#include <cuda_fp16.h>
#include <cstdint>

// Problem constants
#define NGR 4
#define GF 256
#define DIN 834
#define SS 1568
#define NB 16
#define TOT 160
#define IDIM 1024
#define NMAX 16

#define CP2 896             // c padded (28 x 32)
#define ADJ_LD 1664         // s padded (52 x 32)
#define SROWS 1664          // adj s tiles: 13 x 128
#define KSPLIT 8
#define RSPLIT 4
#define ASPLIT 2

// mma smem (A tiles): RS2=80B row stride, k=32 fp16 per stage slot
#define RS2 80
#define A_TB (64 * RS2)             // 5120
// adj B tile: [k=32][n=128] fp16, row stride 272B
#define RSB 272
#define BT_TRANS (32 * RSB)         // 8704
#define AH2 0
#define AL2 (A_TB)
#define BH2 (2 * A_TB)
#define STG_A (2 * A_TB + BT_TRANS) // 18944 (adj stage)
#define SMEM_A (2 * STG_A)          // 37888
// r B tile: [n=128][k=32] fp16, row stride 80B
#define B_TB (128 * RS2)            // 10240
#define STG_R (2 * A_TB + B_TB)     // 20480
#define SMEM_R (2 * STG_R)          // 40960

// ---------------- scratch (static device globals) --------------------------
__device__ float g_emb[TOT * IDIM];
__device__ float g_embP[KSPLIT * TOT * IDIM];
__device__ float g_WcT[NGR * CP2 * GF];              // [g][c][f]
__device__ float g_WcP[NGR * GF * CP2];              // [g][f][c], zero pad
__device__ float g_E2flat[TOT * NGR * CP2];          // [t][g][c]
__device__ __half g_e2h[NB * 64 * CP2];              // A of adj (hi), pad zero
__device__ __half g_e2l[NB * 64 * CP2];
__device__ float g_dP[NB * 64];
__device__ __half g_fmCh[(long long)NB * DIN * SS];  // [b][c][s] (B of both MMAs)
__device__ float g_adjP[ASPLIT][NB * 64 * ADJ_LD];
__device__ __half g_adjh[NB * 64 * ADJ_LD];          // softmaxed, zero-static
__device__ __half g_adjl[NB * 64 * ADJ_LD];
__device__ float g_Rp[RSPLIT][NB * 64 * CP2];
__device__ float g_Rf[TOT * NGR * CP2];
__device__ float g_flat[TOT * IDIM];
__device__ int   g_off[NB];
__device__ int   g_cnt[NB];

// ---------------- PTX helpers ------------------------------------------------
__device__ __forceinline__ uint32_t smem_u32(const void* p) {
    uint32_t a;
    asm("{ .reg .u64 t; cvta.to.shared.u64 t, %1; cvt.u32.u64 %0, t; }"
        : "=r"(a) : "l"(p));
    return a;
}
__device__ __forceinline__ void cp16(uint32_t dst, const void* src) {
    asm volatile("cp.async.cg.shared.global [%0], [%1], 16;"
                 :: "r"(dst), "l"(src) : "memory");
}
__device__ __forceinline__ void cp_commit() {
    asm volatile("cp.async.commit_group;" ::: "memory");
}
template <int N>
__device__ __forceinline__ void cp_wait() {
    asm volatile("cp.async.wait_group %0;" :: "n"(N) : "memory");
}
__device__ __forceinline__ void ldsm4(uint32_t& r0, uint32_t& r1, uint32_t& r2,
                                      uint32_t& r3, uint32_t a) {
    asm volatile("ldmatrix.sync.aligned.m8n8.x4.shared.b16 {%0,%1,%2,%3}, [%4];"
                 : "=r"(r0), "=r"(r1), "=r"(r2), "=r"(r3) : "r"(a));
}
__device__ __forceinline__ void ldsm4t(uint32_t& r0, uint32_t& r1, uint32_t& r2,
                                       uint32_t& r3, uint32_t a) {
    asm volatile("ldmatrix.sync.aligned.m8n8.x4.trans.shared.b16 {%0,%1,%2,%3}, [%4];"
                 : "=r"(r0), "=r"(r1), "=r"(r2), "=r"(r3) : "r"(a));
}
__device__ __forceinline__ void mma_f16(float* c, const uint32_t* a,
                                        uint32_t b0, uint32_t b1) {
    asm volatile(
        "mma.sync.aligned.m16n8k16.row.col.f32.f16.f16.f32 "
        "{%0,%1,%2,%3}, {%4,%5,%6,%7}, {%8,%9}, {%0,%1,%2,%3};"
        : "+f"(c[0]), "+f"(c[1]), "+f"(c[2]), "+f"(c[3])
        : "r"(a[0]), "r"(a[1]), "r"(a[2]), "r"(a[3]), "r"(b0), "r"(b1));
}

// ---------------- K0: ragged bookkeeping ------------------------------------
__global__ void init_offsets_k(const void* __restrict__ counts) {
    if (threadIdx.x == 0 && blockIdx.x == 0) {
        const int* c32 = (const int*)counts;
        const long long* c64 = (const long long*)counts;
        long long s = 0;
        bool ok32 = true;
        for (int b = 0; b < NB; b++) {
            int v = c32[b];
            if (v < 0 || v > NMAX) ok32 = false;
            s += v;
        }
        if (s != TOT) ok32 = false;
        int acc = 0;
        for (int b = 0; b < NB; b++) {
            int c = ok32 ? c32[b] : (int)c64[b];
            if (c < 0) c = 0;
            if (c > NMAX) c = NMAX;
            g_off[b] = acc;
            g_cnt[b] = c;
            acc += c;
        }
    }
}

// ---------------- prep: WcP[g][f][c] + WcT[g][c][f] -------------------------
__global__ void __launch_bounds__(256) prep_w_k(const float* __restrict__ Wc) {
    int id = blockIdx.x * 256 + threadIdx.x;
    if (id >= NGR * GF * CP2) return;
    int c = id % CP2;
    int rf = id / CP2;
    int f = rf % GF, g = rf / GF;
    float v = (c < DIN) ? Wc[(long long)rf * DIN + c] : 0.f;
    g_WcP[id] = v;
    g_WcT[((long long)g * CP2 + c) * GF + f] = v;
}

// ---------------- prep: fm -> fp16 (native [b][c][s] layout), vectorized ----
__global__ void __launch_bounds__(256) convert_fm_k(const float* __restrict__ fm) {
    long long id = ((long long)blockIdx.x * 256 + threadIdx.x) * 4;
    if (id >= (long long)NB * DIN * SS) return;
    float4 v = *(const float4*)(fm + id);
    __half2 h0 = __floats2half2_rn(v.x, v.y);
    __half2 h1 = __floats2half2_rn(v.z, v.w);
    uint2 u;
    u.x = *(uint32_t*)&h0;
    u.y = *(uint32_t*)&h1;
    *(uint2*)(g_fmCh + id) = u;
}

// ---------------- emb: register-tiled 64m x 128n fp32, split-K x8 -----------
__global__ void __launch_bounds__(256) emb_tile_k(
    const float* __restrict__ A, const float* __restrict__ Bm)
{
    __shared__ __align__(16) float As[32][68];
    __shared__ __align__(16) float Bs[32][132];

    int n0 = blockIdx.x * 128;
    int m0 = blockIdx.y * 64;
    int zk = blockIdx.z;
    int kbase = zk * (IDIM / KSPLIT);   // 128
    int tid = threadIdx.x;
    int tx = tid & 31, ty = tid >> 5;

    float acc[8][4];
#pragma unroll
    for (int i = 0; i < 8; i++)
#pragma unroll
        for (int j = 0; j < 4; j++) acc[i][j] = 0.f;

    for (int kc = 0; kc < IDIM / KSPLIT; kc += 32) {
        int k0 = kbase + kc;
#pragma unroll
        for (int t = 0; t < 8; t++) {          // A: 64m x 32k
            int lin = tid + 256 * t;
            int k = lin & 31, m = lin >> 5;
            int row = m0 + m; if (row >= TOT) row = TOT - 1;
            As[k][m] = A[row * IDIM + k0 + k];
        }
#pragma unroll
        for (int t = 0; t < 16; t++) {         // B: 128n x 32k (NT)
            int lin = tid + 256 * t;
            int k = lin & 31, n = lin >> 5;
            Bs[k][n] = Bm[(long long)(n0 + n) * IDIM + k0 + k];
        }
        __syncthreads();
#pragma unroll
        for (int k = 0; k < 32; k++) {
            float a[8], bv[4];
            *(float4*)&a[0] = *(const float4*)&As[k][ty * 8];
            *(float4*)&a[4] = *(const float4*)&As[k][ty * 8 + 4];
            *(float4*)&bv[0] = *(const float4*)&Bs[k][tx * 4];
#pragma unroll
            for (int i = 0; i < 8; i++)
#pragma unroll
                for (int j = 0; j < 4; j++)
                    acc[i][j] += a[i] * bv[j];
        }
        __syncthreads();
    }

    float* P = g_embP + (long long)zk * TOT * IDIM;
#pragma unroll
    for (int i = 0; i < 8; i++) {
        int m = m0 + ty * 8 + i;
        if (m < TOT) {
#pragma unroll
            for (int j = 0; j < 4; j++)
                P[m * IDIM + n0 + tx * 4 + j] = acc[i][j];
        }
    }
}

__global__ void __launch_bounds__(256) emb_reduce_k(const float* __restrict__ ba) {
    int id = blockIdx.x * 256 + threadIdx.x;
    if (id >= TOT * IDIM) return;
    float v = ba[id & (IDIM - 1)];
#pragma unroll
    for (int z = 0; z < KSPLIT; z++)
        v += g_embP[z * (TOT * IDIM) + id];
    g_emb[id] = v;
}

// ---------------- flexible GEMM (small GEMMs): C = A @ B^T ------------------
__global__ void __launch_bounds__(256) gemm_flex_k(
    const float* __restrict__ A, int lda, long long aZ,
    const float* __restrict__ Bm, int ldb, long long bZ, int Brows,
    const float* __restrict__ cbias, long long cbZ,
    const float* __restrict__ resid, int ldres, long long resZ,
    float* __restrict__ C, int ldc, long long cZ,
    int K, int Nstore, int doRelu)
{
    int z = blockIdx.z;
    A  += (long long)z * aZ;
    Bm += (long long)z * bZ;
    C  += (long long)z * cZ;

    __shared__ __align__(16) float As[32][33];
    __shared__ __align__(16) float Bs[32][65];

    int tid = threadIdx.x;
    int m0 = blockIdx.x * 32;
    int n0 = blockIdx.y * 64;
    int tx = tid % 64, ty = tid / 64;

    float acc[8];
#pragma unroll
    for (int i = 0; i < 8; i++) acc[i] = 0.f;

    for (int k0 = 0; k0 < K; k0 += 32) {
#pragma unroll
        for (int t = 0; t < 4; t++) {
            int lin = tid + 256 * t;
            int k = lin & 31, m = lin >> 5;
            As[k][m] = A[(long long)(m0 + m) * lda + k0 + k];
        }
#pragma unroll
        for (int t = 0; t < 8; t++) {
            int lin = tid + 256 * t;
            int k = lin & 31, n = lin >> 5;
            int r = n0 + n;
            if (r >= Brows) r = Brows - 1;
            Bs[k][n] = Bm[(long long)r * ldb + k0 + k];
        }
        __syncthreads();
#pragma unroll
        for (int k = 0; k < 32; k++) {
            float bv = Bs[k][tx];
#pragma unroll
            for (int i = 0; i < 8; i++)
                acc[i] += As[k][ty + 4 * i] * bv;
        }
        __syncthreads();
    }

    int n = n0 + tx;
    bool nok = (n < Nstore);
    float cb = (cbias && nok) ? cbias[z * cbZ + n] : 0.f;
#pragma unroll
    for (int i = 0; i < 8; i++) {
        int m = m0 + ty + 4 * i;
        float outv = 0.f;
        if (nok) {
            float v = acc[i] + cb;
            if (resid) v += resid[z * resZ + (long long)m * ldres + n];
            if (doRelu) v = fmaxf(v, 0.f);
            outv = v;
        }
        C[(long long)m * ldc + n] = outv;
    }
}

// ---------------- scatter E2 -> fp16 hi/lo padded rows, dP -------------------
__global__ void __launch_bounds__(256) scatter_e2_k(const float* __restrict__ bc) {
    int row = blockIdx.x;        // g*16 + n
    int b = blockIdx.y;
    int g = row >> 4, n = row & 15;
    int tid = threadIdx.x;
    bool valid = (n < g_cnt[b]);
    int t = g_off[b] + n;

    long long doff = ((long long)b * 64 + row) * CP2;
    const float* src = g_E2flat + ((long long)t * NGR + g) * CP2;
    for (int c = tid; c < CP2; c += 256) {
        float v = valid ? src[c] : 0.f;
        __half h = __float2half(v);
        g_e2h[doff + c] = h;
        g_e2l[doff + c] = __float2half(v - __half2float(h));
    }

    __shared__ float red[8];
    float v = valid ? g_emb[t * IDIM + g * GF + tid] * bc[g * GF + tid] : 0.f;
#pragma unroll
    for (int o = 16; o > 0; o >>= 1) v += __shfl_xor_sync(0xffffffffu, v, o);
    if ((tid & 31) == 0) red[tid >> 5] = v;
    __syncthreads();
    if (tid == 0) {
        float s = 0.f;
#pragma unroll
        for (int w = 0; w < 8; w++) s += red[w];
        g_dP[b * 64 + row] = s;
    }
}

// ---------------- adj MMA (fp16 2-term, split-K x2), B via ldmatrix.trans ---
// adjP[zk][b][64][s] = E2[b] @ fm[b]^T; B tile loaded from native fmCh [c][s].
__global__ void __launch_bounds__(256, 3) adj_mma_k() {
    extern __shared__ __align__(16) char sm[];
    int tid = threadIdx.x, lane = tid & 31, wid = tid >> 5;
    int stile = blockIdx.x, b = blockIdx.y, zk = blockIdx.z;
    uint32_t sb = smem_u32(sm);

    const char* Ah = (const char*)(g_e2h + (long long)b * 64 * CP2);
    const char* Al = (const char*)(g_e2l + (long long)b * 64 * CP2);
    const char* Bh = (const char*)(g_fmCh + (long long)b * DIN * SS);

    // A load slots (64 rows x 64B = 256 chunks, 1/thread)
    int rA = tid >> 2, cA = tid & 3;
    uint32_t dA = rA * RS2 + cA * 16;
    long long sA = (long long)rA * (CP2 * 2) + cA * 16;
    // B load slots: [k=32 rows][n 256B] = 512 chunks, 2/thread
    int rB0 = tid >> 4, cB0 = tid & 15;          // ids 0..255
    int id1 = tid + 256;
    int rB1 = id1 >> 4, cB1 = id1 & 15;
    uint32_t dB0 = rB0 * RSB + cB0 * 16, dB1 = rB1 * RSB + cB1 * 16;
    int sbyte0 = stile * 256 + cB0 * 16; if (sbyte0 > SS * 2 - 16) sbyte0 = SS * 2 - 16;
    int sbyte1 = stile * 256 + cB1 * 16; if (sbyte1 > SS * 2 - 16) sbyte1 = SS * 2 - 16;

    int warpM = wid & 1, warpN = wid >> 1;
    uint32_t aOff[2], bOffT[2];
#pragma unroll
    for (int i = 0; i < 2; i++)
        aOff[i] = (warpM * 32 + i * 16 + (lane & 15)) * RS2 + (lane >> 4) * 16;
    {
        int rowT = (lane & 7) | ((lane & 16) >> 1);     // k row within 16
        int colT = (lane & 8) * 2;                       // 0 or 16 bytes
#pragma unroll
        for (int jj = 0; jj < 2; jj++)
            bOffT[jj] = rowT * RSB + colT + (warpN * 32 + jj * 16) * 2;
    }

    float acc[2][4][4];
#pragma unroll
    for (int i = 0; i < 2; i++)
#pragma unroll
        for (int j = 0; j < 4; j++)
#pragma unroll
            for (int q = 0; q < 4; q++) acc[i][j][q] = 0.f;

    const int NCH = CP2 / 32 / ASPLIT;   // 14
    int kbeg = zk * NCH;
    {
        int chunk = kbeg;
        long long ko = (long long)chunk * 64;
        cp16(sb + AH2 + dA, Ah + sA + ko);
        cp16(sb + AL2 + dA, Al + sA + ko);
        int c0 = chunk * 32 + rB0; if (c0 >= DIN) c0 = DIN - 1;
        int c1 = chunk * 32 + rB1; if (c1 >= DIN) c1 = DIN - 1;
        cp16(sb + BH2 + dB0, Bh + (long long)c0 * (SS * 2) + sbyte0);
        cp16(sb + BH2 + dB1, Bh + (long long)c1 * (SS * 2) + sbyte1);
        cp_commit();
    }

    for (int kc = 0; kc < NCH; kc++) {
        uint32_t bo = (kc & 1) ? STG_A : 0;
        if (kc + 1 < NCH) {
            int chunk = kbeg + kc + 1;
            long long ko = (long long)chunk * 64;
            uint32_t nbo = ((kc + 1) & 1) ? STG_A : 0;
            cp16(sb + nbo + AH2 + dA, Ah + sA + ko);
            cp16(sb + nbo + AL2 + dA, Al + sA + ko);
            int c0 = chunk * 32 + rB0; if (c0 >= DIN) c0 = DIN - 1;
            int c1 = chunk * 32 + rB1; if (c1 >= DIN) c1 = DIN - 1;
            cp16(sb + nbo + BH2 + dB0, Bh + (long long)c0 * (SS * 2) + sbyte0);
            cp16(sb + nbo + BH2 + dB1, Bh + (long long)c1 * (SS * 2) + sbyte1);
            cp_commit();
            cp_wait<1>();
        } else {
            cp_wait<0>();
        }
        __syncthreads();

#pragma unroll
        for (int ks = 0; ks < 2; ks++) {
            uint32_t kbA = ks * 32;                // A: byte offset in k
            uint32_t kbB = ks * 16 * RSB;          // B: 16 k-rows per step
            uint32_t ah[2][4], al[2][4];
#pragma unroll
            for (int i = 0; i < 2; i++) {
                ldsm4(ah[i][0], ah[i][1], ah[i][2], ah[i][3],
                      sb + bo + AH2 + aOff[i] + kbA);
                ldsm4(al[i][0], al[i][1], al[i][2], al[i][3],
                      sb + bo + AL2 + aOff[i] + kbA);
            }
#pragma unroll
            for (int jj = 0; jj < 2; jj++) {
                uint32_t h0, h1, h2, h3;
                ldsm4t(h0, h1, h2, h3, sb + bo + BH2 + bOffT[jj] + kbB);
                int j0 = 2 * jj, j1 = 2 * jj + 1;
                mma_f16(acc[0][j0], ah[0], h0, h2);
                mma_f16(acc[0][j1], ah[0], h1, h3);
                mma_f16(acc[1][j0], ah[1], h0, h2);
                mma_f16(acc[1][j1], ah[1], h1, h3);
                mma_f16(acc[0][j0], al[0], h0, h2);
                mma_f16(acc[0][j1], al[0], h1, h3);
                mma_f16(acc[1][j0], al[1], h0, h2);
                mma_f16(acc[1][j1], al[1], h1, h3);
            }
        }
        __syncthreads();
    }

    float* C = g_adjP[zk] + (long long)b * 64 * ADJ_LD;
#pragma unroll
    for (int i = 0; i < 2; i++) {
        int m = warpM * 32 + i * 16 + (lane >> 2);
        float rb0 = (zk == 0) ? g_dP[b * 64 + m] : 0.f;
        float rb1 = (zk == 0) ? g_dP[b * 64 + m + 8] : 0.f;
#pragma unroll
        for (int j = 0; j < 4; j++) {
            int n = stile * 128 + warpN * 32 + j * 8 + 2 * (lane & 3);
            C[(long long)m * ADJ_LD + n]           = acc[i][j][0] + rb0;
            C[(long long)m * ADJ_LD + n + 1]       = acc[i][j][1] + rb0;
            C[(long long)(m + 8) * ADJ_LD + n]     = acc[i][j][2] + rb1;
            C[(long long)(m + 8) * ADJ_LD + n + 1] = acc[i][j][3] + rb1;
        }
    }
}

// ---------------- softmax: sum partials, softmax, emit fp16 hi/lo ------------
__global__ void __launch_bounds__(256) softmax_k() {
    int n = blockIdx.x, g = blockIdx.y, b = blockIdx.z;
    if (n >= g_cnt[b]) return;
    long long roff = (long long)(b * 64 + g * 16 + n) * ADJ_LD;
    float* p0 = g_adjP[0] + roff;
    const float* p1 = g_adjP[1] + roff;
    int tid = threadIdx.x;
    __shared__ float red[8];

    float mx = -1e30f;
    for (int s = tid; s < SS; s += 256) mx = fmaxf(mx, p0[s] + p1[s]);
#pragma unroll
    for (int o = 16; o > 0; o >>= 1) mx = fmaxf(mx, __shfl_xor_sync(0xffffffffu, mx, o));
    if ((tid & 31) == 0) red[tid >> 5] = mx;
    __syncthreads();
    if (tid < 32) {
        float v = (tid < 8) ? red[tid] : -1e30f;
#pragma unroll
        for (int o = 4; o > 0; o >>= 1) v = fmaxf(v, __shfl_xor_sync(0xffffffffu, v, o));
        if (tid == 0) red[0] = v;
    }
    __syncthreads();
    mx = red[0];
    __syncthreads();

    float sum = 0.f;
    for (int s = tid; s < SS; s += 256) {
        float e = __expf(p0[s] + p1[s] - mx);
        p0[s] = e;
        sum += e;
    }
#pragma unroll
    for (int o = 16; o > 0; o >>= 1) sum += __shfl_xor_sync(0xffffffffu, sum, o);
    if ((tid & 31) == 0) red[tid >> 5] = sum;
    __syncthreads();
    if (tid < 32) {
        float v = (tid < 8) ? red[tid] : 0.f;
#pragma unroll
        for (int o = 4; o > 0; o >>= 1) v += __shfl_xor_sync(0xffffffffu, v, o);
        if (tid == 0) red[0] = v;
    }
    __syncthreads();
    float inv = 1.f / red[0];
    for (int s = tid; s < SS; s += 256) {
        float v = p0[s] * inv;
        __half h = __float2half(v);
        g_adjh[roff + s] = h;
        g_adjl[roff + s] = __float2half(v - __half2float(h));
    }
}

// ---------------- R MMA (fp16 2-term, split-K x4 over s) ---------------------
__global__ void __launch_bounds__(256, 3) r_mma_k() {
    extern __shared__ __align__(16) char sm[];
    int tid = threadIdx.x, lane = tid & 31, wid = tid >> 5;
    int b = blockIdx.y, zk = blockIdx.z;
    int n0 = blockIdx.x * 128;
    uint32_t sb = smem_u32(sm);

    const char* Ah = (const char*)(g_adjh + (long long)b * 64 * ADJ_LD);
    const char* Al = (const char*)(g_adjl + (long long)b * 64 * ADJ_LD);
    const char* Bh = (const char*)(g_fmCh + (long long)b * DIN * SS);

    int rA = tid >> 2, cA = tid & 3;
    uint32_t dA = rA * RS2 + cA * 16;
    long long sA = (long long)rA * (ADJ_LD * 2) + cA * 16;
    int rB0 = tid >> 2, cB0 = tid & 3;
    int id1 = tid + 256;
    int rB1 = id1 >> 2, cB1 = id1 & 3;
    int cr0 = n0 + rB0; if (cr0 >= DIN) cr0 = DIN - 1;
    int cr1 = n0 + rB1; if (cr1 >= DIN) cr1 = DIN - 1;
    uint32_t dB0 = rB0 * RS2 + cB0 * 16, dB1 = rB1 * RS2 + cB1 * 16;
    long long sB0 = (long long)cr0 * (SS * 2) + cB0 * 16;
    long long sB1 = (long long)cr1 * (SS * 2) + cB1 * 16;

    int warpM = wid & 1, warpN = wid >> 1;
    uint32_t aOff[2], bOff[2];
#pragma unroll
    for (int i = 0; i < 2; i++)
        aOff[i] = (warpM * 32 + i * 16 + (lane & 15)) * RS2 + (lane >> 4) * 16;
#pragma unroll
    for (int jj = 0; jj < 2; jj++)
        bOff[jj] = (warpN * 32 + jj * 16 + (lane & 15)) * RS2 + (lane >> 4) * 16;

    float acc[2][4][4];
#pragma unroll
    for (int i = 0; i < 2; i++)
#pragma unroll
        for (int j = 0; j < 4; j++)
#pragma unroll
            for (int q = 0; q < 4; q++) acc[i][j][q] = 0.f;

    int kbeg = (zk == 0) ? 0 : (zk * 12 + 1);   // 13/12/12/12 chunks of k32
    int kcnt = (zk == 0) ? 13 : 12;
    {
        long long ko = (long long)kbeg * 64;
        cp16(sb + AH2 + dA, Ah + sA + ko);
        cp16(sb + AL2 + dA, Al + sA + ko);
        cp16(sb + BH2 + dB0, Bh + sB0 + ko);
        cp16(sb + BH2 + dB1, Bh + sB1 + ko);
        cp_commit();
    }

    for (int kc = 0; kc < kcnt; kc++) {
        uint32_t bo = (kc & 1) ? STG_R : 0;
        if (kc + 1 < kcnt) {
            long long ko = (long long)(kbeg + kc + 1) * 64;
            uint32_t nbo = ((kc + 1) & 1) ? STG_R : 0;
            cp16(sb + nbo + AH2 + dA, Ah + sA + ko);
            cp16(sb + nbo + AL2 + dA, Al + sA + ko);
            cp16(sb + nbo + BH2 + dB0, Bh + sB0 + ko);
            cp16(sb + nbo + BH2 + dB1, Bh + sB1 + ko);
            cp_commit();
            cp_wait<1>();
        } else {
            cp_wait<0>();
        }
        __syncthreads();

#pragma unroll
        for (int ks = 0; ks < 2; ks++) {
            uint32_t kb = ks * 32;
            uint32_t ah[2][4], al[2][4];
#pragma unroll
            for (int i = 0; i < 2; i++) {
                ldsm4(ah[i][0], ah[i][1], ah[i][2], ah[i][3],
                      sb + bo + AH2 + aOff[i] + kb);
                ldsm4(al[i][0], al[i][1], al[i][2], al[i][3],
                      sb + bo + AL2 + aOff[i] + kb);
            }
#pragma unroll
            for (int jj = 0; jj < 2; jj++) {
                uint32_t h0, h1, h2, h3;
                ldsm4(h0, h1, h2, h3, sb + bo + BH2 + bOff[jj] + kb);
                int j0 = 2 * jj, j1 = 2 * jj + 1;
                mma_f16(acc[0][j0], ah[0], h0, h2);
                mma_f16(acc[0][j1], ah[0], h1, h3);
                mma_f16(acc[1][j0], ah[1], h0, h2);
                mma_f16(acc[1][j1], ah[1], h1, h3);
                mma_f16(acc[0][j0], al[0], h0, h2);
                mma_f16(acc[0][j1], al[0], h1, h3);
                mma_f16(acc[1][j0], al[1], h0, h2);
                mma_f16(acc[1][j1], al[1], h1, h3);
            }
        }
        __syncthreads();
    }

    float* C = g_Rp[zk] + (long long)b * 64 * CP2;
#pragma unroll
    for (int i = 0; i < 2; i++) {
        int m = warpM * 32 + i * 16 + (lane >> 2);
#pragma unroll
        for (int j = 0; j < 4; j++) {
            int n = n0 + warpN * 32 + j * 8 + 2 * (lane & 3);
            bool ok0 = (n < DIN), ok1 = (n + 1 < DIN);
            C[(long long)m * CP2 + n]           = ok0 ? acc[i][j][0] : 0.f;
            C[(long long)m * CP2 + n + 1]       = ok1 ? acc[i][j][1] : 0.f;
            C[(long long)(m + 8) * CP2 + n]     = ok0 ? acc[i][j][2] : 0.f;
            C[(long long)(m + 8) * CP2 + n + 1] = ok1 ? acc[i][j][3] : 0.f;
        }
    }
}

// ---------------- gather sum(Rp) -> Rf (ragged flat) -------------------------
__global__ void __launch_bounds__(256) gather_rf_k() {
    int row = blockIdx.x;
    int b = blockIdx.y;
    int g = row >> 4, n = row & 15;
    if (n >= g_cnt[b]) return;
    int t = g_off[b] + n;
    int tid = threadIdx.x;
    long long roff = ((long long)b * 64 + row) * CP2;
    float* dst = g_Rf + ((long long)t * NGR + g) * CP2;
    for (int c = tid; c < CP2; c += 256) {
        float v = 0.f;
#pragma unroll
        for (int z = 0; z < RSPLIT; z++)
            v += g_Rp[z][roff + c];
        dst[c] = v;
    }
}

// ---------------- launch ----------------------------------------------------
extern "C" void kernel_launch(void* const* d_in, const int* in_sizes, int n_in,
                              void* d_out, int out_size) {
    const float* actor = (const float*)d_in[0];
    const float* fmap  = (const float*)d_in[1];
    const float* W_a   = (const float*)d_in[2];
    const float* b_a   = (const float*)d_in[3];
    const float* W_c   = (const float*)d_in[4];
    const float* b_c   = (const float*)d_in[5];
    const float* W_h   = (const float*)d_in[6];
    const void*  counts = d_in[7];
    int nbias = 0;
    for (int i = 0; i < n_in; i++) {
        switch (in_sizes[i]) {
            case TOT * IDIM:      actor = (const float*)d_in[i]; break;
            case NB * DIN * SS:   fmap  = (const float*)d_in[i]; break;
            case NGR * GF * IDIM: W_a   = (const float*)d_in[i]; break;
            case NGR * GF * DIN:  W_c   = (const float*)d_in[i]; break;
            case NGR * GF * GF:   W_h   = (const float*)d_in[i]; break;
            case NGR * GF:
                if (nbias++ == 0) b_a = (const float*)d_in[i];
                else              b_c = (const float*)d_in[i];
                break;
            case NB:              counts = d_in[i]; break;
            default: break;
        }
    }
    float* out = (float*)d_out;

    float *emb_p, *wcT_p, *wcP_p, *e2f_p, *Rf_p, *flat_p;
    cudaGetSymbolAddress((void**)&emb_p, g_emb);
    cudaGetSymbolAddress((void**)&wcT_p, g_WcT);
    cudaGetSymbolAddress((void**)&wcP_p, g_WcP);
    cudaGetSymbolAddress((void**)&e2f_p, g_E2flat);
    cudaGetSymbolAddress((void**)&Rf_p, g_Rf);
    cudaGetSymbolAddress((void**)&flat_p, g_flat);

    cudaFuncSetAttribute(adj_mma_k, cudaFuncAttributeMaxDynamicSharedMemorySize, SMEM_A);
    cudaFuncSetAttribute(r_mma_k, cudaFuncAttributeMaxDynamicSharedMemorySize, SMEM_R);

    // 0: ragged bookkeeping
    init_offsets_k<<<1, 32>>>(counts);
    // 1: W prep
    prep_w_k<<<(NGR * GF * CP2 + 255) / 256, 256>>>(W_c);
    // 2: emb partials (register-tiled, split-K x8)
    emb_tile_k<<<dim3(IDIM / 128, 3, KSPLIT), 256>>>(actor, W_a);
    // 3: fm -> fp16 (native layout, vectorized)  [profile slot]
    convert_fm_k<<<(int)(((long long)NB * DIN * SS / 4 + 255) / 256), 256>>>(fmap);
    // 4: emb reduce + bias
    emb_reduce_k<<<(TOT * IDIM + 255) / 256, 256>>>(b_a);
    // 5: E2flat[t][g][c] = emb[t,g,:] @ WcT[g]^T
    gemm_flex_k<<<dim3(5, CP2 / 64, NGR), 256>>>(
        emb_p, IDIM, GF,
        wcT_p, GF, (long long)CP2 * GF, CP2,
        nullptr, 0, nullptr, 0, 0,
        e2f_p, NGR * CP2, CP2,
        GF, CP2, 0);
    // 6: scatter E2 -> fp16 padded rows + dP
    scatter_e2_k<<<dim3(64, NB), 256>>>(b_c);
    // 7: adj partials via fp16 MMA (split-K x2, B via ldmatrix.trans)
    adj_mma_k<<<dim3(SROWS / 128, NB, ASPLIT), 256, SMEM_A>>>();
    // 8: softmax (sums partials) -> adj fp16 hi/lo
    softmax_k<<<dim3(NMAX, NGR, NB), 256>>>();
    // 9: R partials via fp16 MMA (split-K x4)
    r_mma_k<<<dim3(CP2 / 128, NB, RSPLIT), 256, SMEM_R>>>();
    // 10: gather sum(Rp) -> ragged flat
    gather_rf_k<<<dim3(64, NB), 256>>>();
    // 11: flat = Rf @ WcP^T + b_c + emb
    gemm_flex_k<<<dim3(5, NGR, NGR), 256>>>(
        Rf_p, NGR * CP2, CP2,
        wcP_p, CP2, (long long)GF * CP2, GF,
        b_c, GF,
        emb_p, IDIM, GF,
        flat_p, IDIM, GF,
        CP2, GF, 0);
    // 12: head: out = relu(flat @ W_h^T)
    gemm_flex_k<<<dim3(5, NGR, NGR), 256>>>(
        flat_p, IDIM, GF,
        W_h, GF, (long long)GF * GF, GF,
        nullptr, 0, nullptr, 0, 0,
        out, IDIM, GF,
        GF, GF, 1);
}

// round 17
// speedup vs baseline: 4.2902x; 1.2332x over previous
#include <cuda_runtime.h>
#include <cuda_fp16.h>
#include <cstdint>

// Problem constants
#define NGR 4
#define GF 256
#define DIN 834
#define SS 1568
#define NB 16
#define TOT 160
#define IDIM 1024
#define NMAX 16

#define CP2 896             // c padded (28 x 32)
#define ADJ_LD 1664         // s padded (52 x 32)
#define SROWS 1664
#define KSPLIT 8
#define RSPLIT 4
#define ASPLIT 2
#define FLATKS 7            // flat split-K (896/7 = 128)

// mma smem (A tiles): RS2=80B row stride, k=32 fp16 per stage slot
#define RS2 80
#define A_TB (64 * RS2)             // 5120
#define RSB 272
#define BT_TRANS (32 * RSB)         // 8704
#define AH2 0
#define AL2 (A_TB)
#define BH2 (2 * A_TB)
#define STG_A (2 * A_TB + BT_TRANS) // 18944
#define SMEM_A (2 * STG_A)          // 37888
#define B_TB (128 * RS2)            // 10240
#define STG_R (2 * A_TB + B_TB)     // 20480
#define SMEM_R (2 * STG_R)          // 40960

// ---------------- scratch (static device globals) --------------------------
__device__ float g_emb[TOT * IDIM];
__device__ float g_embP[KSPLIT * TOT * IDIM];
__device__ float g_WcT[NGR * CP2 * GF];              // [g][c][f]
__device__ float g_WcP[NGR * GF * CP2];              // [g][f][c], zero pad
__device__ float g_E2q[2][TOT * NGR * CP2];          // E2 split-K partials
__device__ __half g_e2h[NB * 64 * CP2];              // A of adj (hi), pad zero
__device__ __half g_e2l[NB * 64 * CP2];
__device__ float g_dP[NB * 64];
__device__ __half g_fmCh[(long long)NB * DIN * SS];  // [b][c][s]
__device__ float g_adjP[ASPLIT][NB * 64 * ADJ_LD];
__device__ __half g_adjh[NB * 64 * ADJ_LD];          // softmaxed, zero-static
__device__ __half g_adjl[NB * 64 * ADJ_LD];
__device__ float g_Rp[RSPLIT][NB * 64 * CP2];
__device__ float g_Rf[TOT * NGR * CP2];
__device__ float g_flatP[FLATKS][TOT * IDIM];
__device__ float g_flat[TOT * IDIM];
__device__ float g_outP[2][TOT * IDIM];
__device__ int   g_off[NB];
__device__ int   g_cnt[NB];

// ---------------- PTX helpers ------------------------------------------------
__device__ __forceinline__ uint32_t smem_u32(const void* p) {
    uint32_t a;
    asm("{ .reg .u64 t; cvta.to.shared.u64 t, %1; cvt.u32.u64 %0, t; }"
        : "=r"(a) : "l"(p));
    return a;
}
__device__ __forceinline__ void cp16(uint32_t dst, const void* src) {
    asm volatile("cp.async.cg.shared.global [%0], [%1], 16;"
                 :: "r"(dst), "l"(src) : "memory");
}
__device__ __forceinline__ void cp_commit() {
    asm volatile("cp.async.commit_group;" ::: "memory");
}
template <int N>
__device__ __forceinline__ void cp_wait() {
    asm volatile("cp.async.wait_group %0;" :: "n"(N) : "memory");
}
__device__ __forceinline__ void ldsm4(uint32_t& r0, uint32_t& r1, uint32_t& r2,
                                      uint32_t& r3, uint32_t a) {
    asm volatile("ldmatrix.sync.aligned.m8n8.x4.shared.b16 {%0,%1,%2,%3}, [%4];"
                 : "=r"(r0), "=r"(r1), "=r"(r2), "=r"(r3) : "r"(a));
}
__device__ __forceinline__ void ldsm4t(uint32_t& r0, uint32_t& r1, uint32_t& r2,
                                       uint32_t& r3, uint32_t a) {
    asm volatile("ldmatrix.sync.aligned.m8n8.x4.trans.shared.b16 {%0,%1,%2,%3}, [%4];"
                 : "=r"(r0), "=r"(r1), "=r"(r2), "=r"(r3) : "r"(a));
}
__device__ __forceinline__ void mma_f16(float* c, const uint32_t* a,
                                        uint32_t b0, uint32_t b1) {
    asm volatile(
        "mma.sync.aligned.m16n8k16.row.col.f32.f16.f16.f32 "
        "{%0,%1,%2,%3}, {%4,%5,%6,%7}, {%8,%9}, {%0,%1,%2,%3};"
        : "+f"(c[0]), "+f"(c[1]), "+f"(c[2]), "+f"(c[3])
        : "r"(a[0]), "r"(a[1]), "r"(a[2]), "r"(a[3]), "r"(b0), "r"(b1));
}

// ---------------- K0: ragged bookkeeping ------------------------------------
__global__ void init_offsets_k(const void* __restrict__ counts) {
    if (threadIdx.x == 0 && blockIdx.x == 0) {
        const int* c32 = (const int*)counts;
        const long long* c64 = (const long long*)counts;
        long long s = 0;
        bool ok32 = true;
        for (int b = 0; b < NB; b++) {
            int v = c32[b];
            if (v < 0 || v > NMAX) ok32 = false;
            s += v;
        }
        if (s != TOT) ok32 = false;
        int acc = 0;
        for (int b = 0; b < NB; b++) {
            int c = ok32 ? c32[b] : (int)c64[b];
            if (c < 0) c = 0;
            if (c > NMAX) c = NMAX;
            g_off[b] = acc;
            g_cnt[b] = c;
            acc += c;
        }
    }
}

// ---------------- prep: WcP[g][f][c] + WcT[g][c][f] -------------------------
__global__ void __launch_bounds__(256) prep_w_k(const float* __restrict__ Wc) {
    int id = blockIdx.x * 256 + threadIdx.x;
    if (id >= NGR * GF * CP2) return;
    int c = id % CP2;
    int rf = id / CP2;
    int f = rf % GF, g = rf / GF;
    float v = (c < DIN) ? Wc[(long long)rf * DIN + c] : 0.f;
    g_WcP[id] = v;
    g_WcT[((long long)g * CP2 + c) * GF + f] = v;
}

// ---------------- prep: fm -> fp16 (native layout), vectorized --------------
__global__ void __launch_bounds__(256) convert_fm_k(const float* __restrict__ fm) {
    long long id = ((long long)blockIdx.x * 256 + threadIdx.x) * 4;
    if (id >= (long long)NB * DIN * SS) return;
    float4 v = *(const float4*)(fm + id);
    __half2 h0 = __floats2half2_rn(v.x, v.y);
    __half2 h1 = __floats2half2_rn(v.z, v.w);
    uint2 u;
    u.x = *(uint32_t*)&h0;
    u.y = *(uint32_t*)&h1;
    *(uint2*)(g_fmCh + id) = u;
}

// ---------------- emb: register-tiled 64m x 128n fp32, split-K x8 -----------
__global__ void __launch_bounds__(256) emb_tile_k(
    const float* __restrict__ A, const float* __restrict__ Bm)
{
    __shared__ __align__(16) float As[32][68];
    __shared__ __align__(16) float Bs[32][132];

    int n0 = blockIdx.x * 128;
    int m0 = blockIdx.y * 64;
    int zk = blockIdx.z;
    int kbase = zk * (IDIM / KSPLIT);
    int tid = threadIdx.x;
    int tx = tid & 31, ty = tid >> 5;

    float acc[8][4];
#pragma unroll
    for (int i = 0; i < 8; i++)
#pragma unroll
        for (int j = 0; j < 4; j++) acc[i][j] = 0.f;

    for (int kc = 0; kc < IDIM / KSPLIT; kc += 32) {
        int k0 = kbase + kc;
#pragma unroll
        for (int t = 0; t < 8; t++) {
            int lin = tid + 256 * t;
            int k = lin & 31, m = lin >> 5;
            int row = m0 + m; if (row >= TOT) row = TOT - 1;
            As[k][m] = A[row * IDIM + k0 + k];
        }
#pragma unroll
        for (int t = 0; t < 16; t++) {
            int lin = tid + 256 * t;
            int k = lin & 31, n = lin >> 5;
            Bs[k][n] = Bm[(long long)(n0 + n) * IDIM + k0 + k];
        }
        __syncthreads();
#pragma unroll
        for (int k = 0; k < 32; k++) {
            float a[8], bv[4];
            *(float4*)&a[0] = *(const float4*)&As[k][ty * 8];
            *(float4*)&a[4] = *(const float4*)&As[k][ty * 8 + 4];
            *(float4*)&bv[0] = *(const float4*)&Bs[k][tx * 4];
#pragma unroll
            for (int i = 0; i < 8; i++)
#pragma unroll
                for (int j = 0; j < 4; j++)
                    acc[i][j] += a[i] * bv[j];
        }
        __syncthreads();
    }

    float* P = g_embP + (long long)zk * TOT * IDIM;
#pragma unroll
    for (int i = 0; i < 8; i++) {
        int m = m0 + ty * 8 + i;
        if (m < TOT) {
#pragma unroll
            for (int j = 0; j < 4; j++)
                P[m * IDIM + n0 + tx * 4 + j] = acc[i][j];
        }
    }
}

__global__ void __launch_bounds__(256) emb_reduce_k(const float* __restrict__ ba) {
    int id = blockIdx.x * 256 + threadIdx.x;
    if (id >= TOT * IDIM) return;
    float v = ba[id & (IDIM - 1)];
#pragma unroll
    for (int z = 0; z < KSPLIT; z++)
        v += g_embP[z * (TOT * IDIM) + id];
    g_emb[id] = v;
}

// ---------------- split-K partial GEMM: C_part = A @ B^T --------------------
// z decomposed: g = bz/KS, zk = bz%KS. 32m x 64n tile, per-CTA K = Ksub.
__global__ void __launch_bounds__(256) gemm_partk(
    const float* __restrict__ A, int lda, long long aZ,
    const float* __restrict__ Bm, int ldb, long long bZ, int Brows,
    float* __restrict__ C, int ldc, long long cZ, long long cZk,
    int KS, int Ksub)
{
    int bz = blockIdx.z;
    int g = bz / KS, zk = bz % KS;
    A  += (long long)g * aZ + zk * Ksub;
    Bm += (long long)g * bZ + zk * Ksub;
    C  += (long long)g * cZ + (long long)zk * cZk;

    __shared__ __align__(16) float As[32][33];
    __shared__ __align__(16) float Bs[32][65];

    int tid = threadIdx.x;
    int m0 = blockIdx.x * 32;
    int n0 = blockIdx.y * 64;
    int tx = tid % 64, ty = tid / 64;

    float acc[8];
#pragma unroll
    for (int i = 0; i < 8; i++) acc[i] = 0.f;

    for (int k0 = 0; k0 < Ksub; k0 += 32) {
#pragma unroll
        for (int t = 0; t < 4; t++) {
            int lin = tid + 256 * t;
            int k = lin & 31, m = lin >> 5;
            As[k][m] = A[(long long)(m0 + m) * lda + k0 + k];
        }
#pragma unroll
        for (int t = 0; t < 8; t++) {
            int lin = tid + 256 * t;
            int k = lin & 31, n = lin >> 5;
            int r = n0 + n;
            if (r >= Brows) r = Brows - 1;
            Bs[k][n] = Bm[(long long)r * ldb + k0 + k];
        }
        __syncthreads();
#pragma unroll
        for (int k = 0; k < 32; k++) {
            float bv = Bs[k][tx];
#pragma unroll
            for (int i = 0; i < 8; i++)
                acc[i] += As[k][ty + 4 * i] * bv;
        }
        __syncthreads();
    }

#pragma unroll
    for (int i = 0; i < 8; i++) {
        int m = m0 + ty + 4 * i;
        C[(long long)m * ldc + n0 + tx] = acc[i];
    }
}

// ---------------- flat reduce: sum partials + b_c + emb ----------------------
__global__ void __launch_bounds__(256) flat_red_k(const float* __restrict__ bc) {
    int id = blockIdx.x * 256 + threadIdx.x;
    if (id >= TOT * IDIM) return;
    float v = bc[id & (IDIM - 1)] + g_emb[id];
#pragma unroll
    for (int z = 0; z < FLATKS; z++)
        v += g_flatP[z][id];
    g_flat[id] = v;
}

// ---------------- head reduce: relu(p0+p1) -> out ----------------------------
__global__ void __launch_bounds__(256) head_red_k(float* __restrict__ out) {
    int id = blockIdx.x * 256 + threadIdx.x;
    if (id >= TOT * IDIM) return;
    out[id] = fmaxf(g_outP[0][id] + g_outP[1][id], 0.f);
}

// ---------------- scatter E2 (sum 2 partials) -> fp16 hi/lo, dP --------------
__global__ void __launch_bounds__(256) scatter_e2_k(const float* __restrict__ bc) {
    int row = blockIdx.x;        // g*16 + n
    int b = blockIdx.y;
    int g = row >> 4, n = row & 15;
    int tid = threadIdx.x;
    bool valid = (n < g_cnt[b]);
    int t = g_off[b] + n;

    long long doff = ((long long)b * 64 + row) * CP2;
    long long soff = ((long long)t * NGR + g) * CP2;
    for (int c = tid; c < CP2; c += 256) {
        float v = valid ? (g_E2q[0][soff + c] + g_E2q[1][soff + c]) : 0.f;
        __half h = __float2half(v);
        g_e2h[doff + c] = h;
        g_e2l[doff + c] = __float2half(v - __half2float(h));
    }

    __shared__ float red[8];
    float v = valid ? g_emb[t * IDIM + g * GF + tid] * bc[g * GF + tid] : 0.f;
#pragma unroll
    for (int o = 16; o > 0; o >>= 1) v += __shfl_xor_sync(0xffffffffu, v, o);
    if ((tid & 31) == 0) red[tid >> 5] = v;
    __syncthreads();
    if (tid == 0) {
        float s = 0.f;
#pragma unroll
        for (int w = 0; w < 8; w++) s += red[w];
        g_dP[b * 64 + row] = s;
    }
}

// ---------------- adj MMA (fp16 2-term, split-K x2), B via ldmatrix.trans ---
__global__ void __launch_bounds__(256, 3) adj_mma_k() {
    extern __shared__ __align__(16) char sm[];
    int tid = threadIdx.x, lane = tid & 31, wid = tid >> 5;
    int stile = blockIdx.x, b = blockIdx.y, zk = blockIdx.z;
    uint32_t sb = smem_u32(sm);

    const char* Ah = (const char*)(g_e2h + (long long)b * 64 * CP2);
    const char* Al = (const char*)(g_e2l + (long long)b * 64 * CP2);
    const char* Bh = (const char*)(g_fmCh + (long long)b * DIN * SS);

    int rA = tid >> 2, cA = tid & 3;
    uint32_t dA = rA * RS2 + cA * 16;
    long long sA = (long long)rA * (CP2 * 2) + cA * 16;
    int rB0 = tid >> 4, cB0 = tid & 15;
    int id1 = tid + 256;
    int rB1 = id1 >> 4, cB1 = id1 & 15;
    uint32_t dB0 = rB0 * RSB + cB0 * 16, dB1 = rB1 * RSB + cB1 * 16;
    int sbyte0 = stile * 256 + cB0 * 16; if (sbyte0 > SS * 2 - 16) sbyte0 = SS * 2 - 16;
    int sbyte1 = stile * 256 + cB1 * 16; if (sbyte1 > SS * 2 - 16) sbyte1 = SS * 2 - 16;

    int warpM = wid & 1, warpN = wid >> 1;
    uint32_t aOff[2], bOffT[2];
#pragma unroll
    for (int i = 0; i < 2; i++)
        aOff[i] = (warpM * 32 + i * 16 + (lane & 15)) * RS2 + (lane >> 4) * 16;
    {
        int rowT = (lane & 7) | ((lane & 16) >> 1);
        int colT = (lane & 8) * 2;
#pragma unroll
        for (int jj = 0; jj < 2; jj++)
            bOffT[jj] = rowT * RSB + colT + (warpN * 32 + jj * 16) * 2;
    }

    float acc[2][4][4];
#pragma unroll
    for (int i = 0; i < 2; i++)
#pragma unroll
        for (int j = 0; j < 4; j++)
#pragma unroll
            for (int q = 0; q < 4; q++) acc[i][j][q] = 0.f;

    const int NCH = CP2 / 32 / ASPLIT;   // 14
    int kbeg = zk * NCH;
    {
        int chunk = kbeg;
        long long ko = (long long)chunk * 64;
        cp16(sb + AH2 + dA, Ah + sA + ko);
        cp16(sb + AL2 + dA, Al + sA + ko);
        int c0 = chunk * 32 + rB0; if (c0 >= DIN) c0 = DIN - 1;
        int c1 = chunk * 32 + rB1; if (c1 >= DIN) c1 = DIN - 1;
        cp16(sb + BH2 + dB0, Bh + (long long)c0 * (SS * 2) + sbyte0);
        cp16(sb + BH2 + dB1, Bh + (long long)c1 * (SS * 2) + sbyte1);
        cp_commit();
    }

    for (int kc = 0; kc < NCH; kc++) {
        uint32_t bo = (kc & 1) ? STG_A : 0;
        if (kc + 1 < NCH) {
            int chunk = kbeg + kc + 1;
            long long ko = (long long)chunk * 64;
            uint32_t nbo = ((kc + 1) & 1) ? STG_A : 0;
            cp16(sb + nbo + AH2 + dA, Ah + sA + ko);
            cp16(sb + nbo + AL2 + dA, Al + sA + ko);
            int c0 = chunk * 32 + rB0; if (c0 >= DIN) c0 = DIN - 1;
            int c1 = chunk * 32 + rB1; if (c1 >= DIN) c1 = DIN - 1;
            cp16(sb + nbo + BH2 + dB0, Bh + (long long)c0 * (SS * 2) + sbyte0);
            cp16(sb + nbo + BH2 + dB1, Bh + (long long)c1 * (SS * 2) + sbyte1);
            cp_commit();
            cp_wait<1>();
        } else {
            cp_wait<0>();
        }
        __syncthreads();

#pragma unroll
        for (int ks = 0; ks < 2; ks++) {
            uint32_t kbA = ks * 32;
            uint32_t kbB = ks * 16 * RSB;
            uint32_t ah[2][4], al[2][4];
#pragma unroll
            for (int i = 0; i < 2; i++) {
                ldsm4(ah[i][0], ah[i][1], ah[i][2], ah[i][3],
                      sb + bo + AH2 + aOff[i] + kbA);
                ldsm4(al[i][0], al[i][1], al[i][2], al[i][3],
                      sb + bo + AL2 + aOff[i] + kbA);
            }
#pragma unroll
            for (int jj = 0; jj < 2; jj++) {
                uint32_t h0, h1, h2, h3;
                ldsm4t(h0, h1, h2, h3, sb + bo + BH2 + bOffT[jj] + kbB);
                int j0 = 2 * jj, j1 = 2 * jj + 1;
                mma_f16(acc[0][j0], ah[0], h0, h2);
                mma_f16(acc[0][j1], ah[0], h1, h3);
                mma_f16(acc[1][j0], ah[1], h0, h2);
                mma_f16(acc[1][j1], ah[1], h1, h3);
                mma_f16(acc[0][j0], al[0], h0, h2);
                mma_f16(acc[0][j1], al[0], h1, h3);
                mma_f16(acc[1][j0], al[1], h0, h2);
                mma_f16(acc[1][j1], al[1], h1, h3);
            }
        }
        __syncthreads();
    }

    float* C = g_adjP[zk] + (long long)b * 64 * ADJ_LD;
#pragma unroll
    for (int i = 0; i < 2; i++) {
        int m = warpM * 32 + i * 16 + (lane >> 2);
        float rb0 = (zk == 0) ? g_dP[b * 64 + m] : 0.f;
        float rb1 = (zk == 0) ? g_dP[b * 64 + m + 8] : 0.f;
#pragma unroll
        for (int j = 0; j < 4; j++) {
            int n = stile * 128 + warpN * 32 + j * 8 + 2 * (lane & 3);
            C[(long long)m * ADJ_LD + n]           = acc[i][j][0] + rb0;
            C[(long long)m * ADJ_LD + n + 1]       = acc[i][j][1] + rb0;
            C[(long long)(m + 8) * ADJ_LD + n]     = acc[i][j][2] + rb1;
            C[(long long)(m + 8) * ADJ_LD + n + 1] = acc[i][j][3] + rb1;
        }
    }
}

// ---------------- softmax: sum partials, softmax, emit fp16 hi/lo ------------
__global__ void __launch_bounds__(256) softmax_k() {
    int n = blockIdx.x, g = blockIdx.y, b = blockIdx.z;
    if (n >= g_cnt[b]) return;
    long long roff = (long long)(b * 64 + g * 16 + n) * ADJ_LD;
    float* p0 = g_adjP[0] + roff;
    const float* p1 = g_adjP[1] + roff;
    int tid = threadIdx.x;
    __shared__ float red[8];

    float mx = -1e30f;
    for (int s = tid; s < SS; s += 256) mx = fmaxf(mx, p0[s] + p1[s]);
#pragma unroll
    for (int o = 16; o > 0; o >>= 1) mx = fmaxf(mx, __shfl_xor_sync(0xffffffffu, mx, o));
    if ((tid & 31) == 0) red[tid >> 5] = mx;
    __syncthreads();
    if (tid < 32) {
        float v = (tid < 8) ? red[tid] : -1e30f;
#pragma unroll
        for (int o = 4; o > 0; o >>= 1) v = fmaxf(v, __shfl_xor_sync(0xffffffffu, v, o));
        if (tid == 0) red[0] = v;
    }
    __syncthreads();
    mx = red[0];
    __syncthreads();

    float sum = 0.f;
    for (int s = tid; s < SS; s += 256) {
        float e = __expf(p0[s] + p1[s] - mx);
        p0[s] = e;
        sum += e;
    }
#pragma unroll
    for (int o = 16; o > 0; o >>= 1) sum += __shfl_xor_sync(0xffffffffu, sum, o);
    if ((tid & 31) == 0) red[tid >> 5] = sum;
    __syncthreads();
    if (tid < 32) {
        float v = (tid < 8) ? red[tid] : 0.f;
#pragma unroll
        for (int o = 4; o > 0; o >>= 1) v += __shfl_xor_sync(0xffffffffu, v, o);
        if (tid == 0) red[0] = v;
    }
    __syncthreads();
    float inv = 1.f / red[0];
    for (int s = tid; s < SS; s += 256) {
        float v = p0[s] * inv;
        __half h = __float2half(v);
        g_adjh[roff + s] = h;
        g_adjl[roff + s] = __float2half(v - __half2float(h));
    }
}

// ---------------- R MMA (fp16 2-term, split-K x4 over s) ---------------------
__global__ void __launch_bounds__(256, 3) r_mma_k() {
    extern __shared__ __align__(16) char sm[];
    int tid = threadIdx.x, lane = tid & 31, wid = tid >> 5;
    int b = blockIdx.y, zk = blockIdx.z;
    int n0 = blockIdx.x * 128;
    uint32_t sb = smem_u32(sm);

    const char* Ah = (const char*)(g_adjh + (long long)b * 64 * ADJ_LD);
    const char* Al = (const char*)(g_adjl + (long long)b * 64 * ADJ_LD);
    const char* Bh = (const char*)(g_fmCh + (long long)b * DIN * SS);

    int rA = tid >> 2, cA = tid & 3;
    uint32_t dA = rA * RS2 + cA * 16;
    long long sA = (long long)rA * (ADJ_LD * 2) + cA * 16;
    int rB0 = tid >> 2, cB0 = tid & 3;
    int id1 = tid + 256;
    int rB1 = id1 >> 2, cB1 = id1 & 3;
    int cr0 = n0 + rB0; if (cr0 >= DIN) cr0 = DIN - 1;
    int cr1 = n0 + rB1; if (cr1 >= DIN) cr1 = DIN - 1;
    uint32_t dB0 = rB0 * RS2 + cB0 * 16, dB1 = rB1 * RS2 + cB1 * 16;
    long long sB0 = (long long)cr0 * (SS * 2) + cB0 * 16;
    long long sB1 = (long long)cr1 * (SS * 2) + cB1 * 16;

    int warpM = wid & 1, warpN = wid >> 1;
    uint32_t aOff[2], bOff[2];
#pragma unroll
    for (int i = 0; i < 2; i++)
        aOff[i] = (warpM * 32 + i * 16 + (lane & 15)) * RS2 + (lane >> 4) * 16;
#pragma unroll
    for (int jj = 0; jj < 2; jj++)
        bOff[jj] = (warpN * 32 + jj * 16 + (lane & 15)) * RS2 + (lane >> 4) * 16;

    float acc[2][4][4];
#pragma unroll
    for (int i = 0; i < 2; i++)
#pragma unroll
        for (int j = 0; j < 4; j++)
#pragma unroll
            for (int q = 0; q < 4; q++) acc[i][j][q] = 0.f;

    int kbeg = (zk == 0) ? 0 : (zk * 12 + 1);
    int kcnt = (zk == 0) ? 13 : 12;
    {
        long long ko = (long long)kbeg * 64;
        cp16(sb + AH2 + dA, Ah + sA + ko);
        cp16(sb + AL2 + dA, Al + sA + ko);
        cp16(sb + BH2 + dB0, Bh + sB0 + ko);
        cp16(sb + BH2 + dB1, Bh + sB1 + ko);
        cp_commit();
    }

    for (int kc = 0; kc < kcnt; kc++) {
        uint32_t bo = (kc & 1) ? STG_R : 0;
        if (kc + 1 < kcnt) {
            long long ko = (long long)(kbeg + kc + 1) * 64;
            uint32_t nbo = ((kc + 1) & 1) ? STG_R : 0;
            cp16(sb + nbo + AH2 + dA, Ah + sA + ko);
            cp16(sb + nbo + AL2 + dA, Al + sA + ko);
            cp16(sb + nbo + BH2 + dB0, Bh + sB0 + ko);
            cp16(sb + nbo + BH2 + dB1, Bh + sB1 + ko);
            cp_commit();
            cp_wait<1>();
        } else {
            cp_wait<0>();
        }
        __syncthreads();

#pragma unroll
        for (int ks = 0; ks < 2; ks++) {
            uint32_t kb = ks * 32;
            uint32_t ah[2][4], al[2][4];
#pragma unroll
            for (int i = 0; i < 2; i++) {
                ldsm4(ah[i][0], ah[i][1], ah[i][2], ah[i][3],
                      sb + bo + AH2 + aOff[i] + kb);
                ldsm4(al[i][0], al[i][1], al[i][2], al[i][3],
                      sb + bo + AL2 + aOff[i] + kb);
            }
#pragma unroll
            for (int jj = 0; jj < 2; jj++) {
                uint32_t h0, h1, h2, h3;
                ldsm4(h0, h1, h2, h3, sb + bo + BH2 + bOff[jj] + kb);
                int j0 = 2 * jj, j1 = 2 * jj + 1;
                mma_f16(acc[0][j0], ah[0], h0, h2);
                mma_f16(acc[0][j1], ah[0], h1, h3);
                mma_f16(acc[1][j0], ah[1], h0, h2);
                mma_f16(acc[1][j1], ah[1], h1, h3);
                mma_f16(acc[0][j0], al[0], h0, h2);
                mma_f16(acc[0][j1], al[0], h1, h3);
                mma_f16(acc[1][j0], al[1], h0, h2);
                mma_f16(acc[1][j1], al[1], h1, h3);
            }
        }
        __syncthreads();
    }

    float* C = g_Rp[zk] + (long long)b * 64 * CP2;
#pragma unroll
    for (int i = 0; i < 2; i++) {
        int m = warpM * 32 + i * 16 + (lane >> 2);
#pragma unroll
        for (int j = 0; j < 4; j++) {
            int n = n0 + warpN * 32 + j * 8 + 2 * (lane & 3);
            bool ok0 = (n < DIN), ok1 = (n + 1 < DIN);
            C[(long long)m * CP2 + n]           = ok0 ? acc[i][j][0] : 0.f;
            C[(long long)m * CP2 + n + 1]       = ok1 ? acc[i][j][1] : 0.f;
            C[(long long)(m + 8) * CP2 + n]     = ok0 ? acc[i][j][2] : 0.f;
            C[(long long)(m + 8) * CP2 + n + 1] = ok1 ? acc[i][j][3] : 0.f;
        }
    }
}

// ---------------- gather sum(Rp) -> Rf (ragged flat) -------------------------
__global__ void __launch_bounds__(256) gather_rf_k() {
    int row = blockIdx.x;
    int b = blockIdx.y;
    int g = row >> 4, n = row & 15;
    if (n >= g_cnt[b]) return;
    int t = g_off[b] + n;
    int tid = threadIdx.x;
    long long roff = ((long long)b * 64 + row) * CP2;
    float* dst = g_Rf + ((long long)t * NGR + g) * CP2;
    for (int c = tid; c < CP2; c += 256) {
        float v = 0.f;
#pragma unroll
        for (int z = 0; z < RSPLIT; z++)
            v += g_Rp[z][roff + c];
        dst[c] = v;
    }
}

// ---------------- launch ----------------------------------------------------
extern "C" void kernel_launch(void* const* d_in, const int* in_sizes, int n_in,
                              void* d_out, int out_size) {
    const float* actor = (const float*)d_in[0];
    const float* fmap  = (const float*)d_in[1];
    const float* W_a   = (const float*)d_in[2];
    const float* b_a   = (const float*)d_in[3];
    const float* W_c   = (const float*)d_in[4];
    const float* b_c   = (const float*)d_in[5];
    const float* W_h   = (const float*)d_in[6];
    const void*  counts = d_in[7];
    int nbias = 0;
    for (int i = 0; i < n_in; i++) {
        switch (in_sizes[i]) {
            case TOT * IDIM:      actor = (const float*)d_in[i]; break;
            case NB * DIN * SS:   fmap  = (const float*)d_in[i]; break;
            case NGR * GF * IDIM: W_a   = (const float*)d_in[i]; break;
            case NGR * GF * DIN:  W_c   = (const float*)d_in[i]; break;
            case NGR * GF * GF:   W_h   = (const float*)d_in[i]; break;
            case NGR * GF:
                if (nbias++ == 0) b_a = (const float*)d_in[i];
                else              b_c = (const float*)d_in[i];
                break;
            case NB:              counts = d_in[i]; break;
            default: break;
        }
    }
    float* out = (float*)d_out;

    float *emb_p, *wcT_p, *wcP_p, *e2q_p, *Rf_p, *flat_p, *flatP_p, *outP_p;
    cudaGetSymbolAddress((void**)&emb_p, g_emb);
    cudaGetSymbolAddress((void**)&wcT_p, g_WcT);
    cudaGetSymbolAddress((void**)&wcP_p, g_WcP);
    cudaGetSymbolAddress((void**)&e2q_p, g_E2q);
    cudaGetSymbolAddress((void**)&Rf_p, g_Rf);
    cudaGetSymbolAddress((void**)&flat_p, g_flat);
    cudaGetSymbolAddress((void**)&flatP_p, g_flatP);
    cudaGetSymbolAddress((void**)&outP_p, g_outP);

    cudaFuncSetAttribute(adj_mma_k, cudaFuncAttributeMaxDynamicSharedMemorySize, SMEM_A);
    cudaFuncSetAttribute(r_mma_k, cudaFuncAttributeMaxDynamicSharedMemorySize, SMEM_R);

    // 0: ragged bookkeeping
    init_offsets_k<<<1, 32>>>(counts);
    // 1: W prep
    prep_w_k<<<(NGR * GF * CP2 + 255) / 256, 256>>>(W_c);
    // 2: emb partials (register-tiled, split-K x8)
    emb_tile_k<<<dim3(IDIM / 128, 3, KSPLIT), 256>>>(actor, W_a);
    // 3: fm -> fp16
    convert_fm_k<<<(int)(((long long)NB * DIN * SS / 4 + 255) / 256), 256>>>(fmap);
    // 4: emb reduce + bias
    emb_reduce_k<<<(TOT * IDIM + 255) / 256, 256>>>(b_a);
    // 5: E2 partials = emb @ WcT^T (split-K x2)
    gemm_partk<<<dim3(5, CP2 / 64, NGR * 2), 256>>>(
        emb_p, IDIM, GF,
        wcT_p, GF, (long long)CP2 * GF, CP2,
        e2q_p, NGR * CP2, CP2, (long long)TOT * NGR * CP2,
        2, GF / 2);
    // 6: scatter E2 (sum partials) -> fp16 padded rows + dP
    scatter_e2_k<<<dim3(64, NB), 256>>>(b_c);
    // 7: adj partials via fp16 MMA (split-K x2)
    adj_mma_k<<<dim3(SROWS / 128, NB, ASPLIT), 256, SMEM_A>>>();
    // 8: softmax
    softmax_k<<<dim3(NMAX, NGR, NB), 256>>>();
    // 9: R partials via fp16 MMA (split-K x4)
    r_mma_k<<<dim3(CP2 / 128, NB, RSPLIT), 256, SMEM_R>>>();
    // 10: gather sum(Rp) -> ragged flat
    gather_rf_k<<<dim3(64, NB), 256>>>();
    // 11: flat partials = Rf @ WcP^T (split-K x7)
    gemm_partk<<<dim3(5, NGR, NGR * FLATKS), 256>>>(
        Rf_p, NGR * CP2, CP2,
        wcP_p, CP2, (long long)GF * CP2, GF,
        flatP_p, IDIM, GF, (long long)TOT * IDIM,
        FLATKS, CP2 / FLATKS);
    // 12: flat reduce (+ b_c + emb)
    flat_red_k<<<(TOT * IDIM + 255) / 256, 256>>>(b_c);
    // 13: head partials = flat @ W_h^T (split-K x2)
    gemm_partk<<<dim3(5, NGR, NGR * 2), 256>>>(
        flat_p, IDIM, GF,
        W_h, GF, (long long)GF * GF, GF,
        outP_p, IDIM, GF, (long long)TOT * IDIM,
        2, GF / 2);
    // 14: head reduce (relu)
    head_red_k<<<(TOT * IDIM + 255) / 256, 256>>>(out);
}